// round 1
// baseline (speedup 1.0000x reference)
#include <cuda_runtime.h>
#include <math.h>

// ---------------- problem constants ----------------
#define VV     32000
#define MM     512
#define NLEAF  16384
#define DD     8
#define NNODE  4096
#define KCH    4
#define BB     64
#define SSEQ   16
#define POOLSZ (1 + NLEAF + DD * NNODE)   // 49153
#define OFFS   (1 + NLEAF)                // 16385
#define G3M    (3 * MM)                   // 1536

// ---------------- device scratch (static; no allocation) ----------------
__device__ float g_c_pool[(size_t)POOLSZ * MM];
__device__ float g_h_pool[(size_t)POOLSZ * MM];
__device__ float g_XH[(size_t)NNODE * 1024];        // [x | sum child h]
__device__ float g_CHH[(size_t)NNODE * KCH * MM];   // child h, flattened
__device__ float g_IOUF[(size_t)NNODE * 2048];      // [iou(1536) | fx(512)]
__device__ float g_FH[(size_t)NNODE * KCH * MM];    // ch_h @ W_fh + b_fh
__device__ float g_Wbig[(size_t)1024 * 2048];       // [[Wioux|Wfx],[Wiouh|0]]
__device__ float g_biasbig[2048];
__device__ float g_wiht[2][(size_t)MM * G3M];       // w_ih transposed, per dir
__device__ float g_xs[(size_t)BB * SSEQ * MM];
__device__ float g_xg[2][(size_t)BB * SSEQ * G3M];
__device__ float g_hg[2][(size_t)BB * G3M];
__device__ float g_hst[2][(size_t)BB * MM];

__device__ __forceinline__ float sigf(float x) { return 1.0f / (1.0f + expf(-x)); }

// ---------------- prep kernels ----------------
__global__ void prep_wbig(const float* __restrict__ Wioux, const float* __restrict__ Wiouh,
                          const float* __restrict__ Wfx,
                          const float* __restrict__ bioux, const float* __restrict__ biouh,
                          const float* __restrict__ bfx) {
    int idx = blockIdx.x * blockDim.x + threadIdx.x;
    if (idx < 1024 * 2048) {
        int k = idx >> 11, j = idx & 2047;
        float v;
        if (j < G3M) v = (k < MM) ? Wioux[k * G3M + j] : Wiouh[(k - MM) * G3M + j];
        else         v = (k < MM) ? Wfx[k * MM + (j - G3M)] : 0.0f;
        g_Wbig[idx] = v;
    }
    if (idx < 2048)
        g_biasbig[idx] = (idx < G3M) ? (bioux[idx] + biouh[idx]) : bfx[idx - G3M];
}

__global__ void prep_wiht(const float* __restrict__ wf, const float* __restrict__ wb) {
    int idx = blockIdx.x * blockDim.x + threadIdx.x;
    int tot = MM * G3M;
    if (idx >= 2 * tot) return;
    int dir = idx / tot, r = idx % tot;
    int m = r / G3M, g = r % G3M;
    const float* w = dir ? wb : wf;
    g_wiht[dir][(size_t)m * G3M + g] = w[(size_t)g * MM + m];
}

// ---------------- init kernels ----------------
__global__ void init_leaf(const float* __restrict__ embed, const int* __restrict__ leaf_idx) {
    int idx = blockIdx.x * blockDim.x + threadIdx.x;
    if (idx >= NLEAF * (MM / 4)) return;
    int n = idx >> 7, m = (idx & 127) * 4;
    int w = leaf_idx[n];
    float4 v = *(const float4*)(embed + (size_t)w * MM + m);
    *(float4*)(g_h_pool + (size_t)(1 + n) * MM + m) = v;
    *(float4*)(g_c_pool + (size_t)(1 + n) * MM + m) = make_float4(0.f, 0.f, 0.f, 0.f);
}

__global__ void init_misc(float* __restrict__ out) {
    int idx = blockIdx.x * blockDim.x + threadIdx.x;
    if (idx < MM) { g_h_pool[idx] = 0.f; g_c_pool[idx] = 0.f; }
    if (idx < 2 * BB * MM) (&g_hst[0][0])[idx] = 0.f;
    if (idx < BB * SSEQ * MM) out[idx] = 0.f;
}

// ---------------- per-level gather ----------------
__global__ void gather_level(const float* __restrict__ embed, const int* __restrict__ lwi,
                             const int* __restrict__ child, int d) {
    int idx = blockIdx.x * blockDim.x + threadIdx.x;
    if (idx >= NNODE * (MM / 4)) return;
    int n = idx >> 7, m = (idx & 127) * 4;
    int w = lwi[d * NNODE + n];
    float4 x = *(const float4*)(embed + (size_t)w * MM + m);
    *(float4*)(g_XH + (size_t)n * 1024 + m) = x;
    float4 s = make_float4(0.f, 0.f, 0.f, 0.f);
    const int* ch = child + ((size_t)d * NNODE + n) * KCH;
#pragma unroll
    for (int k = 0; k < KCH; k++) {
        int ci = ch[k];
        float4 hv = *(const float4*)(g_h_pool + (size_t)ci * MM + m);
        *(float4*)(g_CHH + ((size_t)n * KCH + k) * MM + m) = hv;
        s.x += hv.x; s.y += hv.y; s.z += hv.z; s.w += hv.w;
    }
    *(float4*)(g_XH + (size_t)n * 1024 + MM + m) = s;
}

// ---------------- generic SGEMM: C = A(MxK) @ B(KxN) + bias ----------------
// BM=BN=128, BK=8, 256 threads, 8x8 per thread. All dims multiples of 128/8.
__global__ void __launch_bounds__(256) sgemm128(const float* __restrict__ A,
                                                const float* __restrict__ B,
                                                const float* __restrict__ bias,
                                                float* __restrict__ C,
                                                int M, int N, int K) {
    __shared__ float As[8][128];
    __shared__ float Bs[8][128];
    int tid = threadIdx.x;
    int bx = blockIdx.x, by = blockIdx.y;
    int aRow = tid >> 1, aK = (tid & 1) * 4;
    int bK = tid >> 5, bN = (tid & 31) * 4;
    const float* Ap = A + (size_t)(by * 128 + aRow) * K + aK;
    const float* Bp = B + (size_t)bK * N + bx * 128 + bN;
    int ty = tid >> 4, tx = tid & 15;

    float acc[8][8];
#pragma unroll
    for (int i = 0; i < 8; i++)
#pragma unroll
        for (int j = 0; j < 8; j++) acc[i][j] = 0.f;

    for (int k0 = 0; k0 < K; k0 += 8) {
        float4 a4 = *(const float4*)(Ap + k0);
        float4 b4 = *(const float4*)(Bp + (size_t)k0 * N);
        As[aK + 0][aRow] = a4.x; As[aK + 1][aRow] = a4.y;
        As[aK + 2][aRow] = a4.z; As[aK + 3][aRow] = a4.w;
        *(float4*)&Bs[bK][bN] = b4;
        __syncthreads();
#pragma unroll
        for (int kk = 0; kk < 8; kk++) {
            float a[8], b[8];
            *(float4*)(a)     = *(float4*)&As[kk][ty * 8];
            *(float4*)(a + 4) = *(float4*)&As[kk][ty * 8 + 4];
            *(float4*)(b)     = *(float4*)&Bs[kk][tx * 8];
            *(float4*)(b + 4) = *(float4*)&Bs[kk][tx * 8 + 4];
#pragma unroll
            for (int i = 0; i < 8; i++)
#pragma unroll
                for (int j = 0; j < 8; j++) acc[i][j] += a[i] * b[j];
        }
        __syncthreads();
    }

    float bb[8];
#pragma unroll
    for (int j = 0; j < 8; j++) bb[j] = bias[bx * 128 + tx * 8 + j];
#pragma unroll
    for (int i = 0; i < 8; i++) {
        int gy = by * 128 + ty * 8 + i;
        float* crow = C + (size_t)gy * N + bx * 128 + tx * 8;
        float4 v0 = make_float4(acc[i][0] + bb[0], acc[i][1] + bb[1], acc[i][2] + bb[2], acc[i][3] + bb[3]);
        float4 v1 = make_float4(acc[i][4] + bb[4], acc[i][5] + bb[5], acc[i][6] + bb[6], acc[i][7] + bb[7]);
        *(float4*)(crow)     = v0;
        *(float4*)(crow + 4) = v1;
    }
}

// ---------------- level pointwise ----------------
__global__ void level_point(const int* __restrict__ child, int d) {
    int idx = blockIdx.x * blockDim.x + threadIdx.x;
    if (idx >= NNODE * MM) return;
    int n = idx >> 9, m = idx & 511;
    const float* row = g_IOUF + (size_t)n * 2048;
    float iv = sigf(row[m]);
    float ov = sigf(row[MM + m]);
    float uv = tanhf(row[2 * MM + m]);
    float fx = row[3 * MM + m];
    float c = iv * uv;
    const int* ch = child + ((size_t)d * NNODE + n) * KCH;
#pragma unroll
    for (int k = 0; k < KCH; k++) {
        int ci = ch[k];
        float f = sigf(fx + g_FH[((size_t)n * KCH + k) * MM + m]);
        c += f * g_c_pool[(size_t)ci * MM + m];
    }
    float h = ov * tanhf(c);
    size_t slot = (size_t)(OFFS + d * NNODE + n) * MM + m;
    g_c_pool[slot] = c;
    g_h_pool[slot] = h;
}

// ---------------- GRU ----------------
__global__ void gather_xs(const int* __restrict__ ctx) {
    int idx = blockIdx.x * blockDim.x + threadIdx.x;
    if (idx >= BB * SSEQ * (MM / 4)) return;
    int rowI = idx >> 7, m = (idx & 127) * 4;
    int p = ctx[rowI];
    *(float4*)(g_xs + (size_t)rowI * MM + m) =
        *(const float4*)(g_h_pool + (size_t)p * MM + m);
}

// hg[dir] = h_state[dir] (64x512) @ w_hh^T (512x1536) + b_hh.  H & W tiles in smem.
__global__ void __launch_bounds__(256) gru_gemm(const float* __restrict__ whh_f,
                                                const float* __restrict__ whh_b,
                                                const float* __restrict__ bhh_f,
                                                const float* __restrict__ bhh_b) {
    extern __shared__ float sh[];
    float* Hs = sh;                 // 64 x 513
    float* Ws = sh + 64 * 513;      // 32 x 513
    int dir = blockIdx.y;
    const float* whh = dir ? whh_b : whh_f;
    const float* bhh = dir ? bhh_b : bhh_f;
    const float* H = g_hst[dir];
    int n0 = blockIdx.x * 32;
    int tid = threadIdx.x;

    for (int i = tid; i < 64 * 512; i += 256) Hs[(i >> 9) * 513 + (i & 511)] = H[i];
    for (int i = tid; i < 32 * 512; i += 256) {
        int rr = i >> 9, kk = i & 511;
        Ws[rr * 513 + kk] = whh[(size_t)(n0 + rr) * MM + kk];
    }
    __syncthreads();

    int cg = tid & 7, r = tid >> 3;
    int row0 = 2 * r, row1 = 2 * r + 1;
    float acc0[4] = {0.f, 0.f, 0.f, 0.f};
    float acc1[4] = {0.f, 0.f, 0.f, 0.f};
    for (int k = 0; k < 512; k++) {
        float h0 = Hs[row0 * 513 + k];
        float h1 = Hs[row1 * 513 + k];
#pragma unroll
        for (int c = 0; c < 4; c++) {
            float w = Ws[(cg * 4 + c) * 513 + k];
            acc0[c] += h0 * w;
            acc1[c] += h1 * w;
        }
    }
#pragma unroll
    for (int c = 0; c < 4; c++) {
        int n = n0 + cg * 4 + c;
        float bv = bhh[n];
        g_hg[dir][(size_t)row0 * G3M + n] = acc0[c] + bv;
        g_hg[dir][(size_t)row1 * G3M + n] = acc1[c] + bv;
    }
}

__global__ void gru_point(float* __restrict__ out, int t) {
    int idx = blockIdx.x * blockDim.x + threadIdx.x;
    if (idx >= 2 * BB * MM) return;
    int dir = idx >> 15;
    int rem = idx & 32767;
    int b = rem >> 9, j = rem & 511;
    int pos = dir ? (SSEQ - 1 - t) : t;
    const float* xrow = g_xg[dir] + (size_t)(b * SSEQ + pos) * G3M;
    const float* hrow = g_hg[dir] + (size_t)b * G3M;
    float r = sigf(xrow[j] + hrow[j]);
    float z = sigf(xrow[MM + j] + hrow[MM + j]);
    float nn = tanhf(xrow[2 * MM + j] + r * hrow[2 * MM + j]);
    float hp = g_hst[dir][b * MM + j];
    float hn = (1.f - z) * nn + z * hp;
    g_hst[dir][b * MM + j] = hn;
    out[(size_t)(b * SSEQ + pos) * MM + j] += hn;
}

// ---------------- host launch ----------------
extern "C" void kernel_launch(void* const* d_in, const int* in_sizes, int n_in,
                              void* d_out, int out_size) {
    const float* embed   = (const float*)d_in[0];
    const float* Wioux   = (const float*)d_in[1];
    const float* bioux   = (const float*)d_in[2];
    const float* Wiouh   = (const float*)d_in[3];
    const float* biouh   = (const float*)d_in[4];
    const float* Wfx     = (const float*)d_in[5];
    const float* bfx     = (const float*)d_in[6];
    const float* Wfh     = (const float*)d_in[7];
    const float* bfh     = (const float*)d_in[8];
    const float* wih_f   = (const float*)d_in[9];
    const float* whh_f   = (const float*)d_in[10];
    const float* bih_f   = (const float*)d_in[11];
    const float* bhh_f   = (const float*)d_in[12];
    const float* wih_b   = (const float*)d_in[13];
    const float* whh_b   = (const float*)d_in[14];
    const float* bih_b   = (const float*)d_in[15];
    const float* bhh_b   = (const float*)d_in[16];

    // resolve index inputs by element count (dict-order vs signature-order safety)
    const int* leaf_idx = nullptr; const int* level_idx = nullptr;
    const int* child = nullptr; const int* ctx = nullptr;
    for (int i = 17; i < n_in; i++) {
        int sz = in_sizes[i];
        if (sz == NLEAF)                 leaf_idx  = (const int*)d_in[i];
        else if (sz == DD * NNODE)       level_idx = (const int*)d_in[i];
        else if (sz == DD * NNODE * KCH) child     = (const int*)d_in[i];
        else if (sz == BB * SSEQ)        ctx       = (const int*)d_in[i];
    }

    float* out = (float*)d_out;

    static float* dummy = nullptr; (void)dummy;

    cudaFuncSetAttribute(gru_gemm, cudaFuncAttributeMaxDynamicSharedMemorySize,
                         (64 + 32) * 513 * sizeof(float));

    // prep + init
    prep_wbig<<<(1024 * 2048 + 255) / 256, 256>>>(Wioux, Wiouh, Wfx, bioux, biouh, bfx);
    prep_wiht<<<(2 * MM * G3M + 255) / 256, 256>>>(wih_f, wih_b);
    init_leaf<<<(NLEAF * (MM / 4) + 255) / 256, 256>>>(embed, leaf_idx);
    init_misc<<<(BB * SSEQ * MM + 255) / 256, 256>>>(out);

    // tree levels
    float* c_poolp; float* h_poolp; // not needed host-side; device symbols used in-kernel
    (void)c_poolp; (void)h_poolp;
    float* d_XH;    cudaGetSymbolAddress((void**)&d_XH, g_XH);
    float* d_CHH;   cudaGetSymbolAddress((void**)&d_CHH, g_CHH);
    float* d_IOUF;  cudaGetSymbolAddress((void**)&d_IOUF, g_IOUF);
    float* d_FH;    cudaGetSymbolAddress((void**)&d_FH, g_FH);
    float* d_Wbig;  cudaGetSymbolAddress((void**)&d_Wbig, g_Wbig);
    float* d_bb;    cudaGetSymbolAddress((void**)&d_bb, g_biasbig);
    float* d_wiht;  cudaGetSymbolAddress((void**)&d_wiht, g_wiht);
    float* d_xs;    cudaGetSymbolAddress((void**)&d_xs, g_xs);
    float* d_xg;    cudaGetSymbolAddress((void**)&d_xg, g_xg);

    for (int d = 0; d < DD; d++) {
        gather_level<<<(NNODE * (MM / 4) + 255) / 256, 256>>>(embed, level_idx, child, d);
        {   // IOUF = XH @ Wbig + biasbig : (4096 x 2048), K=1024
            dim3 grid(2048 / 128, 4096 / 128);
            sgemm128<<<grid, 256>>>(d_XH, d_Wbig, d_bb, d_IOUF, 4096, 2048, 1024);
        }
        {   // FH = CHH @ Wfh + bfh : (16384 x 512), K=512
            dim3 grid(512 / 128, 16384 / 128);
            sgemm128<<<grid, 256>>>(d_CHH, Wfh, bfh, d_FH, 16384, 512, 512);
        }
        level_point<<<(NNODE * MM + 255) / 256, 256>>>(child, d);
    }

    // GRU input gates
    gather_xs<<<(BB * SSEQ * (MM / 4) + 255) / 256, 256>>>(ctx);
    {
        dim3 grid(G3M / 128, (BB * SSEQ) / 128);
        sgemm128<<<grid, 256>>>(d_xs, d_wiht,                 bih_f, d_xg,                 BB * SSEQ, G3M, MM);
        sgemm128<<<grid, 256>>>(d_xs, d_wiht + (size_t)MM * G3M, bih_b, d_xg + (size_t)BB * SSEQ * G3M, BB * SSEQ, G3M, MM);
    }

    // GRU recurrence: 16 steps, both directions fused per step
    size_t smem = (64 + 32) * 513 * sizeof(float);
    for (int t = 0; t < SSEQ; t++) {
        dim3 grid(G3M / 32, 2);
        gru_gemm<<<grid, 256, smem>>>(whh_f, whh_b, bhh_f, bhh_b);
        gru_point<<<(2 * BB * MM + 255) / 256, 256>>>(out, t);
    }
}

// round 4
// speedup vs baseline: 1.4946x; 1.4946x over previous
#include <cuda_runtime.h>
#include <math.h>
#include <cstdint>

// ---------------- problem constants ----------------
#define VV     32000
#define MM     512
#define NLEAF  16384
#define DD     8
#define NNODE  4096
#define KCH    4
#define BB     64
#define SSEQ   16
#define POOLSZ (1 + NLEAF + DD * NNODE)   // 49153
#define OFFS   (1 + NLEAF)                // 16385
#define G3M    (3 * MM)                   // 1536

__device__ __forceinline__ float sigf(float x) { return 1.0f / (1.0f + expf(-x)); }

// tf32 split: a = hi + lo, both exact tf32 values held in fp32 regs (b32 pattern)
__device__ __forceinline__ void split32(float a, uint32_t& hi, uint32_t& lo) {
    uint32_t u; asm("cvt.rna.tf32.f32 %0, %1;" : "=r"(u) : "f"(a));
    hi = u;
    float r = a - __uint_as_float(u);
    asm("cvt.rna.tf32.f32 %0, %1;" : "=r"(lo) : "f"(r));
}

#define MMA_TF32(c, a0, a1, a2, a3, b0, b1) \
    asm volatile("mma.sync.aligned.m16n8k8.row.col.f32.tf32.tf32.f32 " \
        "{%0,%1,%2,%3}, {%4,%5,%6,%7}, {%8,%9}, {%0,%1,%2,%3};" \
        : "+f"((c)[0]), "+f"((c)[1]), "+f"((c)[2]), "+f"((c)[3]) \
        : "r"(a0), "r"(a1), "r"(a2), "r"(a3), "r"(b0), "r"(b1))

// ---------------- device scratch ----------------
__device__ float g_c_pool[(size_t)POOLSZ * MM];
__device__ float g_h_pool[(size_t)POOLSZ * MM];
__device__ float g_HW[(size_t)POOLSZ * MM];     // h_pool @ W_fh + b_fh
__device__ float g_XH[(size_t)NNODE * 1024];    // [x | sum child h]
__device__ float g_IOUF[(size_t)NNODE * 2048];  // [iou(1536) | fx(512)]
__device__ float g_WbigT[(size_t)2048 * 1024];  // [[Wioux|Wfx],[Wiouh|0]]^T (N x K)
__device__ float g_WfhT[(size_t)MM * MM];       // Wfh^T (N x K)
__device__ float g_biasbig[2048];
__device__ float g_xs[(size_t)BB * SSEQ * MM];
__device__ float g_xg[2][(size_t)BB * SSEQ * G3M];
__device__ float g_hg[2][(size_t)BB * G3M];
__device__ float g_hst[2][(size_t)BB * MM];

// ---------------- mma.sync tf32x3 GEMM: C = A(MxK) @ Bt(NxK)^T + bias ----------------
// grid = (N/128, M/128); 256 threads. BK=16, double-buffered smem.
#define BKC 16
#define LDS_STRIDE 20   // 16 + 4 pad floats

__global__ void __launch_bounds__(256)
mma_gemm(const float* __restrict__ A, const float* __restrict__ Bt,
         const float* __restrict__ bias, float* __restrict__ C, int N_, int K) {
    __shared__ float As[2][128 * LDS_STRIDE];
    __shared__ float Bs[2][128 * LDS_STRIDE];

    const int tid = threadIdx.x;
    const int mbase = blockIdx.y * 128, nbase = blockIdx.x * 128;
    const int w = tid >> 5, lane = tid & 31;
    const int warpM = w & 1, warpN = w >> 1;      // 2 x 4 warps -> 64x32 warp tiles
    const int g = lane >> 2, tg = lane & 3;

    float acc[4][4][4];
#pragma unroll
    for (int i = 0; i < 4; i++)
#pragma unroll
        for (int j = 0; j < 4; j++)
#pragma unroll
            for (int q = 0; q < 4; q++) acc[i][j][q] = 0.f;

    // loader: 128x16 tile = 512 float4; thread handles float4 ids tid, tid+256
    const int ar0 = tid >> 2,          ac0 = (tid & 3) * 4;
    const int ar1 = (tid + 256) >> 2,  ac1 = ((tid + 256) & 3) * 4;

    const int nCh = K / BKC;
    float4 pa0, pa1, pb0, pb1;

    // prologue: load chunk 0
    pa0 = *(const float4*)(A  + (size_t)(mbase + ar0) * K + ac0);
    pa1 = *(const float4*)(A  + (size_t)(mbase + ar1) * K + ac1);
    pb0 = *(const float4*)(Bt + (size_t)(nbase + ar0) * K + ac0);
    pb1 = *(const float4*)(Bt + (size_t)(nbase + ar1) * K + ac1);
    *(float4*)&As[0][ar0 * LDS_STRIDE + ac0] = pa0;
    *(float4*)&As[0][ar1 * LDS_STRIDE + ac1] = pa1;
    *(float4*)&Bs[0][ar0 * LDS_STRIDE + ac0] = pb0;
    *(float4*)&Bs[0][ar1 * LDS_STRIDE + ac1] = pb1;

    for (int t = 0; t < nCh; t++) {
        __syncthreads();
        if (t + 1 < nCh) {
            int kb = (t + 1) * BKC;
            pa0 = *(const float4*)(A  + (size_t)(mbase + ar0) * K + kb + ac0);
            pa1 = *(const float4*)(A  + (size_t)(mbase + ar1) * K + kb + ac1);
            pb0 = *(const float4*)(Bt + (size_t)(nbase + ar0) * K + kb + ac0);
            pb1 = *(const float4*)(Bt + (size_t)(nbase + ar1) * K + kb + ac1);
        }
        const float* as = As[t & 1];
        const float* bs = Bs[t & 1];
#pragma unroll
        for (int ks = 0; ks < 2; ks++) {
            const int kc = ks * 8 + tg;
            // B fragments for all 4 n-tiles, split
            uint32_t Bhi[4][2], Blo[4][2];
#pragma unroll
            for (int j = 0; j < 4; j++) {
                int nr = warpN * 32 + j * 8 + g;
                float b0 = bs[nr * LDS_STRIDE + kc];
                float b1 = bs[nr * LDS_STRIDE + kc + 4];
                split32(b0, Bhi[j][0], Blo[j][0]);
                split32(b1, Bhi[j][1], Blo[j][1]);
            }
#pragma unroll
            for (int i = 0; i < 4; i++) {
                int r0 = (warpM * 64 + i * 16 + g) * LDS_STRIDE;
                int r1 = r0 + 8 * LDS_STRIDE;
                uint32_t Ahi[4], Alo[4];
                split32(as[r0 + kc],     Ahi[0], Alo[0]);
                split32(as[r1 + kc],     Ahi[1], Alo[1]);
                split32(as[r0 + kc + 4], Ahi[2], Alo[2]);
                split32(as[r1 + kc + 4], Ahi[3], Alo[3]);
#pragma unroll
                for (int j = 0; j < 4; j++) {
                    MMA_TF32(acc[i][j], Ahi[0], Ahi[1], Ahi[2], Ahi[3], Bhi[j][0], Bhi[j][1]);
                    MMA_TF32(acc[i][j], Ahi[0], Ahi[1], Ahi[2], Ahi[3], Blo[j][0], Blo[j][1]);
                    MMA_TF32(acc[i][j], Alo[0], Alo[1], Alo[2], Alo[3], Bhi[j][0], Bhi[j][1]);
                }
            }
        }
        __syncthreads();
        if (t + 1 < nCh) {
            int s = (t + 1) & 1;
            *(float4*)&As[s][ar0 * LDS_STRIDE + ac0] = pa0;
            *(float4*)&As[s][ar1 * LDS_STRIDE + ac1] = pa1;
            *(float4*)&Bs[s][ar0 * LDS_STRIDE + ac0] = pb0;
            *(float4*)&Bs[s][ar1 * LDS_STRIDE + ac1] = pb1;
        }
    }

    // epilogue: c frag (row=g(+8), col=tg*2(+1))
#pragma unroll
    for (int i = 0; i < 4; i++) {
#pragma unroll
        for (int j = 0; j < 4; j++) {
            int row = mbase + warpM * 64 + i * 16 + g;
            int col = nbase + warpN * 32 + j * 8 + tg * 2;
            float b0v = bias[col], b1v = bias[col + 1];
            float2 v0 = make_float2(acc[i][j][0] + b0v, acc[i][j][1] + b1v);
            float2 v1 = make_float2(acc[i][j][2] + b0v, acc[i][j][3] + b1v);
            *(float2*)(C + (size_t)row * N_ + col)       = v0;
            *(float2*)(C + (size_t)(row + 8) * N_ + col) = v1;
        }
    }
}

// ---------------- prep kernels ----------------
__global__ void prep_wbigT(const float* __restrict__ Wioux, const float* __restrict__ Wiouh,
                           const float* __restrict__ Wfx,
                           const float* __restrict__ bioux, const float* __restrict__ biouh,
                           const float* __restrict__ bfx) {
    int idx = blockIdx.x * blockDim.x + threadIdx.x;
    if (idx < 2048 * 1024) {
        int n = idx >> 10, k = idx & 1023;
        float v;
        if (n < G3M) v = (k < MM) ? Wioux[(size_t)k * G3M + n] : Wiouh[(size_t)(k - MM) * G3M + n];
        else         v = (k < MM) ? Wfx[(size_t)k * MM + (n - G3M)] : 0.0f;
        g_WbigT[idx] = v;
    }
    if (idx < 2048)
        g_biasbig[idx] = (idx < G3M) ? (bioux[idx] + biouh[idx]) : bfx[idx - G3M];
}

__global__ void prep_wfhT(const float* __restrict__ Wfh) {
    int idx = blockIdx.x * blockDim.x + threadIdx.x;
    if (idx >= MM * MM) return;
    int n = idx >> 9, k = idx & 511;
    g_WfhT[idx] = Wfh[(size_t)k * MM + n];
}

// ---------------- init ----------------
__global__ void init_leaf(const float* __restrict__ embed, const int* __restrict__ leaf_idx) {
    int idx = blockIdx.x * blockDim.x + threadIdx.x;
    if (idx >= NLEAF * (MM / 4)) return;
    int n = idx >> 7, m = (idx & 127) * 4;
    int w = leaf_idx[n];
    float4 v = *(const float4*)(embed + (size_t)w * MM + m);
    *(float4*)(g_h_pool + (size_t)(1 + n) * MM + m) = v;
    *(float4*)(g_c_pool + (size_t)(1 + n) * MM + m) = make_float4(0.f, 0.f, 0.f, 0.f);
}

__global__ void init_misc(float* __restrict__ out, const float* __restrict__ bfh) {
    int idx = blockIdx.x * blockDim.x + threadIdx.x;
    if (idx < MM) {
        g_h_pool[idx] = 0.f; g_c_pool[idx] = 0.f;
        g_HW[idx] = bfh[idx];       // HW of zero slot
    }
    if (idx < 2 * BB * MM) (&g_hst[0][0])[idx] = 0.f;
    if (idx < BB * SSEQ * MM) out[idx] = 0.f;
}

// ---------------- per-level gather ----------------
__global__ void gather_level(const float* __restrict__ embed, const int* __restrict__ lwi,
                             const int* __restrict__ child, int d) {
    int idx = blockIdx.x * blockDim.x + threadIdx.x;
    if (idx >= NNODE * (MM / 4)) return;
    int n = idx >> 7, m = (idx & 127) * 4;
    int w = lwi[d * NNODE + n];
    float4 x = *(const float4*)(embed + (size_t)w * MM + m);
    *(float4*)(g_XH + (size_t)n * 1024 + m) = x;
    float4 s = make_float4(0.f, 0.f, 0.f, 0.f);
    const int* ch = child + ((size_t)d * NNODE + n) * KCH;
#pragma unroll
    for (int k = 0; k < KCH; k++) {
        int ci = ch[k];
        float4 hv = *(const float4*)(g_h_pool + (size_t)ci * MM + m);
        s.x += hv.x; s.y += hv.y; s.z += hv.z; s.w += hv.w;
    }
    *(float4*)(g_XH + (size_t)n * 1024 + MM + m) = s;
}

// ---------------- level pointwise (forget path = gathered HW[child]) ----------------
__global__ void level_point(const int* __restrict__ child, int d) {
    int idx = blockIdx.x * blockDim.x + threadIdx.x;
    if (idx >= NNODE * MM) return;
    int n = idx >> 9, m = idx & 511;
    const float* row = g_IOUF + (size_t)n * 2048;
    float iv = sigf(row[m]);
    float ov = sigf(row[MM + m]);
    float uv = tanhf(row[2 * MM + m]);
    float fx = row[3 * MM + m];
    float c = iv * uv;
    const int* ch = child + ((size_t)d * NNODE + n) * KCH;
#pragma unroll
    for (int k = 0; k < KCH; k++) {
        int ci = ch[k];
        float f = sigf(fx + g_HW[(size_t)ci * MM + m]);
        c += f * g_c_pool[(size_t)ci * MM + m];
    }
    float h = ov * tanhf(c);
    size_t slot = (size_t)(OFFS + d * NNODE + n) * MM + m;
    g_c_pool[slot] = c;
    g_h_pool[slot] = h;
}

// ---------------- GRU ----------------
__global__ void gather_xs(const int* __restrict__ ctx) {
    int idx = blockIdx.x * blockDim.x + threadIdx.x;
    if (idx >= BB * SSEQ * (MM / 4)) return;
    int rowI = idx >> 7, m = (idx & 127) * 4;
    int p = ctx[rowI];
    *(float4*)(g_xs + (size_t)rowI * MM + m) =
        *(const float4*)(g_h_pool + (size_t)p * MM + m);
}

__global__ void __launch_bounds__(256) gru_gemm(const float* __restrict__ whh_f,
                                                const float* __restrict__ whh_b,
                                                const float* __restrict__ bhh_f,
                                                const float* __restrict__ bhh_b) {
    extern __shared__ float sh[];
    float* Hs = sh;                 // 64 x 513
    float* Ws = sh + 64 * 513;      // 32 x 513
    int dir = blockIdx.y;
    const float* whh = dir ? whh_b : whh_f;
    const float* bhh = dir ? bhh_b : bhh_f;
    const float* H = g_hst[dir];
    int n0 = blockIdx.x * 32;
    int tid = threadIdx.x;

    for (int i = tid; i < 64 * 512; i += 256) Hs[(i >> 9) * 513 + (i & 511)] = H[i];
    for (int i = tid; i < 32 * 512; i += 256) {
        int rr = i >> 9, kk = i & 511;
        Ws[rr * 513 + kk] = whh[(size_t)(n0 + rr) * MM + kk];
    }
    __syncthreads();

    int cg = tid & 7, r = tid >> 3;
    int row0 = 2 * r, row1 = 2 * r + 1;
    float acc0[4] = {0.f, 0.f, 0.f, 0.f};
    float acc1[4] = {0.f, 0.f, 0.f, 0.f};
    for (int k = 0; k < 512; k++) {
        float h0 = Hs[row0 * 513 + k];
        float h1 = Hs[row1 * 513 + k];
#pragma unroll
        for (int c = 0; c < 4; c++) {
            float w = Ws[(cg * 4 + c) * 513 + k];
            acc0[c] += h0 * w;
            acc1[c] += h1 * w;
        }
    }
#pragma unroll
    for (int c = 0; c < 4; c++) {
        int n = n0 + cg * 4 + c;
        float bv = bhh[n];
        g_hg[dir][(size_t)row0 * G3M + n] = acc0[c] + bv;
        g_hg[dir][(size_t)row1 * G3M + n] = acc1[c] + bv;
    }
}

__global__ void gru_point(float* __restrict__ out, int t) {
    int idx = blockIdx.x * blockDim.x + threadIdx.x;
    if (idx >= 2 * BB * MM) return;
    int dir = idx >> 15;
    int rem = idx & 32767;
    int b = rem >> 9, j = rem & 511;
    int pos = dir ? (SSEQ - 1 - t) : t;
    const float* xrow = g_xg[dir] + (size_t)(b * SSEQ + pos) * G3M;
    const float* hrow = g_hg[dir] + (size_t)b * G3M;
    float r = sigf(xrow[j] + hrow[j]);
    float z = sigf(xrow[MM + j] + hrow[MM + j]);
    float nn = tanhf(xrow[2 * MM + j] + r * hrow[2 * MM + j]);
    float hp = g_hst[dir][b * MM + j];
    float hn = (1.f - z) * nn + z * hp;
    g_hst[dir][b * MM + j] = hn;
    out[(size_t)(b * SSEQ + pos) * MM + j] += hn;
}

// ---------------- host launch ----------------
extern "C" void kernel_launch(void* const* d_in, const int* in_sizes, int n_in,
                              void* d_out, int out_size) {
    const float* embed   = (const float*)d_in[0];
    const float* Wioux   = (const float*)d_in[1];
    const float* bioux   = (const float*)d_in[2];
    const float* Wiouh   = (const float*)d_in[3];
    const float* biouh   = (const float*)d_in[4];
    const float* Wfx     = (const float*)d_in[5];
    const float* bfx     = (const float*)d_in[6];
    const float* Wfh     = (const float*)d_in[7];
    const float* bfh     = (const float*)d_in[8];
    const float* wih_f   = (const float*)d_in[9];
    const float* whh_f   = (const float*)d_in[10];
    const float* bih_f   = (const float*)d_in[11];
    const float* bhh_f   = (const float*)d_in[12];
    const float* wih_b   = (const float*)d_in[13];
    const float* whh_b   = (const float*)d_in[14];
    const float* bih_b   = (const float*)d_in[15];
    const float* bhh_b   = (const float*)d_in[16];

    const int* leaf_idx = nullptr; const int* level_idx = nullptr;
    const int* child = nullptr; const int* ctx = nullptr;
    for (int i = 17; i < n_in; i++) {
        int sz = in_sizes[i];
        if (sz == NLEAF)                 leaf_idx  = (const int*)d_in[i];
        else if (sz == DD * NNODE)       level_idx = (const int*)d_in[i];
        else if (sz == DD * NNODE * KCH) child     = (const int*)d_in[i];
        else if (sz == BB * SSEQ)        ctx       = (const int*)d_in[i];
    }

    float* out = (float*)d_out;

    cudaFuncSetAttribute(gru_gemm, cudaFuncAttributeMaxDynamicSharedMemorySize,
                         (64 + 32) * 513 * sizeof(float));

    float* d_hpool;  cudaGetSymbolAddress((void**)&d_hpool, g_h_pool);
    float* d_XH;     cudaGetSymbolAddress((void**)&d_XH, g_XH);
    float* d_IOUF;   cudaGetSymbolAddress((void**)&d_IOUF, g_IOUF);
    float* d_HW;     cudaGetSymbolAddress((void**)&d_HW, g_HW);
    float* d_WbT;    cudaGetSymbolAddress((void**)&d_WbT, g_WbigT);
    float* d_WfT;    cudaGetSymbolAddress((void**)&d_WfT, g_WfhT);
    float* d_bb;     cudaGetSymbolAddress((void**)&d_bb, g_biasbig);
    float* d_xs;     cudaGetSymbolAddress((void**)&d_xs, g_xs);
    float* d_xg;     cudaGetSymbolAddress((void**)&d_xg, g_xg);

    // prep + init
    prep_wbigT<<<(2048 * 1024 + 255) / 256, 256>>>(Wioux, Wiouh, Wfx, bioux, biouh, bfx);
    prep_wfhT<<<(MM * MM + 255) / 256, 256>>>(Wfh);
    init_leaf<<<(NLEAF * (MM / 4) + 255) / 256, 256>>>(embed, leaf_idx);
    init_misc<<<(BB * SSEQ * MM + 255) / 256, 256>>>(out, bfh);

    // leaf HW: HW[1..NLEAF] = h_pool[1..NLEAF] @ WfhT^T + bfh
    {
        dim3 grid(512 / 128, NLEAF / 128);
        mma_gemm<<<grid, 256>>>(d_hpool + MM, d_WfT, bfh, d_HW + MM, 512, 512);
    }

    // tree levels
    for (int d = 0; d < DD; d++) {
        gather_level<<<(NNODE * (MM / 4) + 255) / 256, 256>>>(embed, level_idx, child, d);
        {   // IOUF(4096x2048) = XH(4096x1024) @ WbigT^T
            dim3 grid(2048 / 128, 4096 / 128);
            mma_gemm<<<grid, 256>>>(d_XH, d_WbT, d_bb, d_IOUF, 2048, 1024);
        }
        level_point<<<(NNODE * MM + 255) / 256, 256>>>(child, d);
        if (d < DD - 1) {   // HW for the new 4096 nodes
            dim3 grid(512 / 128, NNODE / 128);
            size_t off = (size_t)(OFFS + d * NNODE) * MM;
            mma_gemm<<<grid, 256>>>(d_hpool + off, d_WfT, bfh, d_HW + off, 512, 512);
        }
    }

    // GRU input gates: xg[dir](1024x1536) = xs(1024x512) @ wih^T  (wih is already NxK)
    gather_xs<<<(BB * SSEQ * (MM / 4) + 255) / 256, 256>>>(ctx);
    {
        dim3 grid(G3M / 128, (BB * SSEQ) / 128);
        mma_gemm<<<grid, 256>>>(d_xs, wih_f, bih_f, d_xg, G3M, 512);
        mma_gemm<<<grid, 256>>>(d_xs, wih_b, bih_b, d_xg + (size_t)BB * SSEQ * G3M, G3M, 512);
    }

    // GRU recurrence
    size_t smem = (64 + 32) * 513 * sizeof(float);
    for (int t = 0; t < SSEQ; t++) {
        dim3 grid(G3M / 32, 2);
        gru_gemm<<<grid, 256, smem>>>(whh_f, whh_b, bhh_f, bhh_b);
        gru_point<<<(2 * BB * MM + 255) / 256, 256>>>(out, t);
    }
}

// round 5
// speedup vs baseline: 2.0226x; 1.3533x over previous
#include <cuda_runtime.h>
#include <math.h>
#include <cstdint>

// ---------------- problem constants ----------------
#define VV     32000
#define MM     512
#define NLEAF  16384
#define DD     8
#define NNODE  4096
#define KCH    4
#define BB     64
#define SSEQ   16
#define POOLSZ (1 + NLEAF + DD * NNODE)   // 49153
#define OFFS   (1 + NLEAF)                // 16385
#define G3M    (3 * MM)                   // 1536

__device__ __forceinline__ float sigf(float x) { return 1.0f / (1.0f + expf(-x)); }

// split (x,y) into packed bf16x2 hi + bf16x2 lo (lower 16 bits = x)
__device__ __forceinline__ void splitpack(float x, float y, uint32_t& hi, uint32_t& lo) {
    uint32_t h;
    asm("cvt.rn.bf16x2.f32 %0, %1, %2;" : "=r"(h) : "f"(y), "f"(x));  // upper=y, lower=x
    float hx = __uint_as_float(h << 16);
    float hy = __uint_as_float(h & 0xFFFF0000u);
    float rx = x - hx, ry = y - hy;
    asm("cvt.rn.bf16x2.f32 %0, %1, %2;" : "=r"(lo) : "f"(ry), "f"(rx));
    hi = h;
}

#define MMA_BF16(c, a0, a1, a2, a3, b0, b1) \
    asm volatile("mma.sync.aligned.m16n8k16.row.col.f32.bf16.bf16.f32 " \
        "{%0,%1,%2,%3}, {%4,%5,%6,%7}, {%8,%9}, {%0,%1,%2,%3};" \
        : "+f"((c)[0]), "+f"((c)[1]), "+f"((c)[2]), "+f"((c)[3]) \
        : "r"(a0), "r"(a1), "r"(a2), "r"(a3), "r"(b0), "r"(b1))

// ---------------- device scratch ----------------
__device__ float g_c_pool[(size_t)POOLSZ * MM];
__device__ float g_h_pool[(size_t)POOLSZ * MM];
__device__ float g_HW[(size_t)POOLSZ * MM];     // h_pool @ W_fh + b_fh
__device__ float g_XH[(size_t)NNODE * 1024];    // [x | sum child h]
__device__ float g_IOUF[(size_t)NNODE * 2048];  // [iou(1536) | fx(512)]
__device__ float g_WbigT[(size_t)2048 * 1024];  // [[Wioux|Wfx],[Wiouh|0]]^T (N x K)
__device__ float g_WfhT[(size_t)MM * MM];       // Wfh^T (N x K)
__device__ float g_biasbig[2048];
__device__ float g_xs[(size_t)BB * SSEQ * MM];
__device__ float g_xg[2][(size_t)BB * SSEQ * G3M];
__device__ float g_hg[2][(size_t)BB * G3M];
__device__ float g_hst[2][(size_t)BB * MM];

// ---------------- bf16x3 mma GEMM: C = A(MxK) @ Bt(NxK)^T + bias ----------------
// grid = (N/128, M/128); 256 threads; BK=32; double-buffered dynamic smem.
// smem words per stage: Ahi/Alo/Bhi/Blo each 128*20 = 2560 words.
#define BKC 32
#define RS 20            // b32 words per bf16 row (16 data + 4 pad) -> conflict-free
#define STG_WORDS 10240  // 4 * 2560

__global__ void __launch_bounds__(256)
mma_gemm(const float* __restrict__ A, const float* __restrict__ Bt,
         const float* __restrict__ bias, float* __restrict__ C, int N_, int K) {
    extern __shared__ uint32_t sm[];

    const int tid = threadIdx.x;
    const int mbase = blockIdx.y * 128, nbase = blockIdx.x * 128;
    const int w = tid >> 5, lane = tid & 31;
    const int warpM = w & 1, warpN = w >> 1;      // 2x4 warps -> 64x32 warp tiles
    const int g = lane >> 2, tg = lane & 3;

    float acc[4][4][4];
#pragma unroll
    for (int i = 0; i < 4; i++)
#pragma unroll
        for (int j = 0; j < 4; j++)
#pragma unroll
            for (int q = 0; q < 4; q++) acc[i][j][q] = 0.f;

    // loader: 128x32 fp32 tile = 1024 float4; thread handles 4 float4 (A) + 4 (B)
    // id = tid + q*256 ; row = id>>3 ; c4 = id&7 ; k = c4*4
    uint32_t pAh[8], pAl[8], pBh[8], pBl[8];

    const int nCh = K / BKC;

#define LOAD_SPLIT(kb) do {                                                      \
    _Pragma("unroll")                                                            \
    for (int q = 0; q < 4; q++) {                                                \
        int id = tid + q * 256;                                                  \
        int r = id >> 3, c4 = id & 7;                                            \
        float4 va = *(const float4*)(A  + (size_t)(mbase + r) * K + (kb) + c4 * 4); \
        float4 vb = *(const float4*)(Bt + (size_t)(nbase + r) * K + (kb) + c4 * 4); \
        splitpack(va.x, va.y, pAh[q * 2], pAl[q * 2]);                           \
        splitpack(va.z, va.w, pAh[q * 2 + 1], pAl[q * 2 + 1]);                   \
        splitpack(vb.x, vb.y, pBh[q * 2], pBl[q * 2]);                           \
        splitpack(vb.z, vb.w, pBh[q * 2 + 1], pBl[q * 2 + 1]);                   \
    } } while (0)

#define STORE_STAGE(s) do {                                                      \
    uint32_t* st = sm + (s) * STG_WORDS;                                         \
    _Pragma("unroll")                                                            \
    for (int q = 0; q < 4; q++) {                                                \
        int id = tid + q * 256;                                                  \
        int r = id >> 3, c4 = id & 7;                                            \
        int wrd = r * RS + c4 * 2;                                               \
        st[wrd]            = pAh[q * 2];     st[wrd + 1]            = pAh[q * 2 + 1]; \
        st[2560 + wrd]     = pAl[q * 2];     st[2560 + wrd + 1]     = pAl[q * 2 + 1]; \
        st[5120 + wrd]     = pBh[q * 2];     st[5120 + wrd + 1]     = pBh[q * 2 + 1]; \
        st[7680 + wrd]     = pBl[q * 2];     st[7680 + wrd + 1]     = pBl[q * 2 + 1]; \
    } } while (0)

    LOAD_SPLIT(0);
    STORE_STAGE(0);

    for (int t = 0; t < nCh; t++) {
        __syncthreads();
        if (t + 1 < nCh) LOAD_SPLIT((t + 1) * BKC);

        const uint32_t* st = sm + (t & 1) * STG_WORDS;
        const uint32_t* ah = st;
        const uint32_t* al = st + 2560;
        const uint32_t* bh = st + 5120;
        const uint32_t* bl = st + 7680;

#pragma unroll
        for (int ks = 0; ks < 2; ks++) {          // two k16 steps in BK=32
            const int kw = ks * 8 + tg;           // word offset in row
            uint32_t Bh[4][2], Bl[4][2];
#pragma unroll
            for (int j = 0; j < 4; j++) {
                int nr = (warpN * 32 + j * 8 + g) * RS;
                Bh[j][0] = bh[nr + kw]; Bh[j][1] = bh[nr + kw + 4];
                Bl[j][0] = bl[nr + kw]; Bl[j][1] = bl[nr + kw + 4];
            }
#pragma unroll
            for (int i = 0; i < 4; i++) {
                int r0 = (warpM * 64 + i * 16 + g) * RS;
                int r1 = r0 + 8 * RS;
                uint32_t Ah0 = ah[r0 + kw], Ah1 = ah[r1 + kw];
                uint32_t Ah2 = ah[r0 + kw + 4], Ah3 = ah[r1 + kw + 4];
                uint32_t Al0 = al[r0 + kw], Al1 = al[r1 + kw];
                uint32_t Al2 = al[r0 + kw + 4], Al3 = al[r1 + kw + 4];
#pragma unroll
                for (int j = 0; j < 4; j++) {
                    MMA_BF16(acc[i][j], Ah0, Ah1, Ah2, Ah3, Bh[j][0], Bh[j][1]);
                    MMA_BF16(acc[i][j], Ah0, Ah1, Ah2, Ah3, Bl[j][0], Bl[j][1]);
                    MMA_BF16(acc[i][j], Al0, Al1, Al2, Al3, Bh[j][0], Bh[j][1]);
                }
            }
        }
        __syncthreads();
        if (t + 1 < nCh) STORE_STAGE((t + 1) & 1);
    }

    // epilogue: c frag rows g, g+8; cols tg*2, tg*2+1
#pragma unroll
    for (int i = 0; i < 4; i++) {
#pragma unroll
        for (int j = 0; j < 4; j++) {
            int row = mbase + warpM * 64 + i * 16 + g;
            int col = nbase + warpN * 32 + j * 8 + tg * 2;
            float b0v = bias[col], b1v = bias[col + 1];
            float2 v0 = make_float2(acc[i][j][0] + b0v, acc[i][j][1] + b1v);
            float2 v1 = make_float2(acc[i][j][2] + b0v, acc[i][j][3] + b1v);
            *(float2*)(C + (size_t)row * N_ + col)       = v0;
            *(float2*)(C + (size_t)(row + 8) * N_ + col) = v1;
        }
    }
}
#define MMA_SMEM_BYTES (2 * STG_WORDS * 4)

// ---------------- prep kernels ----------------
__global__ void prep_wbigT(const float* __restrict__ Wioux, const float* __restrict__ Wiouh,
                           const float* __restrict__ Wfx,
                           const float* __restrict__ bioux, const float* __restrict__ biouh,
                           const float* __restrict__ bfx) {
    int idx = blockIdx.x * blockDim.x + threadIdx.x;
    if (idx < 2048 * 1024) {
        int n = idx >> 10, k = idx & 1023;
        float v;
        if (n < G3M) v = (k < MM) ? Wioux[(size_t)k * G3M + n] : Wiouh[(size_t)(k - MM) * G3M + n];
        else         v = (k < MM) ? Wfx[(size_t)k * MM + (n - G3M)] : 0.0f;
        g_WbigT[idx] = v;
    }
    if (idx < 2048)
        g_biasbig[idx] = (idx < G3M) ? (bioux[idx] + biouh[idx]) : bfx[idx - G3M];
}

__global__ void prep_wfhT(const float* __restrict__ Wfh) {
    int idx = blockIdx.x * blockDim.x + threadIdx.x;
    if (idx >= MM * MM) return;
    int n = idx >> 9, k = idx & 511;
    g_WfhT[idx] = Wfh[(size_t)k * MM + n];
}

// ---------------- init ----------------
__global__ void init_leaf(const float* __restrict__ embed, const int* __restrict__ leaf_idx) {
    int idx = blockIdx.x * blockDim.x + threadIdx.x;
    if (idx >= NLEAF * (MM / 4)) return;
    int n = idx >> 7, m = (idx & 127) * 4;
    int w = leaf_idx[n];
    float4 v = *(const float4*)(embed + (size_t)w * MM + m);
    *(float4*)(g_h_pool + (size_t)(1 + n) * MM + m) = v;
    *(float4*)(g_c_pool + (size_t)(1 + n) * MM + m) = make_float4(0.f, 0.f, 0.f, 0.f);
}

__global__ void init_misc(float* __restrict__ out, const float* __restrict__ bfh) {
    int idx = blockIdx.x * blockDim.x + threadIdx.x;
    if (idx < MM) {
        g_h_pool[idx] = 0.f; g_c_pool[idx] = 0.f;
        g_HW[idx] = bfh[idx];       // HW of zero slot
    }
    if (idx < 2 * BB * MM) (&g_hst[0][0])[idx] = 0.f;
    if (idx < BB * SSEQ * MM) out[idx] = 0.f;
}

// ---------------- per-level gather ----------------
__global__ void gather_level(const float* __restrict__ embed, const int* __restrict__ lwi,
                             const int* __restrict__ child, int d) {
    int idx = blockIdx.x * blockDim.x + threadIdx.x;
    if (idx >= NNODE * (MM / 4)) return;
    int n = idx >> 7, m = (idx & 127) * 4;
    int w = lwi[d * NNODE + n];
    float4 x = *(const float4*)(embed + (size_t)w * MM + m);
    *(float4*)(g_XH + (size_t)n * 1024 + m) = x;
    float4 s = make_float4(0.f, 0.f, 0.f, 0.f);
    const int* ch = child + ((size_t)d * NNODE + n) * KCH;
#pragma unroll
    for (int k = 0; k < KCH; k++) {
        int ci = ch[k];
        float4 hv = *(const float4*)(g_h_pool + (size_t)ci * MM + m);
        s.x += hv.x; s.y += hv.y; s.z += hv.z; s.w += hv.w;
    }
    *(float4*)(g_XH + (size_t)n * 1024 + MM + m) = s;
}

// ---------------- level pointwise (forget path = gathered HW[child]) ----------------
__global__ void level_point(const int* __restrict__ child, int d) {
    int idx = blockIdx.x * blockDim.x + threadIdx.x;
    if (idx >= NNODE * MM) return;
    int n = idx >> 9, m = idx & 511;
    const float* row = g_IOUF + (size_t)n * 2048;
    float iv = sigf(row[m]);
    float ov = sigf(row[MM + m]);
    float uv = tanhf(row[2 * MM + m]);
    float fx = row[3 * MM + m];
    float c = iv * uv;
    const int* ch = child + ((size_t)d * NNODE + n) * KCH;
#pragma unroll
    for (int k = 0; k < KCH; k++) {
        int ci = ch[k];
        float f = sigf(fx + g_HW[(size_t)ci * MM + m]);
        c += f * g_c_pool[(size_t)ci * MM + m];
    }
    float h = ov * tanhf(c);
    size_t slot = (size_t)(OFFS + d * NNODE + n) * MM + m;
    g_c_pool[slot] = c;
    g_h_pool[slot] = h;
}

// ---------------- GRU ----------------
__global__ void gather_xs(const int* __restrict__ ctx) {
    int idx = blockIdx.x * blockDim.x + threadIdx.x;
    if (idx >= BB * SSEQ * (MM / 4)) return;
    int rowI = idx >> 7, m = (idx & 127) * 4;
    int p = ctx[rowI];
    *(float4*)(g_xs + (size_t)rowI * MM + m) =
        *(const float4*)(g_h_pool + (size_t)p * MM + m);
}

__global__ void __launch_bounds__(256) gru_gemm(const float* __restrict__ whh_f,
                                                const float* __restrict__ whh_b,
                                                const float* __restrict__ bhh_f,
                                                const float* __restrict__ bhh_b) {
    extern __shared__ float sh[];
    float* Hs = sh;                 // 64 x 513
    float* Ws = sh + 64 * 513;      // 32 x 513
    int dir = blockIdx.y;
    const float* whh = dir ? whh_b : whh_f;
    const float* bhh = dir ? bhh_b : bhh_f;
    const float* H = g_hst[dir];
    int n0 = blockIdx.x * 32;
    int tid = threadIdx.x;

    for (int i = tid; i < 64 * 512; i += 256) Hs[(i >> 9) * 513 + (i & 511)] = H[i];
    for (int i = tid; i < 32 * 512; i += 256) {
        int rr = i >> 9, kk = i & 511;
        Ws[rr * 513 + kk] = whh[(size_t)(n0 + rr) * MM + kk];
    }
    __syncthreads();

    int cg = tid & 7, r = tid >> 3;
    int row0 = 2 * r, row1 = 2 * r + 1;
    float acc0[4] = {0.f, 0.f, 0.f, 0.f};
    float acc1[4] = {0.f, 0.f, 0.f, 0.f};
    for (int k = 0; k < 512; k++) {
        float h0 = Hs[row0 * 513 + k];
        float h1 = Hs[row1 * 513 + k];
#pragma unroll
        for (int c = 0; c < 4; c++) {
            float w = Ws[(cg * 4 + c) * 513 + k];
            acc0[c] += h0 * w;
            acc1[c] += h1 * w;
        }
    }
#pragma unroll
    for (int c = 0; c < 4; c++) {
        int n = n0 + cg * 4 + c;
        float bv = bhh[n];
        g_hg[dir][(size_t)row0 * G3M + n] = acc0[c] + bv;
        g_hg[dir][(size_t)row1 * G3M + n] = acc1[c] + bv;
    }
}

__global__ void gru_point(float* __restrict__ out, int t) {
    int idx = blockIdx.x * blockDim.x + threadIdx.x;
    if (idx >= 2 * BB * MM) return;
    int dir = idx >> 15;
    int rem = idx & 32767;
    int b = rem >> 9, j = rem & 511;
    int pos = dir ? (SSEQ - 1 - t) : t;
    const float* xrow = g_xg[dir] + (size_t)(b * SSEQ + pos) * G3M;
    const float* hrow = g_hg[dir] + (size_t)b * G3M;
    float r = sigf(xrow[j] + hrow[j]);
    float z = sigf(xrow[MM + j] + hrow[MM + j]);
    float nn = tanhf(xrow[2 * MM + j] + r * hrow[2 * MM + j]);
    float hp = g_hst[dir][b * MM + j];
    float hn = (1.f - z) * nn + z * hp;
    g_hst[dir][b * MM + j] = hn;
    out[(size_t)(b * SSEQ + pos) * MM + j] += hn;
}

// ---------------- host launch ----------------
extern "C" void kernel_launch(void* const* d_in, const int* in_sizes, int n_in,
                              void* d_out, int out_size) {
    const float* embed   = (const float*)d_in[0];
    const float* Wioux   = (const float*)d_in[1];
    const float* bioux   = (const float*)d_in[2];
    const float* Wiouh   = (const float*)d_in[3];
    const float* biouh   = (const float*)d_in[4];
    const float* Wfx     = (const float*)d_in[5];
    const float* bfx     = (const float*)d_in[6];
    const float* Wfh     = (const float*)d_in[7];
    const float* bfh     = (const float*)d_in[8];
    const float* wih_f   = (const float*)d_in[9];
    const float* whh_f   = (const float*)d_in[10];
    const float* bih_f   = (const float*)d_in[11];
    const float* bhh_f   = (const float*)d_in[12];
    const float* wih_b   = (const float*)d_in[13];
    const float* whh_b   = (const float*)d_in[14];
    const float* bih_b   = (const float*)d_in[15];
    const float* bhh_b   = (const float*)d_in[16];

    const int* leaf_idx = nullptr; const int* level_idx = nullptr;
    const int* child = nullptr; const int* ctx = nullptr;
    for (int i = 17; i < n_in; i++) {
        int sz = in_sizes[i];
        if (sz == NLEAF)                 leaf_idx  = (const int*)d_in[i];
        else if (sz == DD * NNODE)       level_idx = (const int*)d_in[i];
        else if (sz == DD * NNODE * KCH) child     = (const int*)d_in[i];
        else if (sz == BB * SSEQ)        ctx       = (const int*)d_in[i];
    }

    float* out = (float*)d_out;

    cudaFuncSetAttribute(mma_gemm, cudaFuncAttributeMaxDynamicSharedMemorySize, MMA_SMEM_BYTES);
    cudaFuncSetAttribute(gru_gemm, cudaFuncAttributeMaxDynamicSharedMemorySize,
                         (64 + 32) * 513 * sizeof(float));

    float* d_hpool;  cudaGetSymbolAddress((void**)&d_hpool, g_h_pool);
    float* d_XH;     cudaGetSymbolAddress((void**)&d_XH, g_XH);
    float* d_IOUF;   cudaGetSymbolAddress((void**)&d_IOUF, g_IOUF);
    float* d_HW;     cudaGetSymbolAddress((void**)&d_HW, g_HW);
    float* d_WbT;    cudaGetSymbolAddress((void**)&d_WbT, g_WbigT);
    float* d_WfT;    cudaGetSymbolAddress((void**)&d_WfT, g_WfhT);
    float* d_bb;     cudaGetSymbolAddress((void**)&d_bb, g_biasbig);
    float* d_xs;     cudaGetSymbolAddress((void**)&d_xs, g_xs);
    float* d_xg;     cudaGetSymbolAddress((void**)&d_xg, g_xg);

    // prep + init
    prep_wbigT<<<(2048 * 1024 + 255) / 256, 256>>>(Wioux, Wiouh, Wfx, bioux, biouh, bfx);
    prep_wfhT<<<(MM * MM + 255) / 256, 256>>>(Wfh);
    init_leaf<<<(NLEAF * (MM / 4) + 255) / 256, 256>>>(embed, leaf_idx);
    init_misc<<<(BB * SSEQ * MM + 255) / 256, 256>>>(out, bfh);

    // leaf HW: HW[1..NLEAF] = h_pool[1..NLEAF] @ WfhT^T + bfh
    {
        dim3 grid(512 / 128, NLEAF / 128);
        mma_gemm<<<grid, 256, MMA_SMEM_BYTES>>>(d_hpool + MM, d_WfT, bfh, d_HW + MM, 512, 512);
    }

    // tree levels
    for (int d = 0; d < DD; d++) {
        gather_level<<<(NNODE * (MM / 4) + 255) / 256, 256>>>(embed, level_idx, child, d);
        {   // IOUF(4096x2048) = XH(4096x1024) @ WbigT^T
            dim3 grid(2048 / 128, 4096 / 128);
            mma_gemm<<<grid, 256, MMA_SMEM_BYTES>>>(d_XH, d_WbT, d_bb, d_IOUF, 2048, 1024);
        }
        level_point<<<(NNODE * MM + 255) / 256, 256>>>(child, d);
        if (d < DD - 1) {   // HW for the new 4096 nodes
            dim3 grid(512 / 128, NNODE / 128);
            size_t off = (size_t)(OFFS + d * NNODE) * MM;
            mma_gemm<<<grid, 256, MMA_SMEM_BYTES>>>(d_hpool + off, d_WfT, bfh, d_HW + off, 512, 512);
        }
    }

    // GRU input gates: xg[dir](1024x1536) = xs(1024x512) @ wih^T  (wih is already NxK)
    gather_xs<<<(BB * SSEQ * (MM / 4) + 255) / 256, 256>>>(ctx);
    {
        dim3 grid(G3M / 128, (BB * SSEQ) / 128);
        mma_gemm<<<grid, 256, MMA_SMEM_BYTES>>>(d_xs, wih_f, bih_f, d_xg, G3M, 512);
        mma_gemm<<<grid, 256, MMA_SMEM_BYTES>>>(d_xs, wih_b, bih_b, d_xg + (size_t)BB * SSEQ * G3M, G3M, 512);
    }

    // GRU recurrence
    size_t smem = (64 + 32) * 513 * sizeof(float);
    for (int t = 0; t < SSEQ; t++) {
        dim3 grid(G3M / 32, 2);
        gru_gemm<<<grid, 256, smem>>>(whh_f, whh_b, bhh_f, bhh_b);
        gru_point<<<(2 * BB * MM + 255) / 256, 256>>>(out, t);
    }
}

// round 6
// speedup vs baseline: 2.2058x; 1.0906x over previous
#include <cuda_runtime.h>
#include <math.h>
#include <cstdint>

// ---------------- problem constants ----------------
#define VV     32000
#define MM     512
#define NLEAF  16384
#define DD     8
#define NNODE  4096
#define KCH    4
#define BB     64
#define SSEQ   16
#define POOLSZ (1 + NLEAF + DD * NNODE)   // 49153
#define OFFS   (1 + NLEAF)                // 16385
#define G3M    (3 * MM)                   // 1536

__device__ __forceinline__ float sigf(float x) { return 1.0f / (1.0f + expf(-x)); }

__device__ __forceinline__ uint32_t smem_u32(const void* p) {
    uint32_t a;
    asm("{ .reg .u64 t; cvta.to.shared.u64 t, %1; cvt.u32.u64 %0, t; }" : "=r"(a) : "l"(p));
    return a;
}

// split (x,y) into packed bf16x2 hi + bf16x2 lo (lower 16 bits = x)
__device__ __forceinline__ void splitpack(float x, float y, uint32_t& hi, uint32_t& lo) {
    uint32_t h;
    asm("cvt.rn.bf16x2.f32 %0, %1, %2;" : "=r"(h) : "f"(y), "f"(x));  // upper=y, lower=x
    float hx = __uint_as_float(h << 16);
    float hy = __uint_as_float(h & 0xFFFF0000u);
    float rx = x - hx, ry = y - hy;
    asm("cvt.rn.bf16x2.f32 %0, %1, %2;" : "=r"(lo) : "f"(ry), "f"(rx));
    hi = h;
}

#define MMA_BF16(c, a0, a1, a2, a3, b0, b1) \
    asm volatile("mma.sync.aligned.m16n8k16.row.col.f32.bf16.bf16.f32 " \
        "{%0,%1,%2,%3}, {%4,%5,%6,%7}, {%8,%9}, {%0,%1,%2,%3};" \
        : "+f"((c)[0]), "+f"((c)[1]), "+f"((c)[2]), "+f"((c)[3]) \
        : "r"(a0), "r"(a1), "r"(a2), "r"(a3), "r"(b0), "r"(b1))

#define LDSM_X4(r0, r1, r2, r3, addr) \
    asm volatile("ldmatrix.sync.aligned.m8n8.x4.shared.b16 {%0,%1,%2,%3}, [%4];" \
        : "=r"(r0), "=r"(r1), "=r"(r2), "=r"(r3) : "r"(addr))

// ---------------- device scratch ----------------
__device__ float g_c_pool[(size_t)POOLSZ * MM];
__device__ float g_h_pool[(size_t)POOLSZ * MM];
__device__ float g_HW[(size_t)POOLSZ * MM];     // h_pool @ W_fh + b_fh
__device__ float g_XH[(size_t)NNODE * 1024];    // [x | sum child h]
__device__ float g_IOUF[(size_t)NNODE * 2048];  // [iou(1536) | fx(512)]
__device__ float g_WbigT[(size_t)2048 * 1024];  // [[Wioux|Wfx],[Wiouh|0]]^T (N x K)
__device__ float g_WfhT[(size_t)MM * MM];       // Wfh^T (N x K)
__device__ float g_biasbig[2048];
__device__ float g_xs[(size_t)BB * SSEQ * MM];
__device__ float g_xg[2][(size_t)BB * SSEQ * G3M];
__device__ float g_hg[2][(size_t)BB * G3M];
__device__ float g_hst[2][(size_t)BB * MM];

// ---------------- bf16x3 mma GEMM with ldmatrix: C = A(MxK) @ Bt(NxK)^T + bias ----------------
#define BKC 32
#define RS 20              // b32 words per row (16 data + 4 pad) -> ldmatrix conflict-free
#define PLANE 2560         // words per plane (128 rows * RS)
#define STG_WORDS 10240    // 4 planes
#define STG_BYTES 40960

__global__ void __launch_bounds__(256)
mma_gemm(const float* __restrict__ A, const float* __restrict__ Bt,
         const float* __restrict__ bias, float* __restrict__ C, int N_, int K) {
    extern __shared__ uint32_t sm[];
    const uint32_t smb = smem_u32(sm);

    const int tid = threadIdx.x;
    const int mbase = blockIdx.y * 128, nbase = blockIdx.x * 128;
    const int w = tid >> 5, lane = tid & 31;
    const int warpM = w & 1, warpN = w >> 1;      // 2x4 warps -> 64x32 warp tiles

    float acc[4][4][4];
#pragma unroll
    for (int i = 0; i < 4; i++)
#pragma unroll
        for (int j = 0; j < 4; j++)
#pragma unroll
            for (int q = 0; q < 4; q++) acc[i][j][q] = 0.f;

    // ldmatrix per-lane base addresses (stage 0)
    const int lrow = lane & 15, lcol = lane >> 4;
    uint32_t aAddr[4], bAddr[2];
#pragma unroll
    for (int i = 0; i < 4; i++)
        aAddr[i] = smb + (uint32_t)(((warpM * 64 + i * 16 + lrow) * RS + lcol * 4) * 4);
#pragma unroll
    for (int jp = 0; jp < 2; jp++)
        bAddr[jp] = smb + (uint32_t)(2 * PLANE * 4 + ((warpN * 32 + jp * 16 + lrow) * RS + lcol * 4) * 4);

    // loader: 128x32 fp32 tile = 1024 float4; thread handles 4 float4 (A) + 4 (B)
    const int nCh = K / BKC;
    float4 ra[4], rb[4];

#define LOAD_RAW(kb) do {                                                        \
    _Pragma("unroll")                                                            \
    for (int q = 0; q < 4; q++) {                                                \
        int id = tid + q * 256;                                                  \
        int r = id >> 3, c4 = id & 7;                                            \
        ra[q] = *(const float4*)(A  + (size_t)(mbase + r) * K + (kb) + c4 * 4);  \
        rb[q] = *(const float4*)(Bt + (size_t)(nbase + r) * K + (kb) + c4 * 4);  \
    } } while (0)

#define CONVERT_STORE(s) do {                                                    \
    uint32_t* st = sm + (s) * STG_WORDS;                                         \
    _Pragma("unroll")                                                            \
    for (int q = 0; q < 4; q++) {                                                \
        int id = tid + q * 256;                                                  \
        int r = id >> 3, c4 = id & 7;                                            \
        int wrd = r * RS + c4 * 2;                                               \
        uint32_t h0, l0, h1, l1;                                                 \
        splitpack(ra[q].x, ra[q].y, h0, l0);                                     \
        splitpack(ra[q].z, ra[q].w, h1, l1);                                     \
        st[wrd] = h0; st[wrd + 1] = h1;                                          \
        st[PLANE + wrd] = l0; st[PLANE + wrd + 1] = l1;                          \
        splitpack(rb[q].x, rb[q].y, h0, l0);                                     \
        splitpack(rb[q].z, rb[q].w, h1, l1);                                     \
        st[2 * PLANE + wrd] = h0; st[2 * PLANE + wrd + 1] = h1;                  \
        st[3 * PLANE + wrd] = l0; st[3 * PLANE + wrd + 1] = l1;                  \
    } } while (0)

    LOAD_RAW(0);
    CONVERT_STORE(0);

    for (int t = 0; t < nCh; t++) {
        __syncthreads();                 // stage t visible; compute of t-1 done everywhere
        if (t + 1 < nCh) LOAD_RAW((t + 1) * BKC);

        const uint32_t so = (uint32_t)((t & 1) * STG_BYTES);
#pragma unroll
        for (int ks = 0; ks < 2; ks++) {
            const uint32_t ko = so + ks * 32;     // ks*8 words = 32 bytes
            uint32_t Bh[4][2], Bl[4][2];
#pragma unroll
            for (int jp = 0; jp < 2; jp++) {
                LDSM_X4(Bh[2 * jp][0], Bh[2 * jp + 1][0], Bh[2 * jp][1], Bh[2 * jp + 1][1],
                        bAddr[jp] + ko);
                LDSM_X4(Bl[2 * jp][0], Bl[2 * jp + 1][0], Bl[2 * jp][1], Bl[2 * jp + 1][1],
                        bAddr[jp] + PLANE * 4 + ko);
            }
#pragma unroll
            for (int i = 0; i < 4; i++) {
                uint32_t Ah0, Ah1, Ah2, Ah3, Al0, Al1, Al2, Al3;
                LDSM_X4(Ah0, Ah1, Ah2, Ah3, aAddr[i] + ko);
                LDSM_X4(Al0, Al1, Al2, Al3, aAddr[i] + PLANE * 4 + ko);
#pragma unroll
                for (int j = 0; j < 4; j++) {
                    MMA_BF16(acc[i][j], Ah0, Ah1, Ah2, Ah3, Bh[j][0], Bh[j][1]);
                    MMA_BF16(acc[i][j], Ah0, Ah1, Ah2, Ah3, Bl[j][0], Bl[j][1]);
                    MMA_BF16(acc[i][j], Al0, Al1, Al2, Al3, Bh[j][0], Bh[j][1]);
                }
            }
        }
        if (t + 1 < nCh) CONVERT_STORE((t + 1) & 1);
    }

    // epilogue
    const int g = lane >> 2, tg = lane & 3;
#pragma unroll
    for (int i = 0; i < 4; i++) {
#pragma unroll
        for (int j = 0; j < 4; j++) {
            int row = mbase + warpM * 64 + i * 16 + g;
            int col = nbase + warpN * 32 + j * 8 + tg * 2;
            float b0v = bias[col], b1v = bias[col + 1];
            float2 v0 = make_float2(acc[i][j][0] + b0v, acc[i][j][1] + b1v);
            float2 v1 = make_float2(acc[i][j][2] + b0v, acc[i][j][3] + b1v);
            *(float2*)(C + (size_t)row * N_ + col)       = v0;
            *(float2*)(C + (size_t)(row + 8) * N_ + col) = v1;
        }
    }
}
#define MMA_SMEM_BYTES (2 * STG_BYTES)

// ---------------- prep kernels ----------------
__global__ void prep_wbigT(const float* __restrict__ Wioux, const float* __restrict__ Wiouh,
                           const float* __restrict__ Wfx,
                           const float* __restrict__ bioux, const float* __restrict__ biouh,
                           const float* __restrict__ bfx) {
    int idx = blockIdx.x * blockDim.x + threadIdx.x;
    if (idx < 2048 * 1024) {
        int n = idx >> 10, k = idx & 1023;
        float v;
        if (n < G3M) v = (k < MM) ? Wioux[(size_t)k * G3M + n] : Wiouh[(size_t)(k - MM) * G3M + n];
        else         v = (k < MM) ? Wfx[(size_t)k * MM + (n - G3M)] : 0.0f;
        g_WbigT[idx] = v;
    }
    if (idx < 2048)
        g_biasbig[idx] = (idx < G3M) ? (bioux[idx] + biouh[idx]) : bfx[idx - G3M];
}

__global__ void prep_wfhT(const float* __restrict__ Wfh) {
    int idx = blockIdx.x * blockDim.x + threadIdx.x;
    if (idx >= MM * MM) return;
    int n = idx >> 9, k = idx & 511;
    g_WfhT[idx] = Wfh[(size_t)k * MM + n];
}

// ---------------- init ----------------
__global__ void init_leaf(const float* __restrict__ embed, const int* __restrict__ leaf_idx) {
    int idx = blockIdx.x * blockDim.x + threadIdx.x;
    if (idx >= NLEAF * (MM / 4)) return;
    int n = idx >> 7, m = (idx & 127) * 4;
    int w = leaf_idx[n];
    float4 v = *(const float4*)(embed + (size_t)w * MM + m);
    *(float4*)(g_h_pool + (size_t)(1 + n) * MM + m) = v;
    *(float4*)(g_c_pool + (size_t)(1 + n) * MM + m) = make_float4(0.f, 0.f, 0.f, 0.f);
}

__global__ void init_misc(float* __restrict__ out, const float* __restrict__ bfh) {
    int idx = blockIdx.x * blockDim.x + threadIdx.x;
    if (idx < MM) {
        g_h_pool[idx] = 0.f; g_c_pool[idx] = 0.f;
        g_HW[idx] = bfh[idx];       // HW of zero slot
    }
    if (idx < 2 * BB * MM) (&g_hst[0][0])[idx] = 0.f;
    if (idx < BB * SSEQ * MM) out[idx] = 0.f;
}

// ---------------- per-level gather ----------------
__global__ void gather_level(const float* __restrict__ embed, const int* __restrict__ lwi,
                             const int* __restrict__ child, int d) {
    int idx = blockIdx.x * blockDim.x + threadIdx.x;
    if (idx >= NNODE * (MM / 4)) return;
    int n = idx >> 7, m = (idx & 127) * 4;
    int w = lwi[d * NNODE + n];
    float4 x = *(const float4*)(embed + (size_t)w * MM + m);
    *(float4*)(g_XH + (size_t)n * 1024 + m) = x;
    float4 s = make_float4(0.f, 0.f, 0.f, 0.f);
    const int* ch = child + ((size_t)d * NNODE + n) * KCH;
#pragma unroll
    for (int k = 0; k < KCH; k++) {
        int ci = ch[k];
        float4 hv = *(const float4*)(g_h_pool + (size_t)ci * MM + m);
        s.x += hv.x; s.y += hv.y; s.z += hv.z; s.w += hv.w;
    }
    *(float4*)(g_XH + (size_t)n * 1024 + MM + m) = s;
}

// ---------------- level pointwise (forget path = gathered HW[child]) ----------------
__global__ void level_point(const int* __restrict__ child, int d) {
    int idx = blockIdx.x * blockDim.x + threadIdx.x;
    if (idx >= NNODE * MM) return;
    int n = idx >> 9, m = idx & 511;
    const float* row = g_IOUF + (size_t)n * 2048;
    float iv = sigf(row[m]);
    float ov = sigf(row[MM + m]);
    float uv = tanhf(row[2 * MM + m]);
    float fx = row[3 * MM + m];
    float c = iv * uv;
    const int* ch = child + ((size_t)d * NNODE + n) * KCH;
#pragma unroll
    for (int k = 0; k < KCH; k++) {
        int ci = ch[k];
        float f = sigf(fx + g_HW[(size_t)ci * MM + m]);
        c += f * g_c_pool[(size_t)ci * MM + m];
    }
    float h = ov * tanhf(c);
    size_t slot = (size_t)(OFFS + d * NNODE + n) * MM + m;
    g_c_pool[slot] = c;
    g_h_pool[slot] = h;
}

// ---------------- GRU ----------------
__global__ void gather_xs(const int* __restrict__ ctx) {
    int idx = blockIdx.x * blockDim.x + threadIdx.x;
    if (idx >= BB * SSEQ * (MM / 4)) return;
    int rowI = idx >> 7, m = (idx & 127) * 4;
    int p = ctx[rowI];
    *(float4*)(g_xs + (size_t)rowI * MM + m) =
        *(const float4*)(g_h_pool + (size_t)p * MM + m);
}

__global__ void __launch_bounds__(256) gru_gemm(const float* __restrict__ whh_f,
                                                const float* __restrict__ whh_b,
                                                const float* __restrict__ bhh_f,
                                                const float* __restrict__ bhh_b) {
    extern __shared__ float sh[];
    float* Hs = sh;                 // 64 x 513
    float* Ws = sh + 64 * 513;      // 32 x 513
    int dir = blockIdx.y;
    const float* whh = dir ? whh_b : whh_f;
    const float* bhh = dir ? bhh_b : bhh_f;
    const float* H = g_hst[dir];
    int n0 = blockIdx.x * 32;
    int tid = threadIdx.x;

    for (int i = tid; i < 64 * 512; i += 256) Hs[(i >> 9) * 513 + (i & 511)] = H[i];
    for (int i = tid; i < 32 * 512; i += 256) {
        int rr = i >> 9, kk = i & 511;
        Ws[rr * 513 + kk] = whh[(size_t)(n0 + rr) * MM + kk];
    }
    __syncthreads();

    int cg = tid & 7, r = tid >> 3;
    int row0 = 2 * r, row1 = 2 * r + 1;
    float acc0[4] = {0.f, 0.f, 0.f, 0.f};
    float acc1[4] = {0.f, 0.f, 0.f, 0.f};
    for (int k = 0; k < 512; k++) {
        float h0 = Hs[row0 * 513 + k];
        float h1 = Hs[row1 * 513 + k];
#pragma unroll
        for (int c = 0; c < 4; c++) {
            float w = Ws[(cg * 4 + c) * 513 + k];
            acc0[c] += h0 * w;
            acc1[c] += h1 * w;
        }
    }
#pragma unroll
    for (int c = 0; c < 4; c++) {
        int n = n0 + cg * 4 + c;
        float bv = bhh[n];
        g_hg[dir][(size_t)row0 * G3M + n] = acc0[c] + bv;
        g_hg[dir][(size_t)row1 * G3M + n] = acc1[c] + bv;
    }
}

__global__ void gru_point(float* __restrict__ out, int t) {
    int idx = blockIdx.x * blockDim.x + threadIdx.x;
    if (idx >= 2 * BB * MM) return;
    int dir = idx >> 15;
    int rem = idx & 32767;
    int b = rem >> 9, j = rem & 511;
    int pos = dir ? (SSEQ - 1 - t) : t;
    const float* xrow = g_xg[dir] + (size_t)(b * SSEQ + pos) * G3M;
    const float* hrow = g_hg[dir] + (size_t)b * G3M;
    float r = sigf(xrow[j] + hrow[j]);
    float z = sigf(xrow[MM + j] + hrow[MM + j]);
    float nn = tanhf(xrow[2 * MM + j] + r * hrow[2 * MM + j]);
    float hp = g_hst[dir][b * MM + j];
    float hn = (1.f - z) * nn + z * hp;
    g_hst[dir][b * MM + j] = hn;
    out[(size_t)(b * SSEQ + pos) * MM + j] += hn;
}

// ---------------- host launch ----------------
extern "C" void kernel_launch(void* const* d_in, const int* in_sizes, int n_in,
                              void* d_out, int out_size) {
    const float* embed   = (const float*)d_in[0];
    const float* Wioux   = (const float*)d_in[1];
    const float* bioux   = (const float*)d_in[2];
    const float* Wiouh   = (const float*)d_in[3];
    const float* biouh   = (const float*)d_in[4];
    const float* Wfx     = (const float*)d_in[5];
    const float* bfx     = (const float*)d_in[6];
    const float* Wfh     = (const float*)d_in[7];
    const float* bfh     = (const float*)d_in[8];
    const float* wih_f   = (const float*)d_in[9];
    const float* whh_f   = (const float*)d_in[10];
    const float* bih_f   = (const float*)d_in[11];
    const float* bhh_f   = (const float*)d_in[12];
    const float* wih_b   = (const float*)d_in[13];
    const float* whh_b   = (const float*)d_in[14];
    const float* bih_b   = (const float*)d_in[15];
    const float* bhh_b   = (const float*)d_in[16];

    const int* leaf_idx = nullptr; const int* level_idx = nullptr;
    const int* child = nullptr; const int* ctx = nullptr;
    for (int i = 17; i < n_in; i++) {
        int sz = in_sizes[i];
        if (sz == NLEAF)                 leaf_idx  = (const int*)d_in[i];
        else if (sz == DD * NNODE)       level_idx = (const int*)d_in[i];
        else if (sz == DD * NNODE * KCH) child     = (const int*)d_in[i];
        else if (sz == BB * SSEQ)        ctx       = (const int*)d_in[i];
    }

    float* out = (float*)d_out;

    cudaFuncSetAttribute(mma_gemm, cudaFuncAttributeMaxDynamicSharedMemorySize, MMA_SMEM_BYTES);
    cudaFuncSetAttribute(gru_gemm, cudaFuncAttributeMaxDynamicSharedMemorySize,
                         (64 + 32) * 513 * sizeof(float));

    float* d_hpool;  cudaGetSymbolAddress((void**)&d_hpool, g_h_pool);
    float* d_XH;     cudaGetSymbolAddress((void**)&d_XH, g_XH);
    float* d_IOUF;   cudaGetSymbolAddress((void**)&d_IOUF, g_IOUF);
    float* d_HW;     cudaGetSymbolAddress((void**)&d_HW, g_HW);
    float* d_WbT;    cudaGetSymbolAddress((void**)&d_WbT, g_WbigT);
    float* d_WfT;    cudaGetSymbolAddress((void**)&d_WfT, g_WfhT);
    float* d_bb;     cudaGetSymbolAddress((void**)&d_bb, g_biasbig);
    float* d_xs;     cudaGetSymbolAddress((void**)&d_xs, g_xs);
    float* d_xg;     cudaGetSymbolAddress((void**)&d_xg, g_xg);

    // prep + init
    prep_wbigT<<<(2048 * 1024 + 255) / 256, 256>>>(Wioux, Wiouh, Wfx, bioux, biouh, bfx);
    prep_wfhT<<<(MM * MM + 255) / 256, 256>>>(Wfh);
    init_leaf<<<(NLEAF * (MM / 4) + 255) / 256, 256>>>(embed, leaf_idx);
    init_misc<<<(BB * SSEQ * MM + 255) / 256, 256>>>(out, bfh);

    // leaf HW: HW[1..NLEAF] = h_pool[1..NLEAF] @ WfhT^T + bfh
    {
        dim3 grid(512 / 128, NLEAF / 128);
        mma_gemm<<<grid, 256, MMA_SMEM_BYTES>>>(d_hpool + MM, d_WfT, bfh, d_HW + MM, 512, 512);
    }

    // tree levels
    for (int d = 0; d < DD; d++) {
        gather_level<<<(NNODE * (MM / 4) + 255) / 256, 256>>>(embed, level_idx, child, d);
        {   // IOUF(4096x2048) = XH(4096x1024) @ WbigT^T
            dim3 grid(2048 / 128, 4096 / 128);
            mma_gemm<<<grid, 256, MMA_SMEM_BYTES>>>(d_XH, d_WbT, d_bb, d_IOUF, 2048, 1024);
        }
        level_point<<<(NNODE * MM + 255) / 256, 256>>>(child, d);
        if (d < DD - 1) {   // HW for the new 4096 nodes
            dim3 grid(512 / 128, NNODE / 128);
            size_t off = (size_t)(OFFS + d * NNODE) * MM;
            mma_gemm<<<grid, 256, MMA_SMEM_BYTES>>>(d_hpool + off, d_WfT, bfh, d_HW + off, 512, 512);
        }
    }

    // GRU input gates: xg[dir](1024x1536) = xs(1024x512) @ wih^T  (wih is already NxK)
    gather_xs<<<(BB * SSEQ * (MM / 4) + 255) / 256, 256>>>(ctx);
    {
        dim3 grid(G3M / 128, (BB * SSEQ) / 128);
        mma_gemm<<<grid, 256, MMA_SMEM_BYTES>>>(d_xs, wih_f, bih_f, d_xg, G3M, 512);
        mma_gemm<<<grid, 256, MMA_SMEM_BYTES>>>(d_xs, wih_b, bih_b, d_xg + (size_t)BB * SSEQ * G3M, G3M, 512);
    }

    // GRU recurrence
    size_t smem = (64 + 32) * 513 * sizeof(float);
    for (int t = 0; t < SSEQ; t++) {
        dim3 grid(G3M / 32, 2);
        gru_gemm<<<grid, 256, smem>>>(whh_f, whh_b, bhh_f, bhh_b);
        gru_point<<<(2 * BB * MM + 255) / 256, 256>>>(out, t);
    }
}

// round 7
// speedup vs baseline: 2.4293x; 1.1013x over previous
#include <cuda_runtime.h>
#include <cuda_bf16.h>
#include <math.h>
#include <cstdint>

// ---------------- problem constants ----------------
#define VV     32000
#define MM     512
#define NLEAF  16384
#define DD     8
#define NNODE  4096
#define KCH    4
#define BB     64
#define SSEQ   16
#define POOLSZ (1 + NLEAF + DD * NNODE)   // 49153
#define OFFS   (1 + NLEAF)                // 16385
#define G3M    (3 * MM)                   // 1536

__device__ __forceinline__ float sigf(float x) { return 1.0f / (1.0f + expf(-x)); }

__device__ __forceinline__ uint32_t smem_u32(const void* p) {
    uint32_t a;
    asm("{ .reg .u64 t; cvta.to.shared.u64 t, %1; cvt.u32.u64 %0, t; }" : "=r"(a) : "l"(p));
    return a;
}

// split (x,y) into packed bf16x2 hi + bf16x2 lo (lower 16 bits = x)
__device__ __forceinline__ void splitpack(float x, float y, uint32_t& hi, uint32_t& lo) {
    uint32_t h;
    asm("cvt.rn.bf16x2.f32 %0, %1, %2;" : "=r"(h) : "f"(y), "f"(x));  // upper=y, lower=x
    float hx = __uint_as_float(h << 16);
    float hy = __uint_as_float(h & 0xFFFF0000u);
    float rx = x - hx, ry = y - hy;
    asm("cvt.rn.bf16x2.f32 %0, %1, %2;" : "=r"(lo) : "f"(ry), "f"(rx));
    hi = h;
}

#define MMA_BF16(c, a0, a1, a2, a3, b0, b1) \
    asm volatile("mma.sync.aligned.m16n8k16.row.col.f32.bf16.bf16.f32 " \
        "{%0,%1,%2,%3}, {%4,%5,%6,%7}, {%8,%9}, {%0,%1,%2,%3};" \
        : "+f"((c)[0]), "+f"((c)[1]), "+f"((c)[2]), "+f"((c)[3]) \
        : "r"(a0), "r"(a1), "r"(a2), "r"(a3), "r"(b0), "r"(b1))

#define LDSM_X4(r0, r1, r2, r3, addr) \
    asm volatile("ldmatrix.sync.aligned.m8n8.x4.shared.b16 {%0,%1,%2,%3}, [%4];" \
        : "=r"(r0), "=r"(r1), "=r"(r2), "=r"(r3) : "r"(addr))

#define CP_ASYNC16(dst, src) \
    asm volatile("cp.async.cg.shared.global [%0], [%1], 16;" :: "r"(dst), "l"(src))
#define CP_COMMIT() asm volatile("cp.async.commit_group;")
#define CP_WAIT1()  asm volatile("cp.async.wait_group 1;")
#define CP_WAIT0()  asm volatile("cp.async.wait_group 0;")

// ---------------- device scratch ----------------
__device__ float g_c_pool[(size_t)POOLSZ * MM];
__device__ float g_h_pool[(size_t)POOLSZ * MM];
__device__ float g_HW[(size_t)POOLSZ * MM];         // h_pool @ W_fh + b_fh
__device__ float g_IOUF[(size_t)NNODE * 2048];      // [iou(1536) | fx(512)]
__device__ float g_biasbig[2048];
// bf16 split planes (hi/lo), produced once per value
__device__ __nv_bfloat16 g_WbThi[(size_t)2048 * 1024];
__device__ __nv_bfloat16 g_WbTlo[(size_t)2048 * 1024];
__device__ __nv_bfloat16 g_WfThi[(size_t)MM * MM];
__device__ __nv_bfloat16 g_WfTlo[(size_t)MM * MM];
__device__ __nv_bfloat16 g_wihhi[2][(size_t)G3M * MM];
__device__ __nv_bfloat16 g_wihlo[2][(size_t)G3M * MM];
__device__ __nv_bfloat16 g_XHhi[(size_t)NNODE * 1024];
__device__ __nv_bfloat16 g_XHlo[(size_t)NNODE * 1024];
__device__ __nv_bfloat16 g_Hhi[(size_t)POOLSZ * MM];
__device__ __nv_bfloat16 g_Hlo[(size_t)POOLSZ * MM];
__device__ __nv_bfloat16 g_xshi[(size_t)BB * SSEQ * MM];
__device__ __nv_bfloat16 g_xslo[(size_t)BB * SSEQ * MM];
// GRU
__device__ float g_xg[2][(size_t)BB * SSEQ * G3M];
__device__ float g_hg[2][(size_t)BB * G3M];
__device__ float g_hst[2][(size_t)BB * MM];

// ---------------- bf16x3 mma GEMM, cp.async fed: C = A(MxK) @ Bt(NxK)^T + bias ----------------
// A/B given as pre-split bf16 hi/lo planes (row-major, K contiguous).
#define RS 20              // b32 words per 32-bf16 row (16 data + 4 pad)
#define PLANE 2560         // words per plane (128 rows * RS)
#define STG_BYTES 40960    // 4 planes * PLANE * 4
#define MMA_SMEM_BYTES (2 * STG_BYTES)

__global__ void __launch_bounds__(256)
mma_gemm(const __nv_bfloat16* __restrict__ Ahi, const __nv_bfloat16* __restrict__ Alo,
         const __nv_bfloat16* __restrict__ Bhi, const __nv_bfloat16* __restrict__ Blo,
         const float* __restrict__ bias, float* __restrict__ C, int N_, int K) {
    extern __shared__ uint32_t sm[];
    const uint32_t smb = smem_u32(sm);

    const int tid = threadIdx.x;
    const int mbase = blockIdx.y * 128, nbase = blockIdx.x * 128;
    const int w = tid >> 5, lane = tid & 31;
    const int warpM = w & 1, warpN = w >> 1;      // 2x4 warps -> 64x32 warp tiles
    const int Kw = K >> 1;                        // b32 words per row
    const int nCh = Kw >> 4;                      // chunks of 16 words (32 bf16)

    const uint32_t* pA0 = (const uint32_t*)Ahi;
    const uint32_t* pA1 = (const uint32_t*)Alo;
    const uint32_t* pB0 = (const uint32_t*)Bhi;
    const uint32_t* pB1 = (const uint32_t*)Blo;

    float acc[4][4][4];
#pragma unroll
    for (int i = 0; i < 4; i++)
#pragma unroll
        for (int j = 0; j < 4; j++)
#pragma unroll
            for (int q = 0; q < 4; q++) acc[i][j][q] = 0.f;

    // ldmatrix per-lane base addresses
    const int lrow = lane & 15, lcol = lane >> 4;
    uint32_t aAddr[4], bAddr[2];
#pragma unroll
    for (int i = 0; i < 4; i++)
        aAddr[i] = smb + (uint32_t)(((warpM * 64 + i * 16 + lrow) * RS + lcol * 4) * 4);
#pragma unroll
    for (int jp = 0; jp < 2; jp++)
        bAddr[jp] = smb + (uint32_t)(2 * PLANE * 4 + ((warpN * 32 + jp * 16 + lrow) * RS + lcol * 4) * 4);

    // cp.async issue of one 128x32bf16 chunk for all 4 planes.
    // seg s = tid + (q&1)*256 (s<512): row r = s>>2, seg = s&3; plane = q>>1.
#define ISSUE(tw) do {                                                            \
    const int kw0 = (tw) * 16;                                                    \
    const uint32_t sb = smb + (uint32_t)(((tw) & 1) * STG_BYTES);                 \
    _Pragma("unroll")                                                             \
    for (int q = 0; q < 8; q++) {                                                 \
        const int pl = q >> 1;                                                    \
        int s = tid + (q & 1) * 256;                                              \
        int r = s >> 2, sg = s & 3;                                               \
        const uint32_t* src = (pl == 0 ? pA0 : pl == 1 ? pA1 : pl == 2 ? pB0 : pB1) \
            + (size_t)((pl < 2 ? mbase : nbase) + r) * Kw + kw0 + sg * 4;         \
        uint32_t dst = sb + (uint32_t)((pl * PLANE + r * RS + sg * 4) * 4);       \
        CP_ASYNC16(dst, src);                                                     \
    }                                                                             \
    CP_COMMIT(); } while (0)

    ISSUE(0);
    if (nCh > 1) ISSUE(1);

    for (int t = 0; t < nCh; t++) {
        if (t + 1 < nCh) CP_WAIT1(); else CP_WAIT0();
        __syncthreads();

        const uint32_t so = (uint32_t)((t & 1) * STG_BYTES);
#pragma unroll
        for (int ks = 0; ks < 2; ks++) {
            const uint32_t ko = so + ks * 32;     // ks*8 words = 32 bytes
            uint32_t Bh[4][2], Bl[4][2];
#pragma unroll
            for (int jp = 0; jp < 2; jp++) {
                LDSM_X4(Bh[2 * jp][0], Bh[2 * jp + 1][0], Bh[2 * jp][1], Bh[2 * jp + 1][1],
                        bAddr[jp] + ko);
                LDSM_X4(Bl[2 * jp][0], Bl[2 * jp + 1][0], Bl[2 * jp][1], Bl[2 * jp + 1][1],
                        bAddr[jp] + PLANE * 4 + ko);
            }
#pragma unroll
            for (int i = 0; i < 4; i++) {
                uint32_t Ah0, Ah1, Ah2, Ah3, Al0, Al1, Al2, Al3;
                LDSM_X4(Ah0, Ah1, Ah2, Ah3, aAddr[i] + ko);
                LDSM_X4(Al0, Al1, Al2, Al3, aAddr[i] + PLANE * 4 + ko);
#pragma unroll
                for (int j = 0; j < 4; j++) {
                    MMA_BF16(acc[i][j], Ah0, Ah1, Ah2, Ah3, Bh[j][0], Bh[j][1]);
                    MMA_BF16(acc[i][j], Ah0, Ah1, Ah2, Ah3, Bl[j][0], Bl[j][1]);
                    MMA_BF16(acc[i][j], Al0, Al1, Al2, Al3, Bh[j][0], Bh[j][1]);
                }
            }
        }
        if (t + 2 < nCh) {
            __syncthreads();            // all readers of buffer (t&1) done
            ISSUE(t + 2);
        }
    }

    // epilogue
    const int g = lane >> 2, tg = lane & 3;
#pragma unroll
    for (int i = 0; i < 4; i++) {
#pragma unroll
        for (int j = 0; j < 4; j++) {
            int row = mbase + warpM * 64 + i * 16 + g;
            int col = nbase + warpN * 32 + j * 8 + tg * 2;
            float b0v = bias[col], b1v = bias[col + 1];
            float2 v0 = make_float2(acc[i][j][0] + b0v, acc[i][j][1] + b1v);
            float2 v1 = make_float2(acc[i][j][2] + b0v, acc[i][j][3] + b1v);
            *(float2*)(C + (size_t)row * N_ + col)       = v0;
            *(float2*)(C + (size_t)(row + 8) * N_ + col) = v1;
        }
    }
}

// ---------------- prep kernels (split weights ONCE) ----------------
__global__ void prep_wbigT(const float* __restrict__ Wioux, const float* __restrict__ Wiouh,
                           const float* __restrict__ Wfx,
                           const float* __restrict__ bioux, const float* __restrict__ biouh,
                           const float* __restrict__ bfx) {
    int idx = blockIdx.x * blockDim.x + threadIdx.x;
    if (idx < 2048 * 512) {
        int n = idx >> 9, kw = idx & 511;
        int k0 = 2 * kw, k1 = 2 * kw + 1;
        float v0, v1;
        if (n < G3M) {
            v0 = (k0 < MM) ? Wioux[(size_t)k0 * G3M + n] : Wiouh[(size_t)(k0 - MM) * G3M + n];
            v1 = (k1 < MM) ? Wioux[(size_t)k1 * G3M + n] : Wiouh[(size_t)(k1 - MM) * G3M + n];
        } else {
            v0 = (k0 < MM) ? Wfx[(size_t)k0 * MM + (n - G3M)] : 0.0f;
            v1 = (k1 < MM) ? Wfx[(size_t)k1 * MM + (n - G3M)] : 0.0f;
        }
        uint32_t h, l; splitpack(v0, v1, h, l);
        ((uint32_t*)g_WbThi)[idx] = h;
        ((uint32_t*)g_WbTlo)[idx] = l;
    }
    if (idx < 2048)
        g_biasbig[idx] = (idx < G3M) ? (bioux[idx] + biouh[idx]) : bfx[idx - G3M];
}

__global__ void prep_small(const float* __restrict__ Wfh,
                           const float* __restrict__ wih_f, const float* __restrict__ wih_b) {
    int idx = blockIdx.x * blockDim.x + threadIdx.x;
    const int T1 = MM * (MM / 2);        // WfhT words
    const int T2 = G3M * (MM / 2);       // one wih words
    if (idx < T1) {
        int n = idx >> 8, kw = idx & 255;
        float v0 = Wfh[(size_t)(2 * kw) * MM + n];
        float v1 = Wfh[(size_t)(2 * kw + 1) * MM + n];
        uint32_t h, l; splitpack(v0, v1, h, l);
        ((uint32_t*)g_WfThi)[idx] = h;
        ((uint32_t*)g_WfTlo)[idx] = l;
    } else if (idx < T1 + 2 * T2) {
        int r = idx - T1;
        int dir = r / T2, j = r % T2;
        const float* wsrc = dir ? wih_b : wih_f;
        float v0 = wsrc[2 * j], v1 = wsrc[2 * j + 1];
        uint32_t h, l; splitpack(v0, v1, h, l);
        ((uint32_t*)g_wihhi[dir])[j] = h;
        ((uint32_t*)g_wihlo[dir])[j] = l;
    }
}

// ---------------- init ----------------
__global__ void init_leaf(const float* __restrict__ embed, const int* __restrict__ leaf_idx) {
    int idx = blockIdx.x * blockDim.x + threadIdx.x;
    if (idx >= NLEAF * (MM / 4)) return;
    int n = idx >> 7, m = (idx & 127) * 4;
    int w = leaf_idx[n];
    float4 v = *(const float4*)(embed + (size_t)w * MM + m);
    *(float4*)(g_h_pool + (size_t)(1 + n) * MM + m) = v;
    *(float4*)(g_c_pool + (size_t)(1 + n) * MM + m) = make_float4(0.f, 0.f, 0.f, 0.f);
    uint32_t h0, l0, h1, l1;
    splitpack(v.x, v.y, h0, l0);
    splitpack(v.z, v.w, h1, l1);
    size_t wrd = ((size_t)(1 + n) * MM + m) >> 1;
    ((uint32_t*)g_Hhi)[wrd] = h0; ((uint32_t*)g_Hhi)[wrd + 1] = h1;
    ((uint32_t*)g_Hlo)[wrd] = l0; ((uint32_t*)g_Hlo)[wrd + 1] = l1;
}

__global__ void init_misc(float* __restrict__ out, const float* __restrict__ bfh) {
    int idx = blockIdx.x * blockDim.x + threadIdx.x;
    if (idx < MM) {
        g_h_pool[idx] = 0.f; g_c_pool[idx] = 0.f;
        g_HW[idx] = bfh[idx];       // HW of zero slot
    }
    if (idx < 2 * BB * MM) (&g_hst[0][0])[idx] = 0.f;
    if (idx < BB * SSEQ * MM) out[idx] = 0.f;
}

// ---------------- per-level gather: write split XH planes ----------------
__global__ void gather_level(const float* __restrict__ embed, const int* __restrict__ lwi,
                             const int* __restrict__ child, int d) {
    int idx = blockIdx.x * blockDim.x + threadIdx.x;
    if (idx >= NNODE * (MM / 4)) return;
    int n = idx >> 7, m = (idx & 127) * 4;
    int w = lwi[d * NNODE + n];
    float4 x = *(const float4*)(embed + (size_t)w * MM + m);
    uint32_t h0, l0, h1, l1;
    splitpack(x.x, x.y, h0, l0);
    splitpack(x.z, x.w, h1, l1);
    size_t wrd = ((size_t)n * 1024 + m) >> 1;
    ((uint32_t*)g_XHhi)[wrd] = h0; ((uint32_t*)g_XHhi)[wrd + 1] = h1;
    ((uint32_t*)g_XHlo)[wrd] = l0; ((uint32_t*)g_XHlo)[wrd + 1] = l1;
    float4 s = make_float4(0.f, 0.f, 0.f, 0.f);
    const int* ch = child + ((size_t)d * NNODE + n) * KCH;
#pragma unroll
    for (int k = 0; k < KCH; k++) {
        int ci = ch[k];
        float4 hv = *(const float4*)(g_h_pool + (size_t)ci * MM + m);
        s.x += hv.x; s.y += hv.y; s.z += hv.z; s.w += hv.w;
    }
    splitpack(s.x, s.y, h0, l0);
    splitpack(s.z, s.w, h1, l1);
    wrd = ((size_t)n * 1024 + MM + m) >> 1;
    ((uint32_t*)g_XHhi)[wrd] = h0; ((uint32_t*)g_XHhi)[wrd + 1] = h1;
    ((uint32_t*)g_XHlo)[wrd] = l0; ((uint32_t*)g_XHlo)[wrd + 1] = l1;
}

// ---------------- level pointwise: emit fp32 h/c + split h planes ----------------
__global__ void level_point(const int* __restrict__ child, int d) {
    int idx = blockIdx.x * blockDim.x + threadIdx.x;
    if (idx >= NNODE * (MM / 2)) return;
    int n = idx >> 8, j = idx & 255;
    int m = 2 * j;
    const float* row = g_IOUF + (size_t)n * 2048;
    float2 iv = *(const float2*)(row + m);
    float2 ov = *(const float2*)(row + MM + m);
    float2 uv = *(const float2*)(row + 2 * MM + m);
    float2 fx = *(const float2*)(row + 3 * MM + m);
    float c0 = sigf(iv.x) * tanhf(uv.x);
    float c1 = sigf(iv.y) * tanhf(uv.y);
    const int* ch = child + ((size_t)d * NNODE + n) * KCH;
#pragma unroll
    for (int k = 0; k < KCH; k++) {
        int ci = ch[k];
        float2 hw = *(const float2*)(g_HW + (size_t)ci * MM + m);
        float2 cc = *(const float2*)(g_c_pool + (size_t)ci * MM + m);
        c0 += sigf(fx.x + hw.x) * cc.x;
        c1 += sigf(fx.y + hw.y) * cc.y;
    }
    float h0 = sigf(ov.x) * tanhf(c0);
    float h1 = sigf(ov.y) * tanhf(c1);
    size_t slot = (size_t)(OFFS + d * NNODE + n) * MM + m;
    *(float2*)(g_c_pool + slot) = make_float2(c0, c1);
    *(float2*)(g_h_pool + slot) = make_float2(h0, h1);
    uint32_t sh, sl; splitpack(h0, h1, sh, sl);
    ((uint32_t*)g_Hhi)[slot >> 1] = sh;
    ((uint32_t*)g_Hlo)[slot >> 1] = sl;
}

// ---------------- GRU ----------------
__global__ void gather_xs(const int* __restrict__ ctx) {
    int idx = blockIdx.x * blockDim.x + threadIdx.x;
    if (idx >= BB * SSEQ * (MM / 4)) return;
    int rowI = idx >> 7, m = (idx & 127) * 4;
    int p = ctx[rowI];
    float4 v = *(const float4*)(g_h_pool + (size_t)p * MM + m);
    uint32_t h0, l0, h1, l1;
    splitpack(v.x, v.y, h0, l0);
    splitpack(v.z, v.w, h1, l1);
    size_t wrd = ((size_t)rowI * MM + m) >> 1;
    ((uint32_t*)g_xshi)[wrd] = h0; ((uint32_t*)g_xshi)[wrd + 1] = h1;
    ((uint32_t*)g_xslo)[wrd] = l0; ((uint32_t*)g_xslo)[wrd + 1] = l1;
}

__global__ void __launch_bounds__(256) gru_gemm(const float* __restrict__ whh_f,
                                                const float* __restrict__ whh_b,
                                                const float* __restrict__ bhh_f,
                                                const float* __restrict__ bhh_b) {
    extern __shared__ float sh[];
    float* Hs = sh;                 // 64 x 513
    float* Ws = sh + 64 * 513;      // 32 x 513
    int dir = blockIdx.y;
    const float* whh = dir ? whh_b : whh_f;
    const float* bhh = dir ? bhh_b : bhh_f;
    const float* H = g_hst[dir];
    int n0 = blockIdx.x * 32;
    int tid = threadIdx.x;

    for (int i = tid; i < 64 * 512; i += 256) Hs[(i >> 9) * 513 + (i & 511)] = H[i];
    for (int i = tid; i < 32 * 512; i += 256) {
        int rr = i >> 9, kk = i & 511;
        Ws[rr * 513 + kk] = whh[(size_t)(n0 + rr) * MM + kk];
    }
    __syncthreads();

    int cg = tid & 7, r = tid >> 3;
    int row0 = 2 * r, row1 = 2 * r + 1;
    float acc0[4] = {0.f, 0.f, 0.f, 0.f};
    float acc1[4] = {0.f, 0.f, 0.f, 0.f};
    for (int k = 0; k < 512; k++) {
        float h0 = Hs[row0 * 513 + k];
        float h1 = Hs[row1 * 513 + k];
#pragma unroll
        for (int c = 0; c < 4; c++) {
            float w = Ws[(cg * 4 + c) * 513 + k];
            acc0[c] += h0 * w;
            acc1[c] += h1 * w;
        }
    }
#pragma unroll
    for (int c = 0; c < 4; c++) {
        int n = n0 + cg * 4 + c;
        float bv = bhh[n];
        g_hg[dir][(size_t)row0 * G3M + n] = acc0[c] + bv;
        g_hg[dir][(size_t)row1 * G3M + n] = acc1[c] + bv;
    }
}

__global__ void gru_point(float* __restrict__ out, int t) {
    int idx = blockIdx.x * blockDim.x + threadIdx.x;
    if (idx >= 2 * BB * MM) return;
    int dir = idx >> 15;
    int rem = idx & 32767;
    int b = rem >> 9, j = rem & 511;
    int pos = dir ? (SSEQ - 1 - t) : t;
    const float* xrow = g_xg[dir] + (size_t)(b * SSEQ + pos) * G3M;
    const float* hrow = g_hg[dir] + (size_t)b * G3M;
    float r = sigf(xrow[j] + hrow[j]);
    float z = sigf(xrow[MM + j] + hrow[MM + j]);
    float nn = tanhf(xrow[2 * MM + j] + r * hrow[2 * MM + j]);
    float hp = g_hst[dir][b * MM + j];
    float hn = (1.f - z) * nn + z * hp;
    g_hst[dir][b * MM + j] = hn;
    out[(size_t)(b * SSEQ + pos) * MM + j] += hn;
}

// ---------------- host launch ----------------
extern "C" void kernel_launch(void* const* d_in, const int* in_sizes, int n_in,
                              void* d_out, int out_size) {
    const float* embed   = (const float*)d_in[0];
    const float* Wioux   = (const float*)d_in[1];
    const float* bioux   = (const float*)d_in[2];
    const float* Wiouh   = (const float*)d_in[3];
    const float* biouh   = (const float*)d_in[4];
    const float* Wfx     = (const float*)d_in[5];
    const float* bfx     = (const float*)d_in[6];
    const float* Wfh     = (const float*)d_in[7];
    const float* bfh     = (const float*)d_in[8];
    const float* wih_f   = (const float*)d_in[9];
    const float* whh_f   = (const float*)d_in[10];
    const float* bih_f   = (const float*)d_in[11];
    const float* bhh_f   = (const float*)d_in[12];
    const float* wih_b   = (const float*)d_in[13];
    const float* whh_b   = (const float*)d_in[14];
    const float* bih_b   = (const float*)d_in[15];
    const float* bhh_b   = (const float*)d_in[16];

    const int* leaf_idx = nullptr; const int* level_idx = nullptr;
    const int* child = nullptr; const int* ctx = nullptr;
    for (int i = 17; i < n_in; i++) {
        int sz = in_sizes[i];
        if (sz == NLEAF)                 leaf_idx  = (const int*)d_in[i];
        else if (sz == DD * NNODE)       level_idx = (const int*)d_in[i];
        else if (sz == DD * NNODE * KCH) child     = (const int*)d_in[i];
        else if (sz == BB * SSEQ)        ctx       = (const int*)d_in[i];
    }

    float* out = (float*)d_out;

    cudaFuncSetAttribute(mma_gemm, cudaFuncAttributeMaxDynamicSharedMemorySize, MMA_SMEM_BYTES);
    cudaFuncSetAttribute(gru_gemm, cudaFuncAttributeMaxDynamicSharedMemorySize,
                         (64 + 32) * 513 * sizeof(float));

    __nv_bfloat16* d_Hhi;   cudaGetSymbolAddress((void**)&d_Hhi, g_Hhi);
    __nv_bfloat16* d_Hlo;   cudaGetSymbolAddress((void**)&d_Hlo, g_Hlo);
    __nv_bfloat16* d_XHhi;  cudaGetSymbolAddress((void**)&d_XHhi, g_XHhi);
    __nv_bfloat16* d_XHlo;  cudaGetSymbolAddress((void**)&d_XHlo, g_XHlo);
    __nv_bfloat16* d_WbThi; cudaGetSymbolAddress((void**)&d_WbThi, g_WbThi);
    __nv_bfloat16* d_WbTlo; cudaGetSymbolAddress((void**)&d_WbTlo, g_WbTlo);
    __nv_bfloat16* d_WfThi; cudaGetSymbolAddress((void**)&d_WfThi, g_WfThi);
    __nv_bfloat16* d_WfTlo; cudaGetSymbolAddress((void**)&d_WfTlo, g_WfTlo);
    __nv_bfloat16* d_wihhi; cudaGetSymbolAddress((void**)&d_wihhi, g_wihhi);
    __nv_bfloat16* d_wihlo; cudaGetSymbolAddress((void**)&d_wihlo, g_wihlo);
    __nv_bfloat16* d_xshi;  cudaGetSymbolAddress((void**)&d_xshi, g_xshi);
    __nv_bfloat16* d_xslo;  cudaGetSymbolAddress((void**)&d_xslo, g_xslo);
    float* d_IOUF;  cudaGetSymbolAddress((void**)&d_IOUF, g_IOUF);
    float* d_HW;    cudaGetSymbolAddress((void**)&d_HW, g_HW);
    float* d_bb;    cudaGetSymbolAddress((void**)&d_bb, g_biasbig);
    float* d_xg;    cudaGetSymbolAddress((void**)&d_xg, g_xg);

    // prep + init
    prep_wbigT<<<(2048 * 512 + 255) / 256, 256>>>(Wioux, Wiouh, Wfx, bioux, biouh, bfx);
    prep_small<<<(MM * (MM / 2) + 2 * G3M * (MM / 2) + 255) / 256, 256>>>(Wfh, wih_f, wih_b);
    init_leaf<<<(NLEAF * (MM / 4) + 255) / 256, 256>>>(embed, leaf_idx);
    init_misc<<<(BB * SSEQ * MM + 255) / 256, 256>>>(out, bfh);

    // leaf HW: HW[1..NLEAF] = h[1..NLEAF] @ WfhT^T + bfh
    {
        dim3 grid(512 / 128, NLEAF / 128);
        mma_gemm<<<grid, 256, MMA_SMEM_BYTES>>>(d_Hhi + MM, d_Hlo + MM, d_WfThi, d_WfTlo,
                                                bfh, d_HW + MM, 512, 512);
    }

    // tree levels
    for (int d = 0; d < DD; d++) {
        gather_level<<<(NNODE * (MM / 4) + 255) / 256, 256>>>(embed, level_idx, child, d);
        {   // IOUF(4096x2048) = XH(4096x1024) @ WbigT^T
            dim3 grid(2048 / 128, 4096 / 128);
            mma_gemm<<<grid, 256, MMA_SMEM_BYTES>>>(d_XHhi, d_XHlo, d_WbThi, d_WbTlo,
                                                    d_bb, d_IOUF, 2048, 1024);
        }
        level_point<<<(NNODE * (MM / 2) + 255) / 256, 256>>>(child, d);
        if (d < DD - 1) {   // HW for the new 4096 nodes
            dim3 grid(512 / 128, NNODE / 128);
            size_t off = (size_t)(OFFS + d * NNODE) * MM;
            mma_gemm<<<grid, 256, MMA_SMEM_BYTES>>>(d_Hhi + off, d_Hlo + off, d_WfThi, d_WfTlo,
                                                    bfh, d_HW + off, 512, 512);
        }
    }

    // GRU input gates: xg[dir](1024x1536) = xs(1024x512) @ wih^T
    gather_xs<<<(BB * SSEQ * (MM / 4) + 255) / 256, 256>>>(ctx);
    {
        dim3 grid(G3M / 128, (BB * SSEQ) / 128);
        mma_gemm<<<grid, 256, MMA_SMEM_BYTES>>>(d_xshi, d_xslo, d_wihhi, d_wihlo,
                                                bih_f, d_xg, G3M, 512);
        mma_gemm<<<grid, 256, MMA_SMEM_BYTES>>>(d_xshi, d_xslo,
                                                d_wihhi + (size_t)G3M * MM, d_wihlo + (size_t)G3M * MM,
                                                bih_b, d_xg + (size_t)BB * SSEQ * G3M, G3M, 512);
    }

    // GRU recurrence
    size_t smem = (64 + 32) * 513 * sizeof(float);
    for (int t = 0; t < SSEQ; t++) {
        dim3 grid(G3M / 32, 2);
        gru_gemm<<<grid, 256, smem>>>(whh_f, whh_b, bhh_f, bhh_b);
        gru_point<<<(2 * BB * MM + 255) / 256, 256>>>(out, t);
    }
}

// round 8
// speedup vs baseline: 2.6400x; 1.0867x over previous
#include <cuda_runtime.h>
#include <cuda_bf16.h>
#include <math.h>
#include <cstdint>

// ---------------- problem constants ----------------
#define VV     32000
#define MM     512
#define NLEAF  16384
#define DD     8
#define NNODE  4096
#define KCH    4
#define BB     64
#define SSEQ   16
#define POOLSZ (1 + NLEAF + DD * NNODE)   // 49153
#define OFFS   (1 + NLEAF)                // 16385
#define G3M    (3 * MM)                   // 1536
#define NALL   (DD * NNODE)               // 32768

__device__ __forceinline__ float sigf(float x) { return 1.0f / (1.0f + expf(-x)); }

__device__ __forceinline__ uint32_t smem_u32(const void* p) {
    uint32_t a;
    asm("{ .reg .u64 t; cvta.to.shared.u64 t, %1; cvt.u32.u64 %0, t; }" : "=r"(a) : "l"(p));
    return a;
}

// split (x,y) into packed bf16x2 hi + bf16x2 lo (lower 16 bits = x)
__device__ __forceinline__ void splitpack(float x, float y, uint32_t& hi, uint32_t& lo) {
    uint32_t h;
    asm("cvt.rn.bf16x2.f32 %0, %1, %2;" : "=r"(h) : "f"(y), "f"(x));
    float hx = __uint_as_float(h << 16);
    float hy = __uint_as_float(h & 0xFFFF0000u);
    float rx = x - hx, ry = y - hy;
    asm("cvt.rn.bf16x2.f32 %0, %1, %2;" : "=r"(lo) : "f"(ry), "f"(rx));
    hi = h;
}

#define MMA_BF16(c, a0, a1, a2, a3, b0, b1) \
    asm volatile("mma.sync.aligned.m16n8k16.row.col.f32.bf16.bf16.f32 " \
        "{%0,%1,%2,%3}, {%4,%5,%6,%7}, {%8,%9}, {%0,%1,%2,%3};" \
        : "+f"((c)[0]), "+f"((c)[1]), "+f"((c)[2]), "+f"((c)[3]) \
        : "r"(a0), "r"(a1), "r"(a2), "r"(a3), "r"(b0), "r"(b1))

#define LDSM_X4(r0, r1, r2, r3, addr) \
    asm volatile("ldmatrix.sync.aligned.m8n8.x4.shared.b16 {%0,%1,%2,%3}, [%4];" \
        : "=r"(r0), "=r"(r1), "=r"(r2), "=r"(r3) : "r"(addr))

#define CP_ASYNC16(dst, src) \
    asm volatile("cp.async.cg.shared.global [%0], [%1], 16;" :: "r"(dst), "l"(src))
#define CP_COMMIT() asm volatile("cp.async.commit_group;")
#define CP_WAIT1()  asm volatile("cp.async.wait_group 1;")
#define CP_WAIT0()  asm volatile("cp.async.wait_group 0;")

// ---------------- device scratch ----------------
__device__ float g_c_pool[(size_t)POOLSZ * MM];
__device__ float g_h_pool[(size_t)POOLSZ * MM];
__device__ float g_HW[(size_t)POOLSZ * MM];
__device__ float g_IOUFall[(size_t)NALL * 2048];    // [iou(1536)|fx(512)] per node, all levels
__device__ float g_biasbig[2048];
__device__ unsigned g_bar;
// bf16 split planes
__device__ __nv_bfloat16 g_W1hi[(size_t)2048 * MM];   // [Wioux|Wfx]^T
__device__ __nv_bfloat16 g_W1lo[(size_t)2048 * MM];
__device__ __nv_bfloat16 g_W2hi[(size_t)G3M * MM];    // Wiouh^T
__device__ __nv_bfloat16 g_W2lo[(size_t)G3M * MM];
__device__ __nv_bfloat16 g_WfThi[(size_t)MM * MM];
__device__ __nv_bfloat16 g_WfTlo[(size_t)MM * MM];
__device__ __nv_bfloat16 g_wihhi[2][(size_t)G3M * MM];
__device__ __nv_bfloat16 g_wihlo[2][(size_t)G3M * MM];
__device__ __nv_bfloat16 g_Xallhi[(size_t)NALL * MM];
__device__ __nv_bfloat16 g_Xalllo[(size_t)NALL * MM];
__device__ __nv_bfloat16 g_SUMHhi[(size_t)NNODE * MM];
__device__ __nv_bfloat16 g_SUMHlo[(size_t)NNODE * MM];
__device__ __nv_bfloat16 g_Hhi[(size_t)POOLSZ * MM];
__device__ __nv_bfloat16 g_Hlo[(size_t)POOLSZ * MM];
__device__ __nv_bfloat16 g_xshi[(size_t)BB * SSEQ * MM];
__device__ __nv_bfloat16 g_xslo[(size_t)BB * SSEQ * MM];
// GRU
__device__ float g_xg[2][(size_t)BB * SSEQ * G3M];
__device__ float g_hg[2][(size_t)BB * G3M];
__device__ float g_hst[2][(size_t)BB * MM];

// ---------------- bf16x3 mma GEMM, cp.async fed ----------------
// C[128*by.., 128*bx..] = A(MxK) @ Bt(NxK)^T (+bias | +=C). ldC explicit.
#define RS 20
#define PLANE 2560
#define STG_BYTES 40960
#define MMA_SMEM_BYTES (2 * STG_BYTES)

__global__ void __launch_bounds__(256)
mma_gemm(const __nv_bfloat16* __restrict__ Ahi, const __nv_bfloat16* __restrict__ Alo,
         const __nv_bfloat16* __restrict__ Bhi, const __nv_bfloat16* __restrict__ Blo,
         const float* __restrict__ bias, float* __restrict__ C, int ldC, int K, int accum) {
    extern __shared__ uint32_t sm[];
    const uint32_t smb = smem_u32(sm);

    const int tid = threadIdx.x;
    const int mbase = blockIdx.y * 128, nbase = blockIdx.x * 128;
    const int w = tid >> 5, lane = tid & 31;
    const int warpM = w & 1, warpN = w >> 1;
    const int Kw = K >> 1;
    const int nCh = Kw >> 4;

    const uint32_t* pA0 = (const uint32_t*)Ahi;
    const uint32_t* pA1 = (const uint32_t*)Alo;
    const uint32_t* pB0 = (const uint32_t*)Bhi;
    const uint32_t* pB1 = (const uint32_t*)Blo;

    float acc[4][4][4];
#pragma unroll
    for (int i = 0; i < 4; i++)
#pragma unroll
        for (int j = 0; j < 4; j++)
#pragma unroll
            for (int q = 0; q < 4; q++) acc[i][j][q] = 0.f;

    const int lrow = lane & 15, lcol = lane >> 4;
    uint32_t aAddr[4], bAddr[2];
#pragma unroll
    for (int i = 0; i < 4; i++)
        aAddr[i] = smb + (uint32_t)(((warpM * 64 + i * 16 + lrow) * RS + lcol * 4) * 4);
#pragma unroll
    for (int jp = 0; jp < 2; jp++)
        bAddr[jp] = smb + (uint32_t)(2 * PLANE * 4 + ((warpN * 32 + jp * 16 + lrow) * RS + lcol * 4) * 4);

#define ISSUE(tw) do {                                                            \
    const int kw0 = (tw) * 16;                                                    \
    const uint32_t sb = smb + (uint32_t)(((tw) & 1) * STG_BYTES);                 \
    _Pragma("unroll")                                                             \
    for (int q = 0; q < 8; q++) {                                                 \
        const int pl = q >> 1;                                                    \
        int s = tid + (q & 1) * 256;                                              \
        int r = s >> 2, sg = s & 3;                                               \
        const uint32_t* src = (pl == 0 ? pA0 : pl == 1 ? pA1 : pl == 2 ? pB0 : pB1) \
            + (size_t)((pl < 2 ? mbase : nbase) + r) * Kw + kw0 + sg * 4;         \
        uint32_t dst = sb + (uint32_t)((pl * PLANE + r * RS + sg * 4) * 4);       \
        CP_ASYNC16(dst, src);                                                     \
    }                                                                             \
    CP_COMMIT(); } while (0)

    ISSUE(0);
    if (nCh > 1) ISSUE(1);

    for (int t = 0; t < nCh; t++) {
        if (t + 1 < nCh) CP_WAIT1(); else CP_WAIT0();
        __syncthreads();

        const uint32_t so = (uint32_t)((t & 1) * STG_BYTES);
#pragma unroll
        for (int ks = 0; ks < 2; ks++) {
            const uint32_t ko = so + ks * 32;
            uint32_t Bh[4][2], Bl[4][2];
#pragma unroll
            for (int jp = 0; jp < 2; jp++) {
                LDSM_X4(Bh[2 * jp][0], Bh[2 * jp + 1][0], Bh[2 * jp][1], Bh[2 * jp + 1][1],
                        bAddr[jp] + ko);
                LDSM_X4(Bl[2 * jp][0], Bl[2 * jp + 1][0], Bl[2 * jp][1], Bl[2 * jp + 1][1],
                        bAddr[jp] + PLANE * 4 + ko);
            }
#pragma unroll
            for (int i = 0; i < 4; i++) {
                uint32_t Ah0, Ah1, Ah2, Ah3, Al0, Al1, Al2, Al3;
                LDSM_X4(Ah0, Ah1, Ah2, Ah3, aAddr[i] + ko);
                LDSM_X4(Al0, Al1, Al2, Al3, aAddr[i] + PLANE * 4 + ko);
#pragma unroll
                for (int j = 0; j < 4; j++) {
                    MMA_BF16(acc[i][j], Ah0, Ah1, Ah2, Ah3, Bh[j][0], Bh[j][1]);
                    MMA_BF16(acc[i][j], Ah0, Ah1, Ah2, Ah3, Bl[j][0], Bl[j][1]);
                    MMA_BF16(acc[i][j], Al0, Al1, Al2, Al3, Bh[j][0], Bh[j][1]);
                }
            }
        }
        if (t + 2 < nCh) {
            __syncthreads();
            ISSUE(t + 2);
        }
    }

    const int g = lane >> 2, tg = lane & 3;
#pragma unroll
    for (int i = 0; i < 4; i++) {
#pragma unroll
        for (int j = 0; j < 4; j++) {
            int row = mbase + warpM * 64 + i * 16 + g;
            int col = nbase + warpN * 32 + j * 8 + tg * 2;
            float* c0p = C + (size_t)row * ldC + col;
            float* c1p = C + (size_t)(row + 8) * ldC + col;
            float a0 = acc[i][j][0], a1 = acc[i][j][1];
            float a2 = acc[i][j][2], a3 = acc[i][j][3];
            if (accum) {
                float2 e0 = *(float2*)c0p, e1 = *(float2*)c1p;
                a0 += e0.x; a1 += e0.y; a2 += e1.x; a3 += e1.y;
            } else {
                float b0v = bias[col], b1v = bias[col + 1];
                a0 += b0v; a1 += b1v; a2 += b0v; a3 += b1v;
            }
            *(float2*)c0p = make_float2(a0, a1);
            *(float2*)c1p = make_float2(a2, a3);
        }
    }
}

// ---------------- prep kernels ----------------
__global__ void prep_w1(const float* __restrict__ Wioux, const float* __restrict__ Wfx,
                        const float* __restrict__ bioux, const float* __restrict__ biouh,
                        const float* __restrict__ bfx) {
    int idx = blockIdx.x * blockDim.x + threadIdx.x;
    if (idx < 2048 * 256) {
        int n = idx >> 8, kw = idx & 255;
        int k0 = 2 * kw, k1 = k0 + 1;
        float v0, v1;
        if (n < G3M) { v0 = Wioux[(size_t)k0 * G3M + n]; v1 = Wioux[(size_t)k1 * G3M + n]; }
        else         { v0 = Wfx[(size_t)k0 * MM + (n - G3M)]; v1 = Wfx[(size_t)k1 * MM + (n - G3M)]; }
        uint32_t h, l; splitpack(v0, v1, h, l);
        ((uint32_t*)g_W1hi)[idx] = h;
        ((uint32_t*)g_W1lo)[idx] = l;
    }
    if (idx < 2048)
        g_biasbig[idx] = (idx < G3M) ? (bioux[idx] + biouh[idx]) : bfx[idx - G3M];
}

__global__ void prep_w2(const float* __restrict__ Wiouh) {
    int idx = blockIdx.x * blockDim.x + threadIdx.x;
    if (idx >= G3M * 256) return;
    int n = idx >> 8, kw = idx & 255;
    float v0 = Wiouh[(size_t)(2 * kw) * G3M + n];
    float v1 = Wiouh[(size_t)(2 * kw + 1) * G3M + n];
    uint32_t h, l; splitpack(v0, v1, h, l);
    ((uint32_t*)g_W2hi)[idx] = h;
    ((uint32_t*)g_W2lo)[idx] = l;
}

__global__ void prep_small(const float* __restrict__ Wfh,
                           const float* __restrict__ wih_f, const float* __restrict__ wih_b) {
    int idx = blockIdx.x * blockDim.x + threadIdx.x;
    const int T1 = MM * (MM / 2);
    const int T2 = G3M * (MM / 2);
    if (idx < T1) {
        int n = idx >> 8, kw = idx & 255;
        float v0 = Wfh[(size_t)(2 * kw) * MM + n];
        float v1 = Wfh[(size_t)(2 * kw + 1) * MM + n];
        uint32_t h, l; splitpack(v0, v1, h, l);
        ((uint32_t*)g_WfThi)[idx] = h;
        ((uint32_t*)g_WfTlo)[idx] = l;
    } else if (idx < T1 + 2 * T2) {
        int r = idx - T1;
        int dir = r / T2, j = r % T2;
        const float* wsrc = dir ? wih_b : wih_f;
        float v0 = wsrc[2 * j], v1 = wsrc[2 * j + 1];
        uint32_t h, l; splitpack(v0, v1, h, l);
        ((uint32_t*)g_wihhi[dir])[j] = h;
        ((uint32_t*)g_wihlo[dir])[j] = l;
    }
}

// ---------------- init ----------------
__global__ void init_leaf(const float* __restrict__ embed, const int* __restrict__ leaf_idx) {
    int idx = blockIdx.x * blockDim.x + threadIdx.x;
    if (idx >= NLEAF * (MM / 4)) return;
    int n = idx >> 7, m = (idx & 127) * 4;
    int w = leaf_idx[n];
    float4 v = *(const float4*)(embed + (size_t)w * MM + m);
    *(float4*)(g_h_pool + (size_t)(1 + n) * MM + m) = v;
    *(float4*)(g_c_pool + (size_t)(1 + n) * MM + m) = make_float4(0.f, 0.f, 0.f, 0.f);
    uint32_t h0, l0, h1, l1;
    splitpack(v.x, v.y, h0, l0);
    splitpack(v.z, v.w, h1, l1);
    size_t wrd = ((size_t)(1 + n) * MM + m) >> 1;
    ((uint32_t*)g_Hhi)[wrd] = h0; ((uint32_t*)g_Hhi)[wrd + 1] = h1;
    ((uint32_t*)g_Hlo)[wrd] = l0; ((uint32_t*)g_Hlo)[wrd + 1] = l1;
}

__global__ void init_misc(float* __restrict__ out, const float* __restrict__ bfh) {
    int idx = blockIdx.x * blockDim.x + threadIdx.x;
    if (idx == 0) g_bar = 0u;
    if (idx < MM) {
        g_h_pool[idx] = 0.f; g_c_pool[idx] = 0.f;
        g_HW[idx] = bfh[idx];
    }
    if (idx < 2 * BB * MM) (&g_hst[0][0])[idx] = 0.f;
    if (idx < BB * SSEQ * MM) out[idx] = 0.f;
}

// ---------------- gather x embeddings for ALL levels ----------------
__global__ void gather_x_all(const float* __restrict__ embed, const int* __restrict__ lwi) {
    int idx = blockIdx.x * blockDim.x + threadIdx.x;
    if (idx >= NALL * (MM / 4)) return;
    int ng = idx >> 7, m = (idx & 127) * 4;
    int w = lwi[ng];
    float4 x = *(const float4*)(embed + (size_t)w * MM + m);
    uint32_t h0, l0, h1, l1;
    splitpack(x.x, x.y, h0, l0);
    splitpack(x.z, x.w, h1, l1);
    size_t wrd = ((size_t)ng * MM + m) >> 1;
    ((uint32_t*)g_Xallhi)[wrd] = h0; ((uint32_t*)g_Xallhi)[wrd + 1] = h1;
    ((uint32_t*)g_Xalllo)[wrd] = l0; ((uint32_t*)g_Xalllo)[wrd + 1] = l1;
}

// ---------------- per-level gather: sum of child h ----------------
__global__ void gather_level(const int* __restrict__ child, int d) {
    int idx = blockIdx.x * blockDim.x + threadIdx.x;
    if (idx >= NNODE * (MM / 4)) return;
    int n = idx >> 7, m = (idx & 127) * 4;
    float4 s = make_float4(0.f, 0.f, 0.f, 0.f);
    const int* ch = child + ((size_t)d * NNODE + n) * KCH;
#pragma unroll
    for (int k = 0; k < KCH; k++) {
        int ci = ch[k];
        float4 hv = *(const float4*)(g_h_pool + (size_t)ci * MM + m);
        s.x += hv.x; s.y += hv.y; s.z += hv.z; s.w += hv.w;
    }
    uint32_t h0, l0, h1, l1;
    splitpack(s.x, s.y, h0, l0);
    splitpack(s.z, s.w, h1, l1);
    size_t wrd = ((size_t)n * MM + m) >> 1;
    ((uint32_t*)g_SUMHhi)[wrd] = h0; ((uint32_t*)g_SUMHhi)[wrd + 1] = h1;
    ((uint32_t*)g_SUMHlo)[wrd] = l0; ((uint32_t*)g_SUMHlo)[wrd + 1] = l1;
}

// ---------------- level pointwise ----------------
__global__ void level_point(const int* __restrict__ child, int d) {
    int idx = blockIdx.x * blockDim.x + threadIdx.x;
    if (idx >= NNODE * (MM / 2)) return;
    int n = idx >> 8, j = idx & 255;
    int m = 2 * j;
    const float* row = g_IOUFall + (size_t)(d * NNODE + n) * 2048;
    float2 iv = *(const float2*)(row + m);
    float2 ov = *(const float2*)(row + MM + m);
    float2 uv = *(const float2*)(row + 2 * MM + m);
    float2 fx = *(const float2*)(row + 3 * MM + m);
    float c0 = sigf(iv.x) * tanhf(uv.x);
    float c1 = sigf(iv.y) * tanhf(uv.y);
    const int* ch = child + ((size_t)d * NNODE + n) * KCH;
#pragma unroll
    for (int k = 0; k < KCH; k++) {
        int ci = ch[k];
        float2 hw = *(const float2*)(g_HW + (size_t)ci * MM + m);
        float2 cc = *(const float2*)(g_c_pool + (size_t)ci * MM + m);
        c0 += sigf(fx.x + hw.x) * cc.x;
        c1 += sigf(fx.y + hw.y) * cc.y;
    }
    float h0 = sigf(ov.x) * tanhf(c0);
    float h1 = sigf(ov.y) * tanhf(c1);
    size_t slot = (size_t)(OFFS + d * NNODE + n) * MM + m;
    *(float2*)(g_c_pool + slot) = make_float2(c0, c1);
    *(float2*)(g_h_pool + slot) = make_float2(h0, h1);
    uint32_t sh, sl; splitpack(h0, h1, sh, sl);
    ((uint32_t*)g_Hhi)[slot >> 1] = sh;
    ((uint32_t*)g_Hlo)[slot >> 1] = sl;
}

// ---------------- GRU ----------------
__global__ void gather_xs(const int* __restrict__ ctx) {
    int idx = blockIdx.x * blockDim.x + threadIdx.x;
    if (idx >= BB * SSEQ * (MM / 4)) return;
    int rowI = idx >> 7, m = (idx & 127) * 4;
    int p = ctx[rowI];
    float4 v = *(const float4*)(g_h_pool + (size_t)p * MM + m);
    uint32_t h0, l0, h1, l1;
    splitpack(v.x, v.y, h0, l0);
    splitpack(v.z, v.w, h1, l1);
    size_t wrd = ((size_t)rowI * MM + m) >> 1;
    ((uint32_t*)g_xshi)[wrd] = h0; ((uint32_t*)g_xshi)[wrd + 1] = h1;
    ((uint32_t*)g_xslo)[wrd] = l0; ((uint32_t*)g_xslo)[wrd + 1] = l1;
}

// persistent GRU: grid (48,2) = 96 blocks, all co-resident (1 block/SM via smem)
#define GNB 96
__device__ __forceinline__ void gridbar(unsigned gen) {
    __syncthreads();
    if (threadIdx.x == 0) {
        __threadfence();
        atomicAdd(&g_bar, 1u);
        while (atomicAdd(&g_bar, 0u) < gen * GNB) { __nanosleep(64); }
        __threadfence();
    }
    __syncthreads();
}

__global__ void __launch_bounds__(256) gru_persist(const float* __restrict__ whh_f,
                                                   const float* __restrict__ whh_b,
                                                   const float* __restrict__ bhh_f,
                                                   const float* __restrict__ bhh_b,
                                                   float* __restrict__ out) {
    extern __shared__ float sh[];
    float* Hs = sh;                 // 64 x 513
    float* Ws = sh + 64 * 513;      // 32 x 513
    const int dir = blockIdx.y;
    const int n0 = blockIdx.x * 32;
    const int tid = threadIdx.x;
    const int bid = blockIdx.y * 48 + blockIdx.x;
    const float* whh = dir ? whh_b : whh_f;
    const float* bhh = dir ? bhh_b : bhh_f;

    // load W tile ONCE
    for (int i = tid; i < 32 * 512; i += 256) {
        int rr = i >> 9, kk = i & 511;
        Ws[rr * 513 + kk] = whh[(size_t)(n0 + rr) * MM + kk];
    }
    const int cg = tid & 7, r = tid >> 3;
    float bv[4];
#pragma unroll
    for (int c = 0; c < 4; c++) bv[c] = bhh[n0 + cg * 4 + c];

    unsigned gen = 0;
    for (int t = 0; t < SSEQ; t++) {
        // phase A: GEMM hg = h @ W^T + b
        __syncthreads();
        const float* H = g_hst[dir];
        for (int i = tid; i < 64 * 512; i += 256) Hs[(i >> 9) * 513 + (i & 511)] = H[i];
        __syncthreads();
        int row0 = 2 * r, row1 = row0 + 1;
        float acc0[4] = {0.f, 0.f, 0.f, 0.f};
        float acc1[4] = {0.f, 0.f, 0.f, 0.f};
        for (int k = 0; k < 512; k++) {
            float h0 = Hs[row0 * 513 + k];
            float h1 = Hs[row1 * 513 + k];
#pragma unroll
            for (int c = 0; c < 4; c++) {
                float wv = Ws[(cg * 4 + c) * 513 + k];
                acc0[c] += h0 * wv;
                acc1[c] += h1 * wv;
            }
        }
#pragma unroll
        for (int c = 0; c < 4; c++) {
            int n = n0 + cg * 4 + c;
            g_hg[dir][(size_t)row0 * G3M + n] = acc0[c] + bv[c];
            g_hg[dir][(size_t)row1 * G3M + n] = acc1[c] + bv[c];
        }
        gridbar(++gen);
        // phase B: pointwise (all blocks cover both dirs)
        for (int e = bid * 256 + tid; e < 2 * BB * MM; e += GNB * 256) {
            int dd = e >> 15;
            int rem = e & 32767;
            int b = rem >> 9, j = rem & 511;
            int pos = dd ? (SSEQ - 1 - t) : t;
            const float* xrow = g_xg[dd] + (size_t)(b * SSEQ + pos) * G3M;
            const float* hrow = g_hg[dd] + (size_t)b * G3M;
            float rr_ = sigf(xrow[j] + hrow[j]);
            float zz = sigf(xrow[MM + j] + hrow[MM + j]);
            float nn = tanhf(xrow[2 * MM + j] + rr_ * hrow[2 * MM + j]);
            float hp = g_hst[dd][b * MM + j];
            float hn = (1.f - zz) * nn + zz * hp;
            g_hst[dd][b * MM + j] = hn;
            out[(size_t)(b * SSEQ + pos) * MM + j] += hn;
        }
        gridbar(++gen);
    }
}

// ---------------- host launch ----------------
extern "C" void kernel_launch(void* const* d_in, const int* in_sizes, int n_in,
                              void* d_out, int out_size) {
    const float* embed   = (const float*)d_in[0];
    const float* Wioux   = (const float*)d_in[1];
    const float* bioux   = (const float*)d_in[2];
    const float* Wiouh   = (const float*)d_in[3];
    const float* biouh   = (const float*)d_in[4];
    const float* Wfx     = (const float*)d_in[5];
    const float* bfx     = (const float*)d_in[6];
    const float* Wfh     = (const float*)d_in[7];
    const float* bfh     = (const float*)d_in[8];
    const float* wih_f   = (const float*)d_in[9];
    const float* whh_f   = (const float*)d_in[10];
    const float* bih_f   = (const float*)d_in[11];
    const float* bhh_f   = (const float*)d_in[12];
    const float* wih_b   = (const float*)d_in[13];
    const float* whh_b   = (const float*)d_in[14];
    const float* bih_b   = (const float*)d_in[15];
    const float* bhh_b   = (const float*)d_in[16];

    const int* leaf_idx = nullptr; const int* level_idx = nullptr;
    const int* child = nullptr; const int* ctx = nullptr;
    for (int i = 17; i < n_in; i++) {
        int sz = in_sizes[i];
        if (sz == NLEAF)                 leaf_idx  = (const int*)d_in[i];
        else if (sz == DD * NNODE)       level_idx = (const int*)d_in[i];
        else if (sz == DD * NNODE * KCH) child     = (const int*)d_in[i];
        else if (sz == BB * SSEQ)        ctx       = (const int*)d_in[i];
    }

    float* out = (float*)d_out;

    const size_t GRU_SMEM = (64 + 32) * 513 * sizeof(float);
    cudaFuncSetAttribute(mma_gemm, cudaFuncAttributeMaxDynamicSharedMemorySize, MMA_SMEM_BYTES);
    cudaFuncSetAttribute(gru_persist, cudaFuncAttributeMaxDynamicSharedMemorySize, (int)GRU_SMEM);

    __nv_bfloat16* d_Hhi;   cudaGetSymbolAddress((void**)&d_Hhi, g_Hhi);
    __nv_bfloat16* d_Hlo;   cudaGetSymbolAddress((void**)&d_Hlo, g_Hlo);
    __nv_bfloat16* d_Xhi;   cudaGetSymbolAddress((void**)&d_Xhi, g_Xallhi);
    __nv_bfloat16* d_Xlo;   cudaGetSymbolAddress((void**)&d_Xlo, g_Xalllo);
    __nv_bfloat16* d_SHhi;  cudaGetSymbolAddress((void**)&d_SHhi, g_SUMHhi);
    __nv_bfloat16* d_SHlo;  cudaGetSymbolAddress((void**)&d_SHlo, g_SUMHlo);
    __nv_bfloat16* d_W1hi;  cudaGetSymbolAddress((void**)&d_W1hi, g_W1hi);
    __nv_bfloat16* d_W1lo;  cudaGetSymbolAddress((void**)&d_W1lo, g_W1lo);
    __nv_bfloat16* d_W2hi;  cudaGetSymbolAddress((void**)&d_W2hi, g_W2hi);
    __nv_bfloat16* d_W2lo;  cudaGetSymbolAddress((void**)&d_W2lo, g_W2lo);
    __nv_bfloat16* d_WfThi; cudaGetSymbolAddress((void**)&d_WfThi, g_WfThi);
    __nv_bfloat16* d_WfTlo; cudaGetSymbolAddress((void**)&d_WfTlo, g_WfTlo);
    __nv_bfloat16* d_wihhi; cudaGetSymbolAddress((void**)&d_wihhi, g_wihhi);
    __nv_bfloat16* d_wihlo; cudaGetSymbolAddress((void**)&d_wihlo, g_wihlo);
    __nv_bfloat16* d_xshi;  cudaGetSymbolAddress((void**)&d_xshi, g_xshi);
    __nv_bfloat16* d_xslo;  cudaGetSymbolAddress((void**)&d_xslo, g_xslo);
    float* d_IOUF;  cudaGetSymbolAddress((void**)&d_IOUF, g_IOUFall);
    float* d_HW;    cudaGetSymbolAddress((void**)&d_HW, g_HW);
    float* d_bb;    cudaGetSymbolAddress((void**)&d_bb, g_biasbig);
    float* d_xg;    cudaGetSymbolAddress((void**)&d_xg, g_xg);

    // prep + init
    prep_w1<<<(2048 * 256 + 255) / 256, 256>>>(Wioux, Wfx, bioux, biouh, bfx);
    prep_w2<<<(G3M * 256 + 255) / 256, 256>>>(Wiouh);
    prep_small<<<(MM * (MM / 2) + 2 * G3M * (MM / 2) + 255) / 256, 256>>>(Wfh, wih_f, wih_b);
    init_leaf<<<(NLEAF * (MM / 4) + 255) / 256, 256>>>(embed, leaf_idx);
    init_misc<<<(BB * SSEQ * MM + 255) / 256, 256>>>(out, bfh);
    gather_x_all<<<(NALL * (MM / 4) + 255) / 256, 256>>>(embed, level_idx);

    // upfront: IOUF_all = X_all @ [Wioux|Wfx]^T + biasbig  (M=32768, N=2048, K=512)
    {
        dim3 grid(2048 / 128, NALL / 128);
        mma_gemm<<<grid, 256, MMA_SMEM_BYTES>>>(d_Xhi, d_Xlo, d_W1hi, d_W1lo,
                                                d_bb, d_IOUF, 2048, 512, 0);
    }
    // leaf HW
    {
        dim3 grid(512 / 128, NLEAF / 128);
        mma_gemm<<<grid, 256, MMA_SMEM_BYTES>>>(d_Hhi + MM, d_Hlo + MM, d_WfThi, d_WfTlo,
                                                bfh, d_HW + MM, 512, 512, 0);
    }

    // tree levels
    for (int d = 0; d < DD; d++) {
        gather_level<<<(NNODE * (MM / 4) + 255) / 256, 256>>>(child, d);
        {   // IOU slice += SUMH @ Wiouh^T : M=4096, N=1536, K=512, accumulate
            dim3 grid(G3M / 128, NNODE / 128);
            mma_gemm<<<grid, 256, MMA_SMEM_BYTES>>>(d_SHhi, d_SHlo, d_W2hi, d_W2lo,
                                                    nullptr, d_IOUF + (size_t)d * NNODE * 2048,
                                                    2048, 512, 1);
        }
        level_point<<<(NNODE * (MM / 2) + 255) / 256, 256>>>(child, d);
        if (d < DD - 1) {
            dim3 grid(512 / 128, NNODE / 128);
            size_t off = (size_t)(OFFS + d * NNODE) * MM;
            mma_gemm<<<grid, 256, MMA_SMEM_BYTES>>>(d_Hhi + off, d_Hlo + off, d_WfThi, d_WfTlo,
                                                    bfh, d_HW + off, 512, 512, 0);
        }
    }

    // GRU input gates
    gather_xs<<<(BB * SSEQ * (MM / 4) + 255) / 256, 256>>>(ctx);
    {
        dim3 grid(G3M / 128, (BB * SSEQ) / 128);
        mma_gemm<<<grid, 256, MMA_SMEM_BYTES>>>(d_xshi, d_xslo, d_wihhi, d_wihlo,
                                                bih_f, d_xg, G3M, 512, 0);
        mma_gemm<<<grid, 256, MMA_SMEM_BYTES>>>(d_xshi, d_xslo,
                                                d_wihhi + (size_t)G3M * MM, d_wihlo + (size_t)G3M * MM,
                                                bih_b, d_xg + (size_t)BB * SSEQ * G3M, G3M, 512, 0);
    }

    // GRU recurrence: single persistent kernel
    {
        dim3 grid(48, 2);
        gru_persist<<<grid, 256, GRU_SMEM>>>(whh_f, whh_b, bhh_f, bhh_b, out);
    }
}

// round 9
// speedup vs baseline: 2.8639x; 1.0848x over previous
#include <cuda_runtime.h>
#include <cuda_bf16.h>
#include <math.h>
#include <cstdint>

// ---------------- problem constants ----------------
#define VV     32000
#define MM     512
#define NLEAF  16384
#define DD     8
#define NNODE  4096
#define KCH    4
#define BB     64
#define SSEQ   16
#define POOLSZ (1 + NLEAF + DD * NNODE)   // 49153
#define OFFS   (1 + NLEAF)                // 16385
#define G3M    (3 * MM)                   // 1536
#define NALL   (DD * NNODE)               // 32768

__device__ __forceinline__ float sigf(float x) { return 1.0f / (1.0f + expf(-x)); }

__device__ __forceinline__ uint32_t smem_u32(const void* p) {
    uint32_t a;
    asm("{ .reg .u64 t; cvta.to.shared.u64 t, %1; cvt.u32.u64 %0, t; }" : "=r"(a) : "l"(p));
    return a;
}

// split (x,y) into packed bf16x2 hi + bf16x2 lo (lower 16 bits = x)
__device__ __forceinline__ void splitpack(float x, float y, uint32_t& hi, uint32_t& lo) {
    uint32_t h;
    asm("cvt.rn.bf16x2.f32 %0, %1, %2;" : "=r"(h) : "f"(y), "f"(x));
    float hx = __uint_as_float(h << 16);
    float hy = __uint_as_float(h & 0xFFFF0000u);
    float rx = x - hx, ry = y - hy;
    asm("cvt.rn.bf16x2.f32 %0, %1, %2;" : "=r"(lo) : "f"(ry), "f"(rx));
    hi = h;
}

#define MMA_BF16(c, a0, a1, a2, a3, b0, b1) \
    asm volatile("mma.sync.aligned.m16n8k16.row.col.f32.bf16.bf16.f32 " \
        "{%0,%1,%2,%3}, {%4,%5,%6,%7}, {%8,%9}, {%0,%1,%2,%3};" \
        : "+f"((c)[0]), "+f"((c)[1]), "+f"((c)[2]), "+f"((c)[3]) \
        : "r"(a0), "r"(a1), "r"(a2), "r"(a3), "r"(b0), "r"(b1))

#define LDSM_X4(r0, r1, r2, r3, addr) \
    asm volatile("ldmatrix.sync.aligned.m8n8.x4.shared.b16 {%0,%1,%2,%3}, [%4];" \
        : "=r"(r0), "=r"(r1), "=r"(r2), "=r"(r3) : "r"(addr))

#define CP_ASYNC16(dst, src) \
    asm volatile("cp.async.cg.shared.global [%0], [%1], 16;" :: "r"(dst), "l"(src))
#define CP_COMMIT() asm volatile("cp.async.commit_group;")
#define CP_WAIT1()  asm volatile("cp.async.wait_group 1;")
#define CP_WAIT0()  asm volatile("cp.async.wait_group 0;")

// ---------------- device scratch ----------------
__device__ float g_c_pool[(size_t)POOLSZ * MM];
__device__ float g_h_pool[(size_t)POOLSZ * MM];
__device__ float g_HW[(size_t)POOLSZ * MM];         // only internal-node region used
__device__ float g_IOUFall[(size_t)NALL * 2048];
__device__ float g_biasbig[2048];
__device__ float g_bihcat[2 * G3M];
__device__ unsigned g_bar;
// bf16 split planes
__device__ __nv_bfloat16 g_W1hi[(size_t)2048 * MM];   // [Wioux|Wfx]^T
__device__ __nv_bfloat16 g_W1lo[(size_t)2048 * MM];
__device__ __nv_bfloat16 g_W2hi[(size_t)G3M * MM];    // Wiouh^T
__device__ __nv_bfloat16 g_W2lo[(size_t)G3M * MM];
__device__ __nv_bfloat16 g_WfThi[(size_t)MM * MM];
__device__ __nv_bfloat16 g_WfTlo[(size_t)MM * MM];
__device__ __nv_bfloat16 g_wihhi[2][(size_t)G3M * MM];  // contiguous -> single 3072xK B
__device__ __nv_bfloat16 g_wihlo[2][(size_t)G3M * MM];
__device__ __nv_bfloat16 g_Xallhi[(size_t)NALL * MM];
__device__ __nv_bfloat16 g_Xalllo[(size_t)NALL * MM];
__device__ __nv_bfloat16 g_SUMHhi[(size_t)NNODE * MM];
__device__ __nv_bfloat16 g_SUMHlo[(size_t)NNODE * MM];
__device__ __nv_bfloat16 g_Hhi[(size_t)POOLSZ * MM];
__device__ __nv_bfloat16 g_Hlo[(size_t)POOLSZ * MM];
__device__ __nv_bfloat16 g_xshi[(size_t)BB * SSEQ * MM];
__device__ __nv_bfloat16 g_xslo[(size_t)BB * SSEQ * MM];
// GRU  (xg row-major [1024][3072]: dir-major within row)
__device__ float g_xg[(size_t)BB * SSEQ * 2 * G3M];
__device__ float g_hg[2][(size_t)BB * G3M];
__device__ float g_hst[2][(size_t)BB * MM];

// ---------------- shared GEMM body: C[tile] = A @ Bt^T (+bias | +=C) ----------------
#define RS 20
#define PLANE 2560
#define STG_BYTES 40960
#define MMA_SMEM_BYTES (2 * STG_BYTES)

__device__ __forceinline__ void gemm_body(
    const uint32_t* pA0, const uint32_t* pA1, const uint32_t* pB0, const uint32_t* pB1,
    int mbase, int nbase, int K, const float* bias, float* C, int ldC, int accum,
    uint32_t smb) {
    const int tid = threadIdx.x;
    const int w = tid >> 5, lane = tid & 31;
    const int warpM = w & 1, warpN = w >> 1;
    const int Kw = K >> 1;
    const int nCh = Kw >> 4;

    float acc[4][4][4];
#pragma unroll
    for (int i = 0; i < 4; i++)
#pragma unroll
        for (int j = 0; j < 4; j++)
#pragma unroll
            for (int q = 0; q < 4; q++) acc[i][j][q] = 0.f;

    const int lrow = lane & 15, lcol = lane >> 4;
    uint32_t aAddr[4], bAddr[2];
#pragma unroll
    for (int i = 0; i < 4; i++)
        aAddr[i] = smb + (uint32_t)(((warpM * 64 + i * 16 + lrow) * RS + lcol * 4) * 4);
#pragma unroll
    for (int jp = 0; jp < 2; jp++)
        bAddr[jp] = smb + (uint32_t)(2 * PLANE * 4 + ((warpN * 32 + jp * 16 + lrow) * RS + lcol * 4) * 4);

#define ISSUE(tw) do {                                                            \
    const int kw0 = (tw) * 16;                                                    \
    const uint32_t sb = smb + (uint32_t)(((tw) & 1) * STG_BYTES);                 \
    _Pragma("unroll")                                                             \
    for (int q = 0; q < 8; q++) {                                                 \
        const int pl = q >> 1;                                                    \
        int s = tid + (q & 1) * 256;                                              \
        int r = s >> 2, sg = s & 3;                                               \
        const uint32_t* src = (pl == 0 ? pA0 : pl == 1 ? pA1 : pl == 2 ? pB0 : pB1) \
            + (size_t)((pl < 2 ? mbase : nbase) + r) * Kw + kw0 + sg * 4;         \
        uint32_t dst = sb + (uint32_t)((pl * PLANE + r * RS + sg * 4) * 4);       \
        CP_ASYNC16(dst, src);                                                     \
    }                                                                             \
    CP_COMMIT(); } while (0)

    ISSUE(0);
    if (nCh > 1) ISSUE(1);

    for (int t = 0; t < nCh; t++) {
        if (t + 1 < nCh) CP_WAIT1(); else CP_WAIT0();
        __syncthreads();

        const uint32_t so = (uint32_t)((t & 1) * STG_BYTES);
#pragma unroll
        for (int ks = 0; ks < 2; ks++) {
            const uint32_t ko = so + ks * 32;
            uint32_t Bh[4][2], Bl[4][2];
#pragma unroll
            for (int jp = 0; jp < 2; jp++) {
                LDSM_X4(Bh[2 * jp][0], Bh[2 * jp + 1][0], Bh[2 * jp][1], Bh[2 * jp + 1][1],
                        bAddr[jp] + ko);
                LDSM_X4(Bl[2 * jp][0], Bl[2 * jp + 1][0], Bl[2 * jp][1], Bl[2 * jp + 1][1],
                        bAddr[jp] + PLANE * 4 + ko);
            }
#pragma unroll
            for (int i = 0; i < 4; i++) {
                uint32_t Ah0, Ah1, Ah2, Ah3, Al0, Al1, Al2, Al3;
                LDSM_X4(Ah0, Ah1, Ah2, Ah3, aAddr[i] + ko);
                LDSM_X4(Al0, Al1, Al2, Al3, aAddr[i] + PLANE * 4 + ko);
#pragma unroll
                for (int j = 0; j < 4; j++) {
                    MMA_BF16(acc[i][j], Ah0, Ah1, Ah2, Ah3, Bh[j][0], Bh[j][1]);
                    MMA_BF16(acc[i][j], Ah0, Ah1, Ah2, Ah3, Bl[j][0], Bl[j][1]);
                    MMA_BF16(acc[i][j], Al0, Al1, Al2, Al3, Bh[j][0], Bh[j][1]);
                }
            }
        }
        if (t + 2 < nCh) {
            __syncthreads();
            ISSUE(t + 2);
        }
    }
#undef ISSUE

    const int g = lane >> 2, tg = lane & 3;
#pragma unroll
    for (int i = 0; i < 4; i++) {
#pragma unroll
        for (int j = 0; j < 4; j++) {
            int row = mbase + warpM * 64 + i * 16 + g;
            int col = nbase + warpN * 32 + j * 8 + tg * 2;
            float* c0p = C + (size_t)row * ldC + col;
            float* c1p = C + (size_t)(row + 8) * ldC + col;
            float a0 = acc[i][j][0], a1 = acc[i][j][1];
            float a2 = acc[i][j][2], a3 = acc[i][j][3];
            if (accum) {
                float2 e0 = *(float2*)c0p, e1 = *(float2*)c1p;
                a0 += e0.x; a1 += e0.y; a2 += e1.x; a3 += e1.y;
            } else {
                float b0v = bias[col], b1v = bias[col + 1];
                a0 += b0v; a1 += b1v; a2 += b0v; a3 += b1v;
            }
            *(float2*)c0p = make_float2(a0, a1);
            *(float2*)c1p = make_float2(a2, a3);
        }
    }
}

// plain GEMM kernel
__global__ void __launch_bounds__(256)
mma_gemm(const __nv_bfloat16* __restrict__ Ahi, const __nv_bfloat16* __restrict__ Alo,
         const __nv_bfloat16* __restrict__ Bhi, const __nv_bfloat16* __restrict__ Blo,
         const float* __restrict__ bias, float* __restrict__ C, int ldC, int K, int accum) {
    extern __shared__ uint32_t sm[];
    gemm_body((const uint32_t*)Ahi, (const uint32_t*)Alo,
              (const uint32_t*)Bhi, (const uint32_t*)Blo,
              blockIdx.y * 128, blockIdx.x * 128, K, bias, C, ldC, accum, smem_u32(sm));
}

// dual GEMM: bx<12 -> IOU accum (A1@W2 += C1, ldC 2048); bx>=12 -> HW (A2@WfT + bfh, ldC 512)
__global__ void __launch_bounds__(256)
mma_gemm_dual(const __nv_bfloat16* __restrict__ A1hi, const __nv_bfloat16* __restrict__ A1lo,
              const __nv_bfloat16* __restrict__ A2hi, const __nv_bfloat16* __restrict__ A2lo,
              const __nv_bfloat16* __restrict__ B1hi, const __nv_bfloat16* __restrict__ B1lo,
              const __nv_bfloat16* __restrict__ B2hi, const __nv_bfloat16* __restrict__ B2lo,
              const float* __restrict__ bias2, float* __restrict__ C1, float* __restrict__ C2) {
    extern __shared__ uint32_t sm[];
    if (blockIdx.x < 12) {
        gemm_body((const uint32_t*)A1hi, (const uint32_t*)A1lo,
                  (const uint32_t*)B1hi, (const uint32_t*)B1lo,
                  blockIdx.y * 128, blockIdx.x * 128, 512, nullptr, C1, 2048, 1, smem_u32(sm));
    } else {
        gemm_body((const uint32_t*)A2hi, (const uint32_t*)A2lo,
                  (const uint32_t*)B2hi, (const uint32_t*)B2lo,
                  blockIdx.y * 128, (blockIdx.x - 12) * 128, 512, bias2, C2, 512, 0, smem_u32(sm));
    }
}

// ---------------- prep kernels ----------------
__global__ void prep_w1(const float* __restrict__ Wioux, const float* __restrict__ Wfx,
                        const float* __restrict__ bioux, const float* __restrict__ biouh,
                        const float* __restrict__ bfx) {
    int idx = blockIdx.x * blockDim.x + threadIdx.x;
    if (idx < 2048 * 256) {
        int n = idx >> 8, kw = idx & 255;
        int k0 = 2 * kw, k1 = k0 + 1;
        float v0, v1;
        if (n < G3M) { v0 = Wioux[(size_t)k0 * G3M + n]; v1 = Wioux[(size_t)k1 * G3M + n]; }
        else         { v0 = Wfx[(size_t)k0 * MM + (n - G3M)]; v1 = Wfx[(size_t)k1 * MM + (n - G3M)]; }
        uint32_t h, l; splitpack(v0, v1, h, l);
        ((uint32_t*)g_W1hi)[idx] = h;
        ((uint32_t*)g_W1lo)[idx] = l;
    }
    if (idx < 2048)
        g_biasbig[idx] = (idx < G3M) ? (bioux[idx] + biouh[idx]) : bfx[idx - G3M];
}

__global__ void prep_w2(const float* __restrict__ Wiouh) {
    int idx = blockIdx.x * blockDim.x + threadIdx.x;
    if (idx >= G3M * 256) return;
    int n = idx >> 8, kw = idx & 255;
    float v0 = Wiouh[(size_t)(2 * kw) * G3M + n];
    float v1 = Wiouh[(size_t)(2 * kw + 1) * G3M + n];
    uint32_t h, l; splitpack(v0, v1, h, l);
    ((uint32_t*)g_W2hi)[idx] = h;
    ((uint32_t*)g_W2lo)[idx] = l;
}

__global__ void prep_small(const float* __restrict__ Wfh,
                           const float* __restrict__ wih_f, const float* __restrict__ wih_b,
                           const float* __restrict__ bih_f, const float* __restrict__ bih_b) {
    int idx = blockIdx.x * blockDim.x + threadIdx.x;
    const int T1 = MM * (MM / 2);
    const int T2 = G3M * (MM / 2);
    if (idx < T1) {
        int n = idx >> 8, kw = idx & 255;
        float v0 = Wfh[(size_t)(2 * kw) * MM + n];
        float v1 = Wfh[(size_t)(2 * kw + 1) * MM + n];
        uint32_t h, l; splitpack(v0, v1, h, l);
        ((uint32_t*)g_WfThi)[idx] = h;
        ((uint32_t*)g_WfTlo)[idx] = l;
    } else if (idx < T1 + 2 * T2) {
        int r = idx - T1;
        int dir = r / T2, j = r % T2;
        const float* wsrc = dir ? wih_b : wih_f;
        float v0 = wsrc[2 * j], v1 = wsrc[2 * j + 1];
        uint32_t h, l; splitpack(v0, v1, h, l);
        ((uint32_t*)g_wihhi[dir])[j] = h;
        ((uint32_t*)g_wihlo[dir])[j] = l;
    }
    if (idx < 2 * G3M)
        g_bihcat[idx] = (idx < G3M) ? bih_f[idx] : bih_b[idx - G3M];
}

// ---------------- init ----------------
__global__ void init_leaf(const float* __restrict__ embed, const int* __restrict__ leaf_idx) {
    int idx = blockIdx.x * blockDim.x + threadIdx.x;
    if (idx >= NLEAF * (MM / 4)) return;
    int n = idx >> 7, m = (idx & 127) * 4;
    int w = leaf_idx[n];
    float4 v = *(const float4*)(embed + (size_t)w * MM + m);
    *(float4*)(g_h_pool + (size_t)(1 + n) * MM + m) = v;
    // NOTE: c_pool of leaves never read (leaf c == 0 handled by ci>NLEAF guard)
    uint32_t h0, l0, h1, l1;
    splitpack(v.x, v.y, h0, l0);
    splitpack(v.z, v.w, h1, l1);
    size_t wrd = ((size_t)(1 + n) * MM + m) >> 1;
    ((uint32_t*)g_Hhi)[wrd] = h0; ((uint32_t*)g_Hhi)[wrd + 1] = h1;
    ((uint32_t*)g_Hlo)[wrd] = l0; ((uint32_t*)g_Hlo)[wrd + 1] = l1;
}

__global__ void init_misc(float* __restrict__ out) {
    int idx = blockIdx.x * blockDim.x + threadIdx.x;
    if (idx == 0) g_bar = 0u;
    if (idx < MM) g_h_pool[idx] = 0.f;         // zero slot h
    if (idx < 2 * BB * MM) (&g_hst[0][0])[idx] = 0.f;
    if (idx < BB * SSEQ * MM) out[idx] = 0.f;
}

// ---------------- gather x embeddings for ALL levels ----------------
__global__ void gather_x_all(const float* __restrict__ embed, const int* __restrict__ lwi) {
    int idx = blockIdx.x * blockDim.x + threadIdx.x;
    if (idx >= NALL * (MM / 4)) return;
    int ng = idx >> 7, m = (idx & 127) * 4;
    int w = lwi[ng];
    float4 x = *(const float4*)(embed + (size_t)w * MM + m);
    uint32_t h0, l0, h1, l1;
    splitpack(x.x, x.y, h0, l0);
    splitpack(x.z, x.w, h1, l1);
    size_t wrd = ((size_t)ng * MM + m) >> 1;
    ((uint32_t*)g_Xallhi)[wrd] = h0; ((uint32_t*)g_Xallhi)[wrd + 1] = h1;
    ((uint32_t*)g_Xalllo)[wrd] = l0; ((uint32_t*)g_Xalllo)[wrd + 1] = l1;
}

// ---------------- per-level gather: sum of child h ----------------
__global__ void gather_level(const int* __restrict__ child, int d) {
    int idx = blockIdx.x * blockDim.x + threadIdx.x;
    if (idx >= NNODE * (MM / 4)) return;
    int n = idx >> 7, m = (idx & 127) * 4;
    float4 s = make_float4(0.f, 0.f, 0.f, 0.f);
    const int* ch = child + ((size_t)d * NNODE + n) * KCH;
#pragma unroll
    for (int k = 0; k < KCH; k++) {
        int ci = ch[k];
        float4 hv = *(const float4*)(g_h_pool + (size_t)ci * MM + m);
        s.x += hv.x; s.y += hv.y; s.z += hv.z; s.w += hv.w;
    }
    uint32_t h0, l0, h1, l1;
    splitpack(s.x, s.y, h0, l0);
    splitpack(s.z, s.w, h1, l1);
    size_t wrd = ((size_t)n * MM + m) >> 1;
    ((uint32_t*)g_SUMHhi)[wrd] = h0; ((uint32_t*)g_SUMHhi)[wrd + 1] = h1;
    ((uint32_t*)g_SUMHlo)[wrd] = l0; ((uint32_t*)g_SUMHlo)[wrd + 1] = l1;
}

// ---------------- level pointwise (skip leaf/zero children: c==0 there) ----------------
__global__ void level_point(const int* __restrict__ child, int d) {
    int idx = blockIdx.x * blockDim.x + threadIdx.x;
    if (idx >= NNODE * (MM / 2)) return;
    int n = idx >> 8, j = idx & 255;
    int m = 2 * j;
    const float* row = g_IOUFall + (size_t)(d * NNODE + n) * 2048;
    float2 iv = *(const float2*)(row + m);
    float2 ov = *(const float2*)(row + MM + m);
    float2 uv = *(const float2*)(row + 2 * MM + m);
    float2 fx = *(const float2*)(row + 3 * MM + m);
    float c0 = sigf(iv.x) * tanhf(uv.x);
    float c1 = sigf(iv.y) * tanhf(uv.y);
    const int* ch = child + ((size_t)d * NNODE + n) * KCH;
#pragma unroll
    for (int k = 0; k < KCH; k++) {
        int ci = ch[k];
        if (ci > NLEAF) {                 // internal node: c != 0
            float2 hw = *(const float2*)(g_HW + (size_t)ci * MM + m);
            float2 cc = *(const float2*)(g_c_pool + (size_t)ci * MM + m);
            c0 += sigf(fx.x + hw.x) * cc.x;
            c1 += sigf(fx.y + hw.y) * cc.y;
        }
    }
    float h0 = sigf(ov.x) * tanhf(c0);
    float h1 = sigf(ov.y) * tanhf(c1);
    size_t slot = (size_t)(OFFS + d * NNODE + n) * MM + m;
    *(float2*)(g_c_pool + slot) = make_float2(c0, c1);
    *(float2*)(g_h_pool + slot) = make_float2(h0, h1);
    uint32_t sh, sl; splitpack(h0, h1, sh, sl);
    ((uint32_t*)g_Hhi)[slot >> 1] = sh;
    ((uint32_t*)g_Hlo)[slot >> 1] = sl;
}

// ---------------- GRU ----------------
__global__ void gather_xs(const int* __restrict__ ctx) {
    int idx = blockIdx.x * blockDim.x + threadIdx.x;
    if (idx >= BB * SSEQ * (MM / 4)) return;
    int rowI = idx >> 7, m = (idx & 127) * 4;
    int p = ctx[rowI];
    float4 v = *(const float4*)(g_h_pool + (size_t)p * MM + m);
    uint32_t h0, l0, h1, l1;
    splitpack(v.x, v.y, h0, l0);
    splitpack(v.z, v.w, h1, l1);
    size_t wrd = ((size_t)rowI * MM + m) >> 1;
    ((uint32_t*)g_xshi)[wrd] = h0; ((uint32_t*)g_xshi)[wrd + 1] = h1;
    ((uint32_t*)g_xslo)[wrd] = l0; ((uint32_t*)g_xslo)[wrd + 1] = l1;
}

// persistent GRU
#define GNB 96
__device__ __forceinline__ void gridbar(unsigned gen) {
    __syncthreads();
    if (threadIdx.x == 0) {
        __threadfence();
        atomicAdd(&g_bar, 1u);
        while (atomicAdd(&g_bar, 0u) < gen * GNB) { __nanosleep(64); }
        __threadfence();
    }
    __syncthreads();
}

__global__ void __launch_bounds__(256) gru_persist(const float* __restrict__ whh_f,
                                                   const float* __restrict__ whh_b,
                                                   const float* __restrict__ bhh_f,
                                                   const float* __restrict__ bhh_b,
                                                   float* __restrict__ out) {
    extern __shared__ float sh[];
    float* Hs = sh;                 // 64 x 513
    float* Ws = sh + 64 * 513;      // 32 x 513
    const int dir = blockIdx.y;
    const int n0 = blockIdx.x * 32;
    const int tid = threadIdx.x;
    const int bid = blockIdx.y * 48 + blockIdx.x;
    const float* whh = dir ? whh_b : whh_f;
    const float* bhh = dir ? bhh_b : bhh_f;

    for (int i = tid; i < 32 * 512; i += 256) {
        int rr = i >> 9, kk = i & 511;
        Ws[rr * 513 + kk] = whh[(size_t)(n0 + rr) * MM + kk];
    }
    const int cg = tid & 7, r = tid >> 3;
    float bv[4];
#pragma unroll
    for (int c = 0; c < 4; c++) bv[c] = bhh[n0 + cg * 4 + c];

    unsigned gen = 0;
    for (int t = 0; t < SSEQ; t++) {
        __syncthreads();
        const float* H = g_hst[dir];
        for (int i = tid; i < 64 * 512; i += 256) Hs[(i >> 9) * 513 + (i & 511)] = H[i];
        __syncthreads();
        int row0 = 2 * r, row1 = row0 + 1;
        float acc0[4] = {0.f, 0.f, 0.f, 0.f};
        float acc1[4] = {0.f, 0.f, 0.f, 0.f};
        for (int k = 0; k < 512; k++) {
            float h0 = Hs[row0 * 513 + k];
            float h1 = Hs[row1 * 513 + k];
#pragma unroll
            for (int c = 0; c < 4; c++) {
                float wv = Ws[(cg * 4 + c) * 513 + k];
                acc0[c] += h0 * wv;
                acc1[c] += h1 * wv;
            }
        }
#pragma unroll
        for (int c = 0; c < 4; c++) {
            int n = n0 + cg * 4 + c;
            g_hg[dir][(size_t)row0 * G3M + n] = acc0[c] + bv[c];
            g_hg[dir][(size_t)row1 * G3M + n] = acc1[c] + bv[c];
        }
        gridbar(++gen);
        for (int e = bid * 256 + tid; e < 2 * BB * MM; e += GNB * 256) {
            int dd = e >> 15;
            int rem = e & 32767;
            int b = rem >> 9, j = rem & 511;
            int pos = dd ? (SSEQ - 1 - t) : t;
            const float* xrow = g_xg + (size_t)(b * SSEQ + pos) * (2 * G3M) + dd * G3M;
            const float* hrow = g_hg[dd] + (size_t)b * G3M;
            float rr_ = sigf(xrow[j] + hrow[j]);
            float zz = sigf(xrow[MM + j] + hrow[MM + j]);
            float nn = tanhf(xrow[2 * MM + j] + rr_ * hrow[2 * MM + j]);
            float hp = g_hst[dd][b * MM + j];
            float hn = (1.f - zz) * nn + zz * hp;
            g_hst[dd][b * MM + j] = hn;
            out[(size_t)(b * SSEQ + pos) * MM + j] += hn;
        }
        gridbar(++gen);
    }
}

// ---------------- host launch ----------------
extern "C" void kernel_launch(void* const* d_in, const int* in_sizes, int n_in,
                              void* d_out, int out_size) {
    const float* embed   = (const float*)d_in[0];
    const float* Wioux   = (const float*)d_in[1];
    const float* bioux   = (const float*)d_in[2];
    const float* Wiouh   = (const float*)d_in[3];
    const float* biouh   = (const float*)d_in[4];
    const float* Wfx     = (const float*)d_in[5];
    const float* bfx     = (const float*)d_in[6];
    const float* Wfh     = (const float*)d_in[7];
    const float* bfh     = (const float*)d_in[8];
    const float* wih_f   = (const float*)d_in[9];
    const float* whh_f   = (const float*)d_in[10];
    const float* bih_f   = (const float*)d_in[11];
    const float* bhh_f   = (const float*)d_in[12];
    const float* wih_b   = (const float*)d_in[13];
    const float* whh_b   = (const float*)d_in[14];
    const float* bih_b   = (const float*)d_in[15];
    const float* bhh_b   = (const float*)d_in[16];

    const int* leaf_idx = nullptr; const int* level_idx = nullptr;
    const int* child = nullptr; const int* ctx = nullptr;
    for (int i = 17; i < n_in; i++) {
        int sz = in_sizes[i];
        if (sz == NLEAF)                 leaf_idx  = (const int*)d_in[i];
        else if (sz == DD * NNODE)       level_idx = (const int*)d_in[i];
        else if (sz == DD * NNODE * KCH) child     = (const int*)d_in[i];
        else if (sz == BB * SSEQ)        ctx       = (const int*)d_in[i];
    }

    float* out = (float*)d_out;

    const size_t GRU_SMEM = (64 + 32) * 513 * sizeof(float);
    cudaFuncSetAttribute(mma_gemm, cudaFuncAttributeMaxDynamicSharedMemorySize, MMA_SMEM_BYTES);
    cudaFuncSetAttribute(mma_gemm_dual, cudaFuncAttributeMaxDynamicSharedMemorySize, MMA_SMEM_BYTES);
    cudaFuncSetAttribute(gru_persist, cudaFuncAttributeMaxDynamicSharedMemorySize, (int)GRU_SMEM);

    __nv_bfloat16* d_Hhi;   cudaGetSymbolAddress((void**)&d_Hhi, g_Hhi);
    __nv_bfloat16* d_Hlo;   cudaGetSymbolAddress((void**)&d_Hlo, g_Hlo);
    __nv_bfloat16* d_Xhi;   cudaGetSymbolAddress((void**)&d_Xhi, g_Xallhi);
    __nv_bfloat16* d_Xlo;   cudaGetSymbolAddress((void**)&d_Xlo, g_Xalllo);
    __nv_bfloat16* d_SHhi;  cudaGetSymbolAddress((void**)&d_SHhi, g_SUMHhi);
    __nv_bfloat16* d_SHlo;  cudaGetSymbolAddress((void**)&d_SHlo, g_SUMHlo);
    __nv_bfloat16* d_W1hi;  cudaGetSymbolAddress((void**)&d_W1hi, g_W1hi);
    __nv_bfloat16* d_W1lo;  cudaGetSymbolAddress((void**)&d_W1lo, g_W1lo);
    __nv_bfloat16* d_W2hi;  cudaGetSymbolAddress((void**)&d_W2hi, g_W2hi);
    __nv_bfloat16* d_W2lo;  cudaGetSymbolAddress((void**)&d_W2lo, g_W2lo);
    __nv_bfloat16* d_WfThi; cudaGetSymbolAddress((void**)&d_WfThi, g_WfThi);
    __nv_bfloat16* d_WfTlo; cudaGetSymbolAddress((void**)&d_WfTlo, g_WfTlo);
    __nv_bfloat16* d_wihhi; cudaGetSymbolAddress((void**)&d_wihhi, g_wihhi);
    __nv_bfloat16* d_wihlo; cudaGetSymbolAddress((void**)&d_wihlo, g_wihlo);
    __nv_bfloat16* d_xshi;  cudaGetSymbolAddress((void**)&d_xshi, g_xshi);
    __nv_bfloat16* d_xslo;  cudaGetSymbolAddress((void**)&d_xslo, g_xslo);
    float* d_IOUF;   cudaGetSymbolAddress((void**)&d_IOUF, g_IOUFall);
    float* d_HW;     cudaGetSymbolAddress((void**)&d_HW, g_HW);
    float* d_bb;     cudaGetSymbolAddress((void**)&d_bb, g_biasbig);
    float* d_bih;    cudaGetSymbolAddress((void**)&d_bih, g_bihcat);
    float* d_xg;     cudaGetSymbolAddress((void**)&d_xg, g_xg);

    // prep + init
    prep_w1<<<(2048 * 256 + 255) / 256, 256>>>(Wioux, Wfx, bioux, biouh, bfx);
    prep_w2<<<(G3M * 256 + 255) / 256, 256>>>(Wiouh);
    prep_small<<<(MM * (MM / 2) + 2 * G3M * (MM / 2) + 255) / 256, 256>>>(Wfh, wih_f, wih_b, bih_f, bih_b);
    init_leaf<<<(NLEAF * (MM / 4) + 255) / 256, 256>>>(embed, leaf_idx);
    init_misc<<<(BB * SSEQ * MM + 255) / 256, 256>>>(out);
    gather_x_all<<<(NALL * (MM / 4) + 255) / 256, 256>>>(embed, level_idx);

    // upfront: IOUF_all = X_all @ [Wioux|Wfx]^T + biasbig
    {
        dim3 grid(2048 / 128, NALL / 128);
        mma_gemm<<<grid, 256, MMA_SMEM_BYTES>>>(d_Xhi, d_Xlo, d_W1hi, d_W1lo,
                                                d_bb, d_IOUF, 2048, 512, 0);
    }
    // NOTE: no leaf HW GEMM — HW only multiplies c, and c==0 for leaves.

    // level 0: IOU accum only
    gather_level<<<(NNODE * (MM / 4) + 255) / 256, 256>>>(child, 0);
    {
        dim3 grid(G3M / 128, NNODE / 128);
        mma_gemm<<<grid, 256, MMA_SMEM_BYTES>>>(d_SHhi, d_SHlo, d_W2hi, d_W2lo,
                                                nullptr, d_IOUF, 2048, 512, 1);
    }
    level_point<<<(NNODE * (MM / 2) + 255) / 256, 256>>>(child, 0);

    // levels 1..7: fused [IOU(d) accum | HW(d-1)] GEMM
    for (int d = 1; d < DD; d++) {
        gather_level<<<(NNODE * (MM / 4) + 255) / 256, 256>>>(child, d);
        size_t hoff = (size_t)(OFFS + (d - 1) * NNODE) * MM;
        {
            dim3 grid(16, NNODE / 128);
            mma_gemm_dual<<<grid, 256, MMA_SMEM_BYTES>>>(
                d_SHhi, d_SHlo, d_Hhi + hoff, d_Hlo + hoff,
                d_W2hi, d_W2lo, d_WfThi, d_WfTlo,
                bfh, d_IOUF + (size_t)d * NNODE * 2048, d_HW + hoff);
        }
        level_point<<<(NNODE * (MM / 2) + 255) / 256, 256>>>(child, d);
    }

    // GRU input gates: single GEMM, N=3072 (wih_f/wih_b planes contiguous)
    gather_xs<<<(BB * SSEQ * (MM / 4) + 255) / 256, 256>>>(ctx);
    {
        dim3 grid(2 * G3M / 128, (BB * SSEQ) / 128);
        mma_gemm<<<grid, 256, MMA_SMEM_BYTES>>>(d_xshi, d_xslo, d_wihhi, d_wihlo,
                                                d_bih, d_xg, 2 * G3M, 512, 0);
    }

    // GRU recurrence
    {
        dim3 grid(48, 2);
        gru_persist<<<grid, 256, GRU_SMEM>>>(whh_f, whh_b, bhh_f, bhh_b, out);
    }
}

// round 11
// speedup vs baseline: 2.8920x; 1.0098x over previous
#include <cuda_runtime.h>
#include <cuda_bf16.h>
#include <math.h>
#include <cstdint>

// ---------------- problem constants ----------------
#define VV     32000
#define MM     512
#define NLEAF  16384
#define DD     8
#define NNODE  4096
#define KCH    4
#define BB     64
#define SSEQ   16
#define POOLSZ (1 + NLEAF + DD * NNODE)   // 49153
#define OFFS   (1 + NLEAF)                // 16385
#define G3M    (3 * MM)                   // 1536
#define NALL   (DD * NNODE)               // 32768

__device__ __forceinline__ float sigf(float x) { return 1.0f / (1.0f + expf(-x)); }

__device__ __forceinline__ uint32_t smem_u32(const void* p) {
    uint32_t a;
    asm("{ .reg .u64 t; cvta.to.shared.u64 t, %1; cvt.u32.u64 %0, t; }" : "=r"(a) : "l"(p));
    return a;
}

// split (x,y) into packed bf16x2 hi + bf16x2 lo (lower 16 bits = x)
__device__ __forceinline__ void splitpack(float x, float y, uint32_t& hi, uint32_t& lo) {
    uint32_t h;
    asm("cvt.rn.bf16x2.f32 %0, %1, %2;" : "=r"(h) : "f"(y), "f"(x));
    float hx = __uint_as_float(h << 16);
    float hy = __uint_as_float(h & 0xFFFF0000u);
    float rx = x - hx, ry = y - hy;
    asm("cvt.rn.bf16x2.f32 %0, %1, %2;" : "=r"(lo) : "f"(ry), "f"(rx));
    hi = h;
}

// unpack bf16x2 word -> float2
__device__ __forceinline__ float2 bf2f(uint32_t w) {
    __nv_bfloat162 b = *reinterpret_cast<__nv_bfloat162*>(&w);
    return __bfloat1622float2(b);
}

#define MMA_BF16(c, a0, a1, a2, a3, b0, b1) \
    asm volatile("mma.sync.aligned.m16n8k16.row.col.f32.bf16.bf16.f32 " \
        "{%0,%1,%2,%3}, {%4,%5,%6,%7}, {%8,%9}, {%0,%1,%2,%3};" \
        : "+f"((c)[0]), "+f"((c)[1]), "+f"((c)[2]), "+f"((c)[3]) \
        : "r"(a0), "r"(a1), "r"(a2), "r"(a3), "r"(b0), "r"(b1))

#define LDSM_X4(r0, r1, r2, r3, addr) \
    asm volatile("ldmatrix.sync.aligned.m8n8.x4.shared.b16 {%0,%1,%2,%3}, [%4];" \
        : "=r"(r0), "=r"(r1), "=r"(r2), "=r"(r3) : "r"(addr))

#define CP_ASYNC16(dst, src) \
    asm volatile("cp.async.cg.shared.global [%0], [%1], 16;" :: "r"(dst), "l"(src))
#define CP_COMMIT() asm volatile("cp.async.commit_group;")
#define CP_WAIT1()  asm volatile("cp.async.wait_group 1;")
#define CP_WAIT0()  asm volatile("cp.async.wait_group 0;")

// ---------------- device scratch ----------------
__device__ float g_c_pool[(size_t)POOLSZ * MM];
__device__ float g_HW[(size_t)POOLSZ * MM];         // only internal-node region used
__device__ float g_IOUFall[(size_t)NALL * 2048];
__device__ float g_biasbig[2048];
__device__ float g_bihcat[2 * G3M];
__device__ unsigned g_bar;
// bf16 split planes
__device__ __nv_bfloat16 g_W1hi[(size_t)2048 * MM];   // [Wioux|Wfx]^T
__device__ __nv_bfloat16 g_W1lo[(size_t)2048 * MM];
__device__ __nv_bfloat16 g_W2hi[(size_t)G3M * MM];    // Wiouh^T
__device__ __nv_bfloat16 g_W2lo[(size_t)G3M * MM];
__device__ __nv_bfloat16 g_WfThi[(size_t)MM * MM];
__device__ __nv_bfloat16 g_WfTlo[(size_t)MM * MM];
__device__ __nv_bfloat16 g_wihhi[2][(size_t)G3M * MM];
__device__ __nv_bfloat16 g_wihlo[2][(size_t)G3M * MM];
__device__ __nv_bfloat16 g_Xallhi[(size_t)NALL * MM];
__device__ __nv_bfloat16 g_Xalllo[(size_t)NALL * MM];
__device__ __nv_bfloat16 g_SUMHhi[(size_t)NNODE * MM];
__device__ __nv_bfloat16 g_SUMHlo[(size_t)NNODE * MM];
__device__ __nv_bfloat16 g_Hhi[(size_t)POOLSZ * MM];
__device__ __nv_bfloat16 g_Hlo[(size_t)POOLSZ * MM];
__device__ __nv_bfloat16 g_xshi[(size_t)BB * SSEQ * MM];
__device__ __nv_bfloat16 g_xslo[(size_t)BB * SSEQ * MM];
// GRU  (xg row-major [1024][3072]: dir-major within row)
__device__ float g_xg[(size_t)BB * SSEQ * 2 * G3M];
__device__ float g_hg[2][(size_t)BB * G3M];
__device__ float g_hst[2][(size_t)BB * MM];

// ---------------- shared GEMM body ----------------
#define RS 20
#define PLANE 2560
#define STG_BYTES 40960
#define MMA_SMEM_BYTES (2 * STG_BYTES)

__device__ __forceinline__ void gemm_body(
    const uint32_t* pA0, const uint32_t* pA1, const uint32_t* pB0, const uint32_t* pB1,
    int mbase, int nbase, int K, const float* bias, float* C, int ldC, int accum,
    uint32_t smb) {
    const int tid = threadIdx.x;
    const int w = tid >> 5, lane = tid & 31;
    const int warpM = w & 1, warpN = w >> 1;
    const int Kw = K >> 1;
    const int nCh = Kw >> 4;

    float acc[4][4][4];
#pragma unroll
    for (int i = 0; i < 4; i++)
#pragma unroll
        for (int j = 0; j < 4; j++)
#pragma unroll
            for (int q = 0; q < 4; q++) acc[i][j][q] = 0.f;

    const int lrow = lane & 15, lcol = lane >> 4;
    uint32_t aAddr[4], bAddr[2];
#pragma unroll
    for (int i = 0; i < 4; i++)
        aAddr[i] = smb + (uint32_t)(((warpM * 64 + i * 16 + lrow) * RS + lcol * 4) * 4);
#pragma unroll
    for (int jp = 0; jp < 2; jp++)
        bAddr[jp] = smb + (uint32_t)(2 * PLANE * 4 + ((warpN * 32 + jp * 16 + lrow) * RS + lcol * 4) * 4);

#define ISSUE(tw) do {                                                            \
    const int kw0 = (tw) * 16;                                                    \
    const uint32_t sb = smb + (uint32_t)(((tw) & 1) * STG_BYTES);                 \
    _Pragma("unroll")                                                             \
    for (int q = 0; q < 8; q++) {                                                 \
        const int pl = q >> 1;                                                    \
        int s = tid + (q & 1) * 256;                                              \
        int r = s >> 2, sg = s & 3;                                               \
        const uint32_t* src = (pl == 0 ? pA0 : pl == 1 ? pA1 : pl == 2 ? pB0 : pB1) \
            + (size_t)((pl < 2 ? mbase : nbase) + r) * Kw + kw0 + sg * 4;         \
        uint32_t dst = sb + (uint32_t)((pl * PLANE + r * RS + sg * 4) * 4);       \
        CP_ASYNC16(dst, src);                                                     \
    }                                                                             \
    CP_COMMIT(); } while (0)

    ISSUE(0);
    if (nCh > 1) ISSUE(1);

    for (int t = 0; t < nCh; t++) {
        if (t + 1 < nCh) CP_WAIT1(); else CP_WAIT0();
        __syncthreads();

        const uint32_t so = (uint32_t)((t & 1) * STG_BYTES);
#pragma unroll
        for (int ks = 0; ks < 2; ks++) {
            const uint32_t ko = so + ks * 32;
            uint32_t Bh[4][2], Bl[4][2];
#pragma unroll
            for (int jp = 0; jp < 2; jp++) {
                LDSM_X4(Bh[2 * jp][0], Bh[2 * jp + 1][0], Bh[2 * jp][1], Bh[2 * jp + 1][1],
                        bAddr[jp] + ko);
                LDSM_X4(Bl[2 * jp][0], Bl[2 * jp + 1][0], Bl[2 * jp][1], Bl[2 * jp + 1][1],
                        bAddr[jp] + PLANE * 4 + ko);
            }
#pragma unroll
            for (int i = 0; i < 4; i++) {
                uint32_t Ah0, Ah1, Ah2, Ah3, Al0, Al1, Al2, Al3;
                LDSM_X4(Ah0, Ah1, Ah2, Ah3, aAddr[i] + ko);
                LDSM_X4(Al0, Al1, Al2, Al3, aAddr[i] + PLANE * 4 + ko);
#pragma unroll
                for (int j = 0; j < 4; j++) {
                    MMA_BF16(acc[i][j], Ah0, Ah1, Ah2, Ah3, Bh[j][0], Bh[j][1]);
                    MMA_BF16(acc[i][j], Ah0, Ah1, Ah2, Ah3, Bl[j][0], Bl[j][1]);
                    MMA_BF16(acc[i][j], Al0, Al1, Al2, Al3, Bh[j][0], Bh[j][1]);
                }
            }
        }
        if (t + 2 < nCh) {
            __syncthreads();
            ISSUE(t + 2);
        }
    }
#undef ISSUE

    const int g = lane >> 2, tg = lane & 3;
#pragma unroll
    for (int i = 0; i < 4; i++) {
#pragma unroll
        for (int j = 0; j < 4; j++) {
            int row = mbase + warpM * 64 + i * 16 + g;
            int col = nbase + warpN * 32 + j * 8 + tg * 2;
            float* c0p = C + (size_t)row * ldC + col;
            float* c1p = C + (size_t)(row + 8) * ldC + col;
            float a0 = acc[i][j][0], a1 = acc[i][j][1];
            float a2 = acc[i][j][2], a3 = acc[i][j][3];
            if (accum) {
                float2 e0 = *(float2*)c0p, e1 = *(float2*)c1p;
                a0 += e0.x; a1 += e0.y; a2 += e1.x; a3 += e1.y;
            } else {
                float b0v = bias[col], b1v = bias[col + 1];
                a0 += b0v; a1 += b1v; a2 += b0v; a3 += b1v;
            }
            *(float2*)c0p = make_float2(a0, a1);
            *(float2*)c1p = make_float2(a2, a3);
        }
    }
}

__global__ void __launch_bounds__(256)
mma_gemm(const __nv_bfloat16* __restrict__ Ahi, const __nv_bfloat16* __restrict__ Alo,
         const __nv_bfloat16* __restrict__ Bhi, const __nv_bfloat16* __restrict__ Blo,
         const float* __restrict__ bias, float* __restrict__ C, int ldC, int K, int accum) {
    extern __shared__ uint32_t sm[];
    gemm_body((const uint32_t*)Ahi, (const uint32_t*)Alo,
              (const uint32_t*)Bhi, (const uint32_t*)Blo,
              blockIdx.y * 128, blockIdx.x * 128, K, bias, C, ldC, accum, smem_u32(sm));
}

__global__ void __launch_bounds__(256)
mma_gemm_dual(const __nv_bfloat16* __restrict__ A1hi, const __nv_bfloat16* __restrict__ A1lo,
              const __nv_bfloat16* __restrict__ A2hi, const __nv_bfloat16* __restrict__ A2lo,
              const __nv_bfloat16* __restrict__ B1hi, const __nv_bfloat16* __restrict__ B1lo,
              const __nv_bfloat16* __restrict__ B2hi, const __nv_bfloat16* __restrict__ B2lo,
              const float* __restrict__ bias2, float* __restrict__ C1, float* __restrict__ C2) {
    extern __shared__ uint32_t sm[];
    if (blockIdx.x < 12) {
        gemm_body((const uint32_t*)A1hi, (const uint32_t*)A1lo,
                  (const uint32_t*)B1hi, (const uint32_t*)B1lo,
                  blockIdx.y * 128, blockIdx.x * 128, 512, nullptr, C1, 2048, 1, smem_u32(sm));
    } else {
        gemm_body((const uint32_t*)A2hi, (const uint32_t*)A2lo,
                  (const uint32_t*)B2hi, (const uint32_t*)B2lo,
                  blockIdx.y * 128, (blockIdx.x - 12) * 128, 512, bias2, C2, 512, 0, smem_u32(sm));
    }
}

// ---------------- prep: tiled transpose+split (coalesced both sides) ----------------
__global__ void __launch_bounds__(256)
transp_split(const float* __restrict__ srcA, const float* __restrict__ srcB,
             int ldA, int ldB, int nsplit, int K,
             __nv_bfloat16* __restrict__ dsthi, __nv_bfloat16* __restrict__ dstlo) {
    __shared__ float tile[32][33];
    const int n0 = blockIdx.x * 32, k0 = blockIdx.y * 32;
    const int tx = threadIdx.x, ty = threadIdx.y;
    const int n = n0 + tx;
    const float* src = (n0 < nsplit) ? srcA : srcB;
    const int ld = (n0 < nsplit) ? ldA : ldB;
    const int col = (n0 < nsplit) ? n : n - nsplit;
#pragma unroll
    for (int i = 0; i < 4; i++) {
        int k = k0 + ty + i * 8;
        tile[ty + i * 8][tx] = src[(size_t)k * ld + col];
    }
    __syncthreads();
    const int Kw = K >> 1;
#pragma unroll
    for (int j = 0; j < 2; j++) {
        int lin = j * 256 + ty * 32 + tx;
        int nl = lin >> 4, kp = lin & 15;
        float v0 = tile[kp * 2][nl], v1 = tile[kp * 2 + 1][nl];
        uint32_t h, l; splitpack(v0, v1, h, l);
        size_t wd = (size_t)(n0 + nl) * Kw + (k0 >> 1) + kp;
        ((uint32_t*)dsthi)[wd] = h;
        ((uint32_t*)dstlo)[wd] = l;
    }
}

// wih split (already coalesced) + biases
__global__ void prep_copy(const float* __restrict__ wih_f, const float* __restrict__ wih_b,
                          const float* __restrict__ bioux, const float* __restrict__ biouh,
                          const float* __restrict__ bfx,
                          const float* __restrict__ bih_f, const float* __restrict__ bih_b) {
    int idx = blockIdx.x * blockDim.x + threadIdx.x;
    const int T2 = G3M * (MM / 2);
    if (idx < 2 * T2) {
        int dir = idx / T2, j = idx % T2;
        const float* wsrc = dir ? wih_b : wih_f;
        float v0 = wsrc[2 * j], v1 = wsrc[2 * j + 1];
        uint32_t h, l; splitpack(v0, v1, h, l);
        ((uint32_t*)g_wihhi[dir])[j] = h;
        ((uint32_t*)g_wihlo[dir])[j] = l;
    }
    if (idx < 2048)
        g_biasbig[idx] = (idx < G3M) ? (bioux[idx] + biouh[idx]) : bfx[idx - G3M];
    if (idx < 2 * G3M)
        g_bihcat[idx] = (idx < G3M) ? bih_f[idx] : bih_b[idx - G3M];
}

// ---------------- init ----------------
__global__ void init_leaf(const float* __restrict__ embed, const int* __restrict__ leaf_idx) {
    int idx = blockIdx.x * blockDim.x + threadIdx.x;
    if (idx >= NLEAF * (MM / 4)) return;
    int n = idx >> 7, m = (idx & 127) * 4;
    int w = leaf_idx[n];
    float4 v = *(const float4*)(embed + (size_t)w * MM + m);
    uint32_t h0, l0, h1, l1;
    splitpack(v.x, v.y, h0, l0);
    splitpack(v.z, v.w, h1, l1);
    size_t wrd = ((size_t)(1 + n) * MM + m) >> 1;
    ((uint32_t*)g_Hhi)[wrd] = h0; ((uint32_t*)g_Hhi)[wrd + 1] = h1;
    ((uint32_t*)g_Hlo)[wrd] = l0; ((uint32_t*)g_Hlo)[wrd + 1] = l1;
}

__global__ void init_misc() {
    int idx = blockIdx.x * blockDim.x + threadIdx.x;
    if (idx == 0) g_bar = 0u;
    if (idx < MM / 2) {                 // zero-slot h planes (bf16 zeros)
        ((uint32_t*)g_Hhi)[idx] = 0u;
        ((uint32_t*)g_Hlo)[idx] = 0u;
    }
    if (idx < 2 * BB * MM) (&g_hst[0][0])[idx] = 0.f;
}

// ---------------- gather x embeddings for ALL levels ----------------
__global__ void gather_x_all(const float* __restrict__ embed, const int* __restrict__ lwi) {
    int idx = blockIdx.x * blockDim.x + threadIdx.x;
    if (idx >= NALL * (MM / 4)) return;
    int ng = idx >> 7, m = (idx & 127) * 4;
    int w = lwi[ng];
    float4 x = *(const float4*)(embed + (size_t)w * MM + m);
    uint32_t h0, l0, h1, l1;
    splitpack(x.x, x.y, h0, l0);
    splitpack(x.z, x.w, h1, l1);
    size_t wrd = ((size_t)ng * MM + m) >> 1;
    ((uint32_t*)g_Xallhi)[wrd] = h0; ((uint32_t*)g_Xallhi)[wrd + 1] = h1;
    ((uint32_t*)g_Xalllo)[wrd] = l0; ((uint32_t*)g_Xalllo)[wrd + 1] = l1;
}

// ---------------- per-level gather: sum of child h (from bf16 planes) ----------------
__global__ void gather_level(const int* __restrict__ child, int d) {
    int idx = blockIdx.x * blockDim.x + threadIdx.x;
    if (idx >= NNODE * (MM / 4)) return;
    int n = idx >> 7, m = (idx & 127) * 4;
    float4 s = make_float4(0.f, 0.f, 0.f, 0.f);
    const int* ch = child + ((size_t)d * NNODE + n) * KCH;
#pragma unroll
    for (int k = 0; k < KCH; k++) {
        int ci = ch[k];
        size_t wrd = ((size_t)ci * MM + m) >> 1;
        uint2 hw = *(const uint2*)((const uint32_t*)g_Hhi + wrd);
        uint2 lw = *(const uint2*)((const uint32_t*)g_Hlo + wrd);
        float2 a0 = bf2f(hw.x), b0 = bf2f(lw.x);
        float2 a1 = bf2f(hw.y), b1 = bf2f(lw.y);
        s.x += a0.x + b0.x; s.y += a0.y + b0.y;
        s.z += a1.x + b1.x; s.w += a1.y + b1.y;
    }
    uint32_t h0, l0, h1, l1;
    splitpack(s.x, s.y, h0, l0);
    splitpack(s.z, s.w, h1, l1);
    size_t wrd = ((size_t)n * MM + m) >> 1;
    ((uint32_t*)g_SUMHhi)[wrd] = h0; ((uint32_t*)g_SUMHhi)[wrd + 1] = h1;
    ((uint32_t*)g_SUMHlo)[wrd] = l0; ((uint32_t*)g_SUMHlo)[wrd + 1] = l1;
}

// ---------------- level pointwise ----------------
__global__ void level_point(const int* __restrict__ child, int d) {
    int idx = blockIdx.x * blockDim.x + threadIdx.x;
    if (idx >= NNODE * (MM / 2)) return;
    int n = idx >> 8, j = idx & 255;
    int m = 2 * j;
    const float* row = g_IOUFall + (size_t)(d * NNODE + n) * 2048;
    float2 iv = *(const float2*)(row + m);
    float2 ov = *(const float2*)(row + MM + m);
    float2 uv = *(const float2*)(row + 2 * MM + m);
    float2 fx = *(const float2*)(row + 3 * MM + m);
    float c0 = sigf(iv.x) * tanhf(uv.x);
    float c1 = sigf(iv.y) * tanhf(uv.y);
    const int* ch = child + ((size_t)d * NNODE + n) * KCH;
#pragma unroll
    for (int k = 0; k < KCH; k++) {
        int ci = ch[k];
        if (ci > NLEAF) {
            float2 hw = *(const float2*)(g_HW + (size_t)ci * MM + m);
            float2 cc = *(const float2*)(g_c_pool + (size_t)ci * MM + m);
            c0 += sigf(fx.x + hw.x) * cc.x;
            c1 += sigf(fx.y + hw.y) * cc.y;
        }
    }
    float h0 = sigf(ov.x) * tanhf(c0);
    float h1 = sigf(ov.y) * tanhf(c1);
    size_t slot = (size_t)(OFFS + d * NNODE + n) * MM + m;
    *(float2*)(g_c_pool + slot) = make_float2(c0, c1);
    uint32_t sh, sl; splitpack(h0, h1, sh, sl);
    ((uint32_t*)g_Hhi)[slot >> 1] = sh;
    ((uint32_t*)g_Hlo)[slot >> 1] = sl;
}

// ---------------- GRU ----------------
__global__ void gather_xs(const int* __restrict__ ctx) {
    int idx = blockIdx.x * blockDim.x + threadIdx.x;
    if (idx >= BB * SSEQ * (MM / 4)) return;
    int rowI = idx >> 7, m = (idx & 127) * 4;
    int p = ctx[rowI];
    size_t swrd = ((size_t)p * MM + m) >> 1;
    uint2 hw = *(const uint2*)((const uint32_t*)g_Hhi + swrd);
    uint2 lw = *(const uint2*)((const uint32_t*)g_Hlo + swrd);
    float2 a0 = bf2f(hw.x), b0 = bf2f(lw.x);
    float2 a1 = bf2f(hw.y), b1 = bf2f(lw.y);
    uint32_t h0, l0, h1, l1;
    splitpack(a0.x + b0.x, a0.y + b0.y, h0, l0);
    splitpack(a1.x + b1.x, a1.y + b1.y, h1, l1);
    size_t wrd = ((size_t)rowI * MM + m) >> 1;
    ((uint32_t*)g_xshi)[wrd] = h0; ((uint32_t*)g_xshi)[wrd + 1] = h1;
    ((uint32_t*)g_xslo)[wrd] = l0; ((uint32_t*)g_xslo)[wrd + 1] = l1;
}

#define GNB 96
#define HS_STR 516
__device__ __forceinline__ void gridbar(unsigned gen) {
    __syncthreads();
    if (threadIdx.x == 0) {
        __threadfence();
        atomicAdd(&g_bar, 1u);
        while (atomicAdd(&g_bar, 0u) < gen * GNB) { __nanosleep(64); }
        __threadfence();
    }
    __syncthreads();
}

__global__ void __launch_bounds__(256) gru_persist(const float* __restrict__ whh_f,
                                                   const float* __restrict__ whh_b,
                                                   const float* __restrict__ bhh_f,
                                                   const float* __restrict__ bhh_b,
                                                   float* __restrict__ out) {
    extern __shared__ float sh[];
    float* Hs = sh;                     // 64 x HS_STR
    float* Ws = sh + 64 * HS_STR;       // k-major [512][32]
    const int dir = blockIdx.y;
    const int n0 = blockIdx.x * 32;
    const int tid = threadIdx.x;
    const int bid = blockIdx.y * 48 + blockIdx.x;
    const float* whh = dir ? whh_b : whh_f;
    const float* bhh = dir ? bhh_b : bhh_f;

    // W tile once, k-major: Ws[k*32 + col] = whh[(n0+col)*MM + k]
    for (int i = tid; i < 32 * 512; i += 256) {
        int k = i & 511, col = i >> 9;
        Ws[k * 32 + col] = whh[(size_t)(n0 + col) * MM + k];
    }
    const int cg = tid & 7, r = tid >> 3;
    float bv[4];
#pragma unroll
    for (int c = 0; c < 4; c++) bv[c] = bhh[n0 + cg * 4 + c];

    unsigned gen = 0;
    for (int t = 0; t < SSEQ; t++) {
        __syncthreads();
        const float* H = g_hst[dir];
        for (int i = tid; i < 64 * 512; i += 256) Hs[(i >> 9) * HS_STR + (i & 511)] = H[i];
        __syncthreads();
        int row0 = 2 * r, row1 = row0 + 1;
        float acc0[4] = {0.f, 0.f, 0.f, 0.f};
        float acc1[4] = {0.f, 0.f, 0.f, 0.f};
        for (int k = 0; k < 512; k += 4) {
            float4 ha = *(float4*)&Hs[row0 * HS_STR + k];
            float4 hb = *(float4*)&Hs[row1 * HS_STR + k];
#pragma unroll
            for (int i = 0; i < 4; i++) {
                float4 wv = *(float4*)&Ws[(k + i) * 32 + cg * 4];
                float a = (&ha.x)[i], b = (&hb.x)[i];
                acc0[0] += a * wv.x; acc0[1] += a * wv.y; acc0[2] += a * wv.z; acc0[3] += a * wv.w;
                acc1[0] += b * wv.x; acc1[1] += b * wv.y; acc1[2] += b * wv.z; acc1[3] += b * wv.w;
            }
        }
#pragma unroll
        for (int c = 0; c < 4; c++) {
            int n = n0 + cg * 4 + c;
            g_hg[dir][(size_t)row0 * G3M + n] = acc0[c] + bv[c];
            g_hg[dir][(size_t)row1 * G3M + n] = acc1[c] + bv[c];
        }
        gridbar(++gen);
        for (int e = bid * 256 + tid; e < 2 * BB * MM; e += GNB * 256) {
            int dd = e >> 15;
            int rem = e & 32767;
            int b = rem >> 9, j = rem & 511;
            int pos = dd ? (SSEQ - 1 - t) : t;
            const float* xrow = g_xg + (size_t)(b * SSEQ + pos) * (2 * G3M) + dd * G3M;
            const float* hrow = g_hg[dd] + (size_t)b * G3M;
            float rr_ = sigf(xrow[j] + hrow[j]);
            float zz = sigf(xrow[MM + j] + hrow[MM + j]);
            float nn = tanhf(xrow[2 * MM + j] + rr_ * hrow[2 * MM + j]);
            float hp = g_hst[dd][b * MM + j];
            float hn = (1.f - zz) * nn + zz * hp;
            g_hst[dd][b * MM + j] = hn;
            float* op = out + (size_t)(b * SSEQ + pos) * MM + j;
            if (t < 8) *op = hn; else *op += hn;   // first touch at step min(p,15-p) < 8
        }
        gridbar(++gen);
    }
}

// ---------------- host launch ----------------
extern "C" void kernel_launch(void* const* d_in, const int* in_sizes, int n_in,
                              void* d_out, int out_size) {
    const float* embed   = (const float*)d_in[0];
    const float* Wioux   = (const float*)d_in[1];
    const float* bioux   = (const float*)d_in[2];
    const float* Wiouh   = (const float*)d_in[3];
    const float* biouh   = (const float*)d_in[4];
    const float* Wfx     = (const float*)d_in[5];
    const float* bfx     = (const float*)d_in[6];
    const float* Wfh     = (const float*)d_in[7];
    const float* bfh     = (const float*)d_in[8];
    const float* wih_f   = (const float*)d_in[9];
    const float* whh_f   = (const float*)d_in[10];
    const float* bih_f   = (const float*)d_in[11];
    const float* bhh_f   = (const float*)d_in[12];
    const float* wih_b   = (const float*)d_in[13];
    const float* whh_b   = (const float*)d_in[14];
    const float* bih_b   = (const float*)d_in[15];
    const float* bhh_b   = (const float*)d_in[16];

    const int* leaf_idx = nullptr; const int* level_idx = nullptr;
    const int* child = nullptr; const int* ctx = nullptr;
    for (int i = 17; i < n_in; i++) {
        int sz = in_sizes[i];
        if (sz == NLEAF)                 leaf_idx  = (const int*)d_in[i];
        else if (sz == DD * NNODE)       level_idx = (const int*)d_in[i];
        else if (sz == DD * NNODE * KCH) child     = (const int*)d_in[i];
        else if (sz == BB * SSEQ)        ctx       = (const int*)d_in[i];
    }

    float* out = (float*)d_out;

    const size_t GRU_SMEM = (64 * HS_STR + 512 * 32) * sizeof(float);
    cudaFuncSetAttribute(mma_gemm, cudaFuncAttributeMaxDynamicSharedMemorySize, MMA_SMEM_BYTES);
    cudaFuncSetAttribute(mma_gemm_dual, cudaFuncAttributeMaxDynamicSharedMemorySize, MMA_SMEM_BYTES);
    cudaFuncSetAttribute(gru_persist, cudaFuncAttributeMaxDynamicSharedMemorySize, (int)GRU_SMEM);

    __nv_bfloat16* d_Hhi;   cudaGetSymbolAddress((void**)&d_Hhi, g_Hhi);
    __nv_bfloat16* d_Hlo;   cudaGetSymbolAddress((void**)&d_Hlo, g_Hlo);
    __nv_bfloat16* d_Xhi;   cudaGetSymbolAddress((void**)&d_Xhi, g_Xallhi);
    __nv_bfloat16* d_Xlo;   cudaGetSymbolAddress((void**)&d_Xlo, g_Xalllo);
    __nv_bfloat16* d_SHhi;  cudaGetSymbolAddress((void**)&d_SHhi, g_SUMHhi);
    __nv_bfloat16* d_SHlo;  cudaGetSymbolAddress((void**)&d_SHlo, g_SUMHlo);
    __nv_bfloat16* d_W1hi;  cudaGetSymbolAddress((void**)&d_W1hi, g_W1hi);
    __nv_bfloat16* d_W1lo;  cudaGetSymbolAddress((void**)&d_W1lo, g_W1lo);
    __nv_bfloat16* d_W2hi;  cudaGetSymbolAddress((void**)&d_W2hi, g_W2hi);
    __nv_bfloat16* d_W2lo;  cudaGetSymbolAddress((void**)&d_W2lo, g_W2lo);
    __nv_bfloat16* d_WfThi; cudaGetSymbolAddress((void**)&d_WfThi, g_WfThi);
    __nv_bfloat16* d_WfTlo; cudaGetSymbolAddress((void**)&d_WfTlo, g_WfTlo);
    __nv_bfloat16* d_wihhi; cudaGetSymbolAddress((void**)&d_wihhi, g_wihhi);
    __nv_bfloat16* d_wihlo; cudaGetSymbolAddress((void**)&d_wihlo, g_wihlo);
    __nv_bfloat16* d_xshi;  cudaGetSymbolAddress((void**)&d_xshi, g_xshi);
    __nv_bfloat16* d_xslo;  cudaGetSymbolAddress((void**)&d_xslo, g_xslo);
    float* d_IOUF;   cudaGetSymbolAddress((void**)&d_IOUF, g_IOUFall);
    float* d_HW;     cudaGetSymbolAddress((void**)&d_HW, g_HW);
    float* d_bb;     cudaGetSymbolAddress((void**)&d_bb, g_biasbig);
    float* d_bih;    cudaGetSymbolAddress((void**)&d_bih, g_bihcat);
    float* d_xg;     cudaGetSymbolAddress((void**)&d_xg, g_xg);

    // prep + init (tiled transposes: coalesced reads AND writes)
    {
        dim3 blk(32, 8);
        transp_split<<<dim3(2048 / 32, 512 / 32), blk>>>(Wioux, Wfx, G3M, MM, G3M, 512,
                                                         d_W1hi, d_W1lo);
        transp_split<<<dim3(G3M / 32, 512 / 32), blk>>>(Wiouh, nullptr, G3M, 0, G3M, 512,
                                                        d_W2hi, d_W2lo);
        transp_split<<<dim3(MM / 32, 512 / 32), blk>>>(Wfh, nullptr, MM, 0, MM, 512,
                                                       d_WfThi, d_WfTlo);
    }
    prep_copy<<<(2 * G3M * (MM / 2) + 255) / 256, 256>>>(wih_f, wih_b, bioux, biouh, bfx,
                                                         bih_f, bih_b);
    init_leaf<<<(NLEAF * (MM / 4) + 255) / 256, 256>>>(embed, leaf_idx);
    init_misc<<<(2 * BB * MM + 255) / 256, 256>>>();
    gather_x_all<<<(NALL * (MM / 4) + 255) / 256, 256>>>(embed, level_idx);

    // upfront: IOUF_all = X_all @ [Wioux|Wfx]^T + biasbig
    {
        dim3 grid(2048 / 128, NALL / 128);
        mma_gemm<<<grid, 256, MMA_SMEM_BYTES>>>(d_Xhi, d_Xlo, d_W1hi, d_W1lo,
                                                d_bb, d_IOUF, 2048, 512, 0);
    }

    // level 0: IOU accum only
    gather_level<<<(NNODE * (MM / 4) + 255) / 256, 256>>>(child, 0);
    {
        dim3 grid(G3M / 128, NNODE / 128);
        mma_gemm<<<grid, 256, MMA_SMEM_BYTES>>>(d_SHhi, d_SHlo, d_W2hi, d_W2lo,
                                                nullptr, d_IOUF, 2048, 512, 1);
    }
    level_point<<<(NNODE * (MM / 2) + 255) / 256, 256>>>(child, 0);

    // levels 1..7: fused [IOU(d) accum | HW(d-1)]
    for (int d = 1; d < DD; d++) {
        gather_level<<<(NNODE * (MM / 4) + 255) / 256, 256>>>(child, d);
        size_t hoff = (size_t)(OFFS + (d - 1) * NNODE) * MM;
        {
            dim3 grid(16, NNODE / 128);
            mma_gemm_dual<<<grid, 256, MMA_SMEM_BYTES>>>(
                d_SHhi, d_SHlo, d_Hhi + hoff, d_Hlo + hoff,
                d_W2hi, d_W2lo, d_WfThi, d_WfTlo,
                bfh, d_IOUF + (size_t)d * NNODE * 2048, d_HW + hoff);
        }
        level_point<<<(NNODE * (MM / 2) + 255) / 256, 256>>>(child, d);
    }

    // GRU input gates: single GEMM, N=3072
    gather_xs<<<(BB * SSEQ * (MM / 4) + 255) / 256, 256>>>(ctx);
    {
        dim3 grid(2 * G3M / 128, (BB * SSEQ) / 128);
        mma_gemm<<<grid, 256, MMA_SMEM_BYTES>>>(d_xshi, d_xslo, d_wihhi, d_wihlo,
                                                d_bih, d_xg, 2 * G3M, 512, 0);
    }

    // GRU recurrence
    {
        dim3 grid(48, 2);
        gru_persist<<<grid, 256, GRU_SMEM>>>(whh_f, whh_b, bhh_f, bhh_b, out);
    }
}

// round 12
// speedup vs baseline: 4.6351x; 1.6027x over previous
#include <cuda_runtime.h>
#include <cuda_fp16.h>
#include <math.h>
#include <cstdint>

// ---------------- problem constants ----------------
#define VV     32000
#define MM     512
#define NLEAF  16384
#define DD     8
#define NNODE  4096
#define KCH    4
#define BB     64
#define SSEQ   16
#define POOLSZ (1 + NLEAF + DD * NNODE)   // 49153
#define OFFS   (1 + NLEAF)                // 16385
#define G3M    (3 * MM)                   // 1536
#define NALL   (DD * NNODE)               // 32768

__device__ __forceinline__ float sigf(float x) { return 1.0f / (1.0f + expf(-x)); }

__device__ __forceinline__ uint32_t smem_u32(const void* p) {
    uint32_t a;
    asm("{ .reg .u64 t; cvta.to.shared.u64 t, %1; cvt.u32.u64 %0, t; }" : "=r"(a) : "l"(p));
    return a;
}

// pack two floats -> fp16x2 word (low = x)
__device__ __forceinline__ uint32_t f2h(float x, float y) {
    __half2 h = __floats2half2_rn(x, y);
    return *reinterpret_cast<uint32_t*>(&h);
}
__device__ __forceinline__ float2 h2f(uint32_t w) {
    __half2 h = *reinterpret_cast<__half2*>(&w);
    return __half22float2(h);
}
// hi + residual lo (both fp16x2) for accurate activation storage
__device__ __forceinline__ void packres(float x, float y, uint32_t& hi, uint32_t& lo) {
    hi = f2h(x, y);
    float2 f = h2f(hi);
    lo = f2h(x - f.x, y - f.y);
}

#define MMA_F16(c, a0, a1, a2, a3, b0, b1) \
    asm volatile("mma.sync.aligned.m16n8k16.row.col.f32.f16.f16.f32 " \
        "{%0,%1,%2,%3}, {%4,%5,%6,%7}, {%8,%9}, {%0,%1,%2,%3};" \
        : "+f"((c)[0]), "+f"((c)[1]), "+f"((c)[2]), "+f"((c)[3]) \
        : "r"(a0), "r"(a1), "r"(a2), "r"(a3), "r"(b0), "r"(b1))

#define LDSM_X4(r0, r1, r2, r3, addr) \
    asm volatile("ldmatrix.sync.aligned.m8n8.x4.shared.b16 {%0,%1,%2,%3}, [%4];" \
        : "=r"(r0), "=r"(r1), "=r"(r2), "=r"(r3) : "r"(addr))

#define CP_ASYNC16(dst, src) \
    asm volatile("cp.async.cg.shared.global [%0], [%1], 16;" :: "r"(dst), "l"(src))
#define CP_COMMIT() asm volatile("cp.async.commit_group;")
#define CP_WAIT1()  asm volatile("cp.async.wait_group 1;")
#define CP_WAIT0()  asm volatile("cp.async.wait_group 0;")

// ---------------- device scratch ----------------
__device__ float g_c_pool[(size_t)POOLSZ * MM];
__device__ float g_HW[(size_t)POOLSZ * MM];
__device__ float g_IOUFall[(size_t)NALL * 2048];
__device__ float g_biasbig[2048];
__device__ float g_bihcat[2 * G3M];
__device__ unsigned g_bar;
// fp16 planes (weights/GEMM operands single; pool h keeps residual for reconstruct)
__device__ __half g_W1[(size_t)2048 * MM];
__device__ __half g_W2[(size_t)G3M * MM];
__device__ __half g_WfT[(size_t)MM * MM];
__device__ __half g_wih[2][(size_t)G3M * MM];
__device__ __half g_Xall[(size_t)NALL * MM];
__device__ __half g_SUMH[(size_t)NNODE * MM];
__device__ __half g_Hhi[(size_t)POOLSZ * MM];
__device__ __half g_Hlo[(size_t)POOLSZ * MM];
__device__ __half g_xs[(size_t)BB * SSEQ * MM];
// GRU (fp32, unchanged from R11)
__device__ float g_xg[(size_t)BB * SSEQ * 2 * G3M];
__device__ float g_hg[2][(size_t)BB * G3M];
__device__ float g_hst[2][(size_t)BB * MM];

// ---------------- fp16 1-pass mma GEMM ----------------
#define RS 20              // b32 words per 32-fp16 row (16 data + 4 pad)
#define PLANE 2560         // words per plane (128 rows * RS)
#define STG_BYTES 20480    // 2 planes (A, B)
#define MMA_SMEM_BYTES (2 * STG_BYTES)

__device__ __forceinline__ void gemm_body(
    const uint32_t* pA, const uint32_t* pB,
    int mbase, int nbase, int K, const float* bias, float* C, int ldC, int accum,
    uint32_t smb) {
    const int tid = threadIdx.x;
    const int w = tid >> 5, lane = tid & 31;
    const int warpM = w & 1, warpN = w >> 1;
    const int Kw = K >> 1;
    const int nCh = Kw >> 4;

    float acc[4][4][4];
#pragma unroll
    for (int i = 0; i < 4; i++)
#pragma unroll
        for (int j = 0; j < 4; j++)
#pragma unroll
            for (int q = 0; q < 4; q++) acc[i][j][q] = 0.f;

    const int lrow = lane & 15, lcol = lane >> 4;
    uint32_t aAddr[4], bAddr[2];
#pragma unroll
    for (int i = 0; i < 4; i++)
        aAddr[i] = smb + (uint32_t)(((warpM * 64 + i * 16 + lrow) * RS + lcol * 4) * 4);
#pragma unroll
    for (int jp = 0; jp < 2; jp++)
        bAddr[jp] = smb + (uint32_t)(PLANE * 4 + ((warpN * 32 + jp * 16 + lrow) * RS + lcol * 4) * 4);

#define ISSUE(tw) do {                                                            \
    const int kw0 = (tw) * 16;                                                    \
    const uint32_t sb = smb + (uint32_t)(((tw) & 1) * STG_BYTES);                 \
    _Pragma("unroll")                                                             \
    for (int q = 0; q < 4; q++) {                                                 \
        const int pl = q >> 1;                                                    \
        int s = tid + (q & 1) * 256;                                              \
        int r = s >> 2, sg = s & 3;                                               \
        const uint32_t* src = (pl == 0 ? pA : pB)                                 \
            + (size_t)((pl == 0 ? mbase : nbase) + r) * Kw + kw0 + sg * 4;        \
        uint32_t dst = sb + (uint32_t)((pl * PLANE + r * RS + sg * 4) * 4);       \
        CP_ASYNC16(dst, src);                                                     \
    }                                                                             \
    CP_COMMIT(); } while (0)

    ISSUE(0);
    if (nCh > 1) ISSUE(1);

    for (int t = 0; t < nCh; t++) {
        if (t + 1 < nCh) CP_WAIT1(); else CP_WAIT0();
        __syncthreads();

        const uint32_t so = (uint32_t)((t & 1) * STG_BYTES);
#pragma unroll
        for (int ks = 0; ks < 2; ks++) {
            const uint32_t ko = so + ks * 32;
            uint32_t Bf[4][2];
#pragma unroll
            for (int jp = 0; jp < 2; jp++) {
                LDSM_X4(Bf[2 * jp][0], Bf[2 * jp + 1][0], Bf[2 * jp][1], Bf[2 * jp + 1][1],
                        bAddr[jp] + ko);
            }
#pragma unroll
            for (int i = 0; i < 4; i++) {
                uint32_t A0, A1, A2, A3;
                LDSM_X4(A0, A1, A2, A3, aAddr[i] + ko);
#pragma unroll
                for (int j = 0; j < 4; j++)
                    MMA_F16(acc[i][j], A0, A1, A2, A3, Bf[j][0], Bf[j][1]);
            }
        }
        if (t + 2 < nCh) {
            __syncthreads();
            ISSUE(t + 2);
        }
    }
#undef ISSUE

    const int g = lane >> 2, tg = lane & 3;
#pragma unroll
    for (int i = 0; i < 4; i++) {
#pragma unroll
        for (int j = 0; j < 4; j++) {
            int row = mbase + warpM * 64 + i * 16 + g;
            int col = nbase + warpN * 32 + j * 8 + tg * 2;
            float* c0p = C + (size_t)row * ldC + col;
            float* c1p = C + (size_t)(row + 8) * ldC + col;
            float a0 = acc[i][j][0], a1 = acc[i][j][1];
            float a2 = acc[i][j][2], a3 = acc[i][j][3];
            if (accum) {
                float2 e0 = *(float2*)c0p, e1 = *(float2*)c1p;
                a0 += e0.x; a1 += e0.y; a2 += e1.x; a3 += e1.y;
            } else {
                float b0v = bias[col], b1v = bias[col + 1];
                a0 += b0v; a1 += b1v; a2 += b0v; a3 += b1v;
            }
            *(float2*)c0p = make_float2(a0, a1);
            *(float2*)c1p = make_float2(a2, a3);
        }
    }
}

__global__ void __launch_bounds__(256)
mma_gemm(const __half* __restrict__ A, const __half* __restrict__ B,
         const float* __restrict__ bias, float* __restrict__ C, int ldC, int K, int accum) {
    extern __shared__ uint32_t sm[];
    gemm_body((const uint32_t*)A, (const uint32_t*)B,
              blockIdx.y * 128, blockIdx.x * 128, K, bias, C, ldC, accum, smem_u32(sm));
}

// dual: bx<12 -> IOU accum (A1@B1 += C1, ldC 2048); bx>=12 -> HW (A2@B2 + bias2, ldC 512)
__global__ void __launch_bounds__(256)
mma_gemm_dual(const __half* __restrict__ A1, const __half* __restrict__ A2,
              const __half* __restrict__ B1, const __half* __restrict__ B2,
              const float* __restrict__ bias2, float* __restrict__ C1, float* __restrict__ C2) {
    extern __shared__ uint32_t sm[];
    if (blockIdx.x < 12) {
        gemm_body((const uint32_t*)A1, (const uint32_t*)B1,
                  blockIdx.y * 128, blockIdx.x * 128, 512, nullptr, C1, 2048, 1, smem_u32(sm));
    } else {
        gemm_body((const uint32_t*)A2, (const uint32_t*)B2,
                  blockIdx.y * 128, (blockIdx.x - 12) * 128, 512, bias2, C2, 512, 0, smem_u32(sm));
    }
}

// ---------------- prep: tiled transpose -> fp16 (coalesced both sides) ----------------
__global__ void __launch_bounds__(256)
transp_h(const float* __restrict__ srcA, const float* __restrict__ srcB,
         int ldA, int ldB, int nsplit, int K, __half* __restrict__ dst) {
    __shared__ float tile[32][33];
    const int n0 = blockIdx.x * 32, k0 = blockIdx.y * 32;
    const int tx = threadIdx.x, ty = threadIdx.y;
    const int n = n0 + tx;
    const float* src = (n0 < nsplit) ? srcA : srcB;
    const int ld = (n0 < nsplit) ? ldA : ldB;
    const int col = (n0 < nsplit) ? n : n - nsplit;
#pragma unroll
    for (int i = 0; i < 4; i++) {
        int k = k0 + ty + i * 8;
        tile[ty + i * 8][tx] = src[(size_t)k * ld + col];
    }
    __syncthreads();
    const int Kw = K >> 1;
#pragma unroll
    for (int j = 0; j < 2; j++) {
        int lin = j * 256 + ty * 32 + tx;
        int nl = lin >> 4, kp = lin & 15;
        uint32_t h = f2h(tile[kp * 2][nl], tile[kp * 2 + 1][nl]);
        ((uint32_t*)dst)[(size_t)(n0 + nl) * Kw + (k0 >> 1) + kp] = h;
    }
}

// wih fp16 (coalesced) + biases
__global__ void prep_copy(const float* __restrict__ wih_f, const float* __restrict__ wih_b,
                          const float* __restrict__ bioux, const float* __restrict__ biouh,
                          const float* __restrict__ bfx,
                          const float* __restrict__ bih_f, const float* __restrict__ bih_b) {
    int idx = blockIdx.x * blockDim.x + threadIdx.x;
    const int T2 = G3M * (MM / 2);
    if (idx < 2 * T2) {
        int dir = idx / T2, j = idx % T2;
        const float* wsrc = dir ? wih_b : wih_f;
        ((uint32_t*)g_wih[dir])[j] = f2h(wsrc[2 * j], wsrc[2 * j + 1]);
    }
    if (idx < 2048)
        g_biasbig[idx] = (idx < G3M) ? (bioux[idx] + biouh[idx]) : bfx[idx - G3M];
    if (idx < 2 * G3M)
        g_bihcat[idx] = (idx < G3M) ? bih_f[idx] : bih_b[idx - G3M];
}

// ---------------- init ----------------
__global__ void init_leaf(const float* __restrict__ embed, const int* __restrict__ leaf_idx) {
    int idx = blockIdx.x * blockDim.x + threadIdx.x;
    if (idx >= NLEAF * (MM / 4)) return;
    int n = idx >> 7, m = (idx & 127) * 4;
    int w = leaf_idx[n];
    float4 v = *(const float4*)(embed + (size_t)w * MM + m);
    uint32_t h0, l0, h1, l1;
    packres(v.x, v.y, h0, l0);
    packres(v.z, v.w, h1, l1);
    size_t wrd = ((size_t)(1 + n) * MM + m) >> 1;
    ((uint32_t*)g_Hhi)[wrd] = h0; ((uint32_t*)g_Hhi)[wrd + 1] = h1;
    ((uint32_t*)g_Hlo)[wrd] = l0; ((uint32_t*)g_Hlo)[wrd + 1] = l1;
}

__global__ void init_misc() {
    int idx = blockIdx.x * blockDim.x + threadIdx.x;
    if (idx == 0) g_bar = 0u;
    if (idx < MM / 2) {
        ((uint32_t*)g_Hhi)[idx] = 0u;
        ((uint32_t*)g_Hlo)[idx] = 0u;
    }
    if (idx < 2 * BB * MM) (&g_hst[0][0])[idx] = 0.f;
}

// ---------------- gather x embeddings for ALL levels ----------------
__global__ void gather_x_all(const float* __restrict__ embed, const int* __restrict__ lwi) {
    int idx = blockIdx.x * blockDim.x + threadIdx.x;
    if (idx >= NALL * (MM / 4)) return;
    int ng = idx >> 7, m = (idx & 127) * 4;
    int w = lwi[ng];
    float4 x = *(const float4*)(embed + (size_t)w * MM + m);
    size_t wrd = ((size_t)ng * MM + m) >> 1;
    ((uint32_t*)g_Xall)[wrd]     = f2h(x.x, x.y);
    ((uint32_t*)g_Xall)[wrd + 1] = f2h(x.z, x.w);
}

// ---------------- per-level gather: sum of child h (reconstruct hi+lo) ----------------
__global__ void gather_level(const int* __restrict__ child, int d) {
    int idx = blockIdx.x * blockDim.x + threadIdx.x;
    if (idx >= NNODE * (MM / 4)) return;
    int n = idx >> 7, m = (idx & 127) * 4;
    float4 s = make_float4(0.f, 0.f, 0.f, 0.f);
    const int* ch = child + ((size_t)d * NNODE + n) * KCH;
#pragma unroll
    for (int k = 0; k < KCH; k++) {
        int ci = ch[k];
        size_t wrd = ((size_t)ci * MM + m) >> 1;
        uint2 hw = *(const uint2*)((const uint32_t*)g_Hhi + wrd);
        uint2 lw = *(const uint2*)((const uint32_t*)g_Hlo + wrd);
        float2 a0 = h2f(hw.x), b0 = h2f(lw.x);
        float2 a1 = h2f(hw.y), b1 = h2f(lw.y);
        s.x += a0.x + b0.x; s.y += a0.y + b0.y;
        s.z += a1.x + b1.x; s.w += a1.y + b1.y;
    }
    size_t wrd = ((size_t)n * MM + m) >> 1;
    ((uint32_t*)g_SUMH)[wrd]     = f2h(s.x, s.y);
    ((uint32_t*)g_SUMH)[wrd + 1] = f2h(s.z, s.w);
}

// ---------------- level pointwise ----------------
__global__ void level_point(const int* __restrict__ child, int d) {
    int idx = blockIdx.x * blockDim.x + threadIdx.x;
    if (idx >= NNODE * (MM / 2)) return;
    int n = idx >> 8, j = idx & 255;
    int m = 2 * j;
    const float* row = g_IOUFall + (size_t)(d * NNODE + n) * 2048;
    float2 iv = *(const float2*)(row + m);
    float2 ov = *(const float2*)(row + MM + m);
    float2 uv = *(const float2*)(row + 2 * MM + m);
    float2 fx = *(const float2*)(row + 3 * MM + m);
    float c0 = sigf(iv.x) * tanhf(uv.x);
    float c1 = sigf(iv.y) * tanhf(uv.y);
    const int* ch = child + ((size_t)d * NNODE + n) * KCH;
#pragma unroll
    for (int k = 0; k < KCH; k++) {
        int ci = ch[k];
        if (ci > NLEAF) {
            float2 hw = *(const float2*)(g_HW + (size_t)ci * MM + m);
            float2 cc = *(const float2*)(g_c_pool + (size_t)ci * MM + m);
            c0 += sigf(fx.x + hw.x) * cc.x;
            c1 += sigf(fx.y + hw.y) * cc.y;
        }
    }
    float h0 = sigf(ov.x) * tanhf(c0);
    float h1 = sigf(ov.y) * tanhf(c1);
    size_t slot = (size_t)(OFFS + d * NNODE + n) * MM + m;
    *(float2*)(g_c_pool + slot) = make_float2(c0, c1);
    uint32_t sh, sl; packres(h0, h1, sh, sl);
    ((uint32_t*)g_Hhi)[slot >> 1] = sh;
    ((uint32_t*)g_Hlo)[slot >> 1] = sl;
}

// ---------------- GRU ----------------
__global__ void gather_xs(const int* __restrict__ ctx) {
    int idx = blockIdx.x * blockDim.x + threadIdx.x;
    if (idx >= BB * SSEQ * (MM / 4)) return;
    int rowI = idx >> 7, m = (idx & 127) * 4;
    int p = ctx[rowI];
    size_t swrd = ((size_t)p * MM + m) >> 1;
    uint2 hw = *(const uint2*)((const uint32_t*)g_Hhi + swrd);
    uint2 lw = *(const uint2*)((const uint32_t*)g_Hlo + swrd);
    float2 a0 = h2f(hw.x), b0 = h2f(lw.x);
    float2 a1 = h2f(hw.y), b1 = h2f(lw.y);
    size_t wrd = ((size_t)rowI * MM + m) >> 1;
    ((uint32_t*)g_xs)[wrd]     = f2h(a0.x + b0.x, a0.y + b0.y);
    ((uint32_t*)g_xs)[wrd + 1] = f2h(a1.x + b1.x, a1.y + b1.y);
}

#define GNB 96
#define HS_STR 516
__device__ __forceinline__ void gridbar(unsigned gen) {
    __syncthreads();
    if (threadIdx.x == 0) {
        __threadfence();
        atomicAdd(&g_bar, 1u);
        while (atomicAdd(&g_bar, 0u) < gen * GNB) { __nanosleep(64); }
        __threadfence();
    }
    __syncthreads();
}

__global__ void __launch_bounds__(256) gru_persist(const float* __restrict__ whh_f,
                                                   const float* __restrict__ whh_b,
                                                   const float* __restrict__ bhh_f,
                                                   const float* __restrict__ bhh_b,
                                                   float* __restrict__ out) {
    extern __shared__ float sh[];
    float* Hs = sh;                     // 64 x HS_STR
    float* Ws = sh + 64 * HS_STR;       // k-major [512][32]
    const int dir = blockIdx.y;
    const int n0 = blockIdx.x * 32;
    const int tid = threadIdx.x;
    const int bid = blockIdx.y * 48 + blockIdx.x;
    const float* whh = dir ? whh_b : whh_f;
    const float* bhh = dir ? bhh_b : bhh_f;

    for (int i = tid; i < 32 * 512; i += 256) {
        int k = i & 511, col = i >> 9;
        Ws[k * 32 + col] = whh[(size_t)(n0 + col) * MM + k];
    }
    const int cg = tid & 7, r = tid >> 3;
    float bv[4];
#pragma unroll
    for (int c = 0; c < 4; c++) bv[c] = bhh[n0 + cg * 4 + c];

    unsigned gen = 0;
    for (int t = 0; t < SSEQ; t++) {
        __syncthreads();
        const float* H = g_hst[dir];
        for (int i = tid; i < 64 * 512; i += 256) Hs[(i >> 9) * HS_STR + (i & 511)] = H[i];
        __syncthreads();
        int row0 = 2 * r, row1 = row0 + 1;
        float acc0[4] = {0.f, 0.f, 0.f, 0.f};
        float acc1[4] = {0.f, 0.f, 0.f, 0.f};
        for (int k = 0; k < 512; k += 4) {
            float4 ha = *(float4*)&Hs[row0 * HS_STR + k];
            float4 hb = *(float4*)&Hs[row1 * HS_STR + k];
#pragma unroll
            for (int i = 0; i < 4; i++) {
                float4 wv = *(float4*)&Ws[(k + i) * 32 + cg * 4];
                float a = (&ha.x)[i], b = (&hb.x)[i];
                acc0[0] += a * wv.x; acc0[1] += a * wv.y; acc0[2] += a * wv.z; acc0[3] += a * wv.w;
                acc1[0] += b * wv.x; acc1[1] += b * wv.y; acc1[2] += b * wv.z; acc1[3] += b * wv.w;
            }
        }
#pragma unroll
        for (int c = 0; c < 4; c++) {
            int n = n0 + cg * 4 + c;
            g_hg[dir][(size_t)row0 * G3M + n] = acc0[c] + bv[c];
            g_hg[dir][(size_t)row1 * G3M + n] = acc1[c] + bv[c];
        }
        gridbar(++gen);
        for (int e = bid * 256 + tid; e < 2 * BB * MM; e += GNB * 256) {
            int dd = e >> 15;
            int rem = e & 32767;
            int b = rem >> 9, j = rem & 511;
            int pos = dd ? (SSEQ - 1 - t) : t;
            const float* xrow = g_xg + (size_t)(b * SSEQ + pos) * (2 * G3M) + dd * G3M;
            const float* hrow = g_hg[dd] + (size_t)b * G3M;
            float rr_ = sigf(xrow[j] + hrow[j]);
            float zz = sigf(xrow[MM + j] + hrow[MM + j]);
            float nn = tanhf(xrow[2 * MM + j] + rr_ * hrow[2 * MM + j]);
            float hp = g_hst[dd][b * MM + j];
            float hn = (1.f - zz) * nn + zz * hp;
            g_hst[dd][b * MM + j] = hn;
            float* op = out + (size_t)(b * SSEQ + pos) * MM + j;
            if (t < 8) *op = hn; else *op += hn;
        }
        gridbar(++gen);
    }
}

// ---------------- host launch ----------------
extern "C" void kernel_launch(void* const* d_in, const int* in_sizes, int n_in,
                              void* d_out, int out_size) {
    const float* embed   = (const float*)d_in[0];
    const float* Wioux   = (const float*)d_in[1];
    const float* bioux   = (const float*)d_in[2];
    const float* Wiouh   = (const float*)d_in[3];
    const float* biouh   = (const float*)d_in[4];
    const float* Wfx     = (const float*)d_in[5];
    const float* bfx     = (const float*)d_in[6];
    const float* Wfh     = (const float*)d_in[7];
    const float* bfh     = (const float*)d_in[8];
    const float* wih_f   = (const float*)d_in[9];
    const float* whh_f   = (const float*)d_in[10];
    const float* bih_f   = (const float*)d_in[11];
    const float* bhh_f   = (const float*)d_in[12];
    const float* wih_b   = (const float*)d_in[13];
    const float* whh_b   = (const float*)d_in[14];
    const float* bih_b   = (const float*)d_in[15];
    const float* bhh_b   = (const float*)d_in[16];

    const int* leaf_idx = nullptr; const int* level_idx = nullptr;
    const int* child = nullptr; const int* ctx = nullptr;
    for (int i = 17; i < n_in; i++) {
        int sz = in_sizes[i];
        if (sz == NLEAF)                 leaf_idx  = (const int*)d_in[i];
        else if (sz == DD * NNODE)       level_idx = (const int*)d_in[i];
        else if (sz == DD * NNODE * KCH) child     = (const int*)d_in[i];
        else if (sz == BB * SSEQ)        ctx       = (const int*)d_in[i];
    }

    float* out = (float*)d_out;

    const size_t GRU_SMEM = (64 * HS_STR + 512 * 32) * sizeof(float);
    cudaFuncSetAttribute(mma_gemm, cudaFuncAttributeMaxDynamicSharedMemorySize, MMA_SMEM_BYTES);
    cudaFuncSetAttribute(mma_gemm_dual, cudaFuncAttributeMaxDynamicSharedMemorySize, MMA_SMEM_BYTES);
    cudaFuncSetAttribute(gru_persist, cudaFuncAttributeMaxDynamicSharedMemorySize, (int)GRU_SMEM);

    __half* d_Hhi;  cudaGetSymbolAddress((void**)&d_Hhi, g_Hhi);
    __half* d_X;    cudaGetSymbolAddress((void**)&d_X, g_Xall);
    __half* d_SH;   cudaGetSymbolAddress((void**)&d_SH, g_SUMH);
    __half* d_W1;   cudaGetSymbolAddress((void**)&d_W1, g_W1);
    __half* d_W2;   cudaGetSymbolAddress((void**)&d_W2, g_W2);
    __half* d_WfT;  cudaGetSymbolAddress((void**)&d_WfT, g_WfT);
    __half* d_wih;  cudaGetSymbolAddress((void**)&d_wih, g_wih);
    __half* d_xs;   cudaGetSymbolAddress((void**)&d_xs, g_xs);
    float* d_IOUF;  cudaGetSymbolAddress((void**)&d_IOUF, g_IOUFall);
    float* d_HW;    cudaGetSymbolAddress((void**)&d_HW, g_HW);
    float* d_bb;    cudaGetSymbolAddress((void**)&d_bb, g_biasbig);
    float* d_bih;   cudaGetSymbolAddress((void**)&d_bih, g_bihcat);
    float* d_xg;    cudaGetSymbolAddress((void**)&d_xg, g_xg);

    // prep + init
    {
        dim3 blk(32, 8);
        transp_h<<<dim3(2048 / 32, 512 / 32), blk>>>(Wioux, Wfx, G3M, MM, G3M, 512, d_W1);
        transp_h<<<dim3(G3M / 32, 512 / 32), blk>>>(Wiouh, nullptr, G3M, 0, G3M, 512, d_W2);
        transp_h<<<dim3(MM / 32, 512 / 32), blk>>>(Wfh, nullptr, MM, 0, MM, 512, d_WfT);
    }
    prep_copy<<<(2 * G3M * (MM / 2) + 255) / 256, 256>>>(wih_f, wih_b, bioux, biouh, bfx,
                                                         bih_f, bih_b);
    init_leaf<<<(NLEAF * (MM / 4) + 255) / 256, 256>>>(embed, leaf_idx);
    init_misc<<<(2 * BB * MM + 255) / 256, 256>>>();
    gather_x_all<<<(NALL * (MM / 4) + 255) / 256, 256>>>(embed, level_idx);

    // upfront: IOUF_all = X_all @ [Wioux|Wfx]^T + biasbig
    {
        dim3 grid(2048 / 128, NALL / 128);
        mma_gemm<<<grid, 256, MMA_SMEM_BYTES>>>(d_X, d_W1, d_bb, d_IOUF, 2048, 512, 0);
    }

    // level 0: IOU accum only
    gather_level<<<(NNODE * (MM / 4) + 255) / 256, 256>>>(child, 0);
    {
        dim3 grid(G3M / 128, NNODE / 128);
        mma_gemm<<<grid, 256, MMA_SMEM_BYTES>>>(d_SH, d_W2, nullptr, d_IOUF, 2048, 512, 1);
    }
    level_point<<<(NNODE * (MM / 2) + 255) / 256, 256>>>(child, 0);

    // levels 1..7: fused [IOU(d) accum | HW(d-1)]
    for (int d = 1; d < DD; d++) {
        gather_level<<<(NNODE * (MM / 4) + 255) / 256, 256>>>(child, d);
        size_t hoff = (size_t)(OFFS + (d - 1) * NNODE) * MM;
        {
            dim3 grid(16, NNODE / 128);
            mma_gemm_dual<<<grid, 256, MMA_SMEM_BYTES>>>(
                d_SH, d_Hhi + hoff, d_W2, d_WfT,
                bfh, d_IOUF + (size_t)d * NNODE * 2048, d_HW + hoff);
        }
        level_point<<<(NNODE * (MM / 2) + 255) / 256, 256>>>(child, d);
    }

    // GRU input gates: single GEMM, N=3072
    gather_xs<<<(BB * SSEQ * (MM / 4) + 255) / 256, 256>>>(ctx);
    {
        dim3 grid(2 * G3M / 128, (BB * SSEQ) / 128);
        mma_gemm<<<grid, 256, MMA_SMEM_BYTES>>>(d_xs, d_wih, d_bih, d_xg, 2 * G3M, 512, 0);
    }

    // GRU recurrence
    {
        dim3 grid(48, 2);
        gru_persist<<<grid, 256, GRU_SMEM>>>(whh_f, whh_b, bhh_f, bhh_b, out);
    }
}